// round 1
// baseline (speedup 1.0000x reference)
#include <cuda_runtime.h>
#include <math.h>

#define VIEW 8
#define SEQ  2048
#define HID  1024
#define ATT  128
#define SCALE 0.08838834764831845f   // ATT^-0.5

#define BM 128
#define BN 128
#define BK 16
#define TM 8
#define TN 8
#define PAD 4
#define NTHREADS 256

// ---------------- scratch (static device globals: allocation-guard safe) ----
__device__ float g_qh[VIEW * SEQ * ATT];                 // 8 MB
__device__ float g_kh[VIEW * SEQ * ATT];                 // 8 MB
__device__ float g_vh[VIEW * SEQ * ATT];                 // 8 MB
__device__ float g_scores[(size_t)VIEW * SEQ * SEQ];     // 128 MiB (holds attn after softmax)
__device__ float g_x[VIEW * SEQ * ATT];                  // 8 MB

// ---------------------------------------------------------------------------
// Shared inner-product core: As/Bs are [BK][BM+PAD]/[BK][BN+PAD]
// ---------------------------------------------------------------------------
__device__ __forceinline__ void tile_mma(const float (*As)[BM + PAD],
                                         const float (*Bs)[BN + PAD],
                                         float acc[TM][TN], int ty, int tx) {
#pragma unroll
    for (int kk = 0; kk < BK; kk++) {
        float4 a0 = *(const float4*)&As[kk][ty * TM];
        float4 a1 = *(const float4*)&As[kk][ty * TM + 4];
        float4 b0 = *(const float4*)&Bs[kk][tx * TN];
        float4 b1 = *(const float4*)&Bs[kk][tx * TN + 4];
        float ra[TM] = {a0.x, a0.y, a0.z, a0.w, a1.x, a1.y, a1.z, a1.w};
        float rb[TN] = {b0.x, b0.y, b0.z, b0.w, b1.x, b1.y, b1.z, b1.w};
#pragma unroll
        for (int i = 0; i < TM; i++)
#pragma unroll
            for (int j = 0; j < TN; j++)
                acc[i][j] = fmaf(ra[i], rb[j], acc[i][j]);
    }
}

// ---------------------------------------------------------------------------
// 1) Projections:  C = (X @ W + b) * scale    X:[16384,1024]  W:[1024,128]
//    blockIdx.z selects q / k / v
// ---------------------------------------------------------------------------
__global__ __launch_bounds__(NTHREADS) void proj_kernel(
    const float* __restrict__ qin, const float* __restrict__ kin,
    const float* __restrict__ vin,
    const float* __restrict__ wq, const float* __restrict__ bq,
    const float* __restrict__ wk, const float* __restrict__ bk,
    const float* __restrict__ wv, const float* __restrict__ bv) {
    const float *X, *W, *bias;
    float* C;
    float scale;
    if (blockIdx.z == 0)      { X = qin; W = wq; bias = bq; C = g_qh; scale = SCALE; }
    else if (blockIdx.z == 1) { X = kin; W = wk; bias = bk; C = g_kh; scale = 1.f; }
    else                      { X = vin; W = wv; bias = bv; C = g_vh; scale = 1.f; }

    __shared__ float As[BK][BM + PAD];
    __shared__ float Bs[BK][BN + PAD];
    const int tid = threadIdx.x;
    const int tx = tid % (BN / TN);
    const int ty = tid / (BN / TN);
    const int mBase = blockIdx.x * BM;

    float acc[TM][TN];
#pragma unroll
    for (int i = 0; i < TM; i++)
#pragma unroll
        for (int j = 0; j < TN; j++) acc[i][j] = 0.f;

    for (int kb = 0; kb < HID; kb += BK) {
#pragma unroll
        for (int i = 0; i < (BM * BK) / NTHREADS; i++) {
            int idx = tid + i * NTHREADS;
            int kk = idx % BK, m = idx / BK;
            As[kk][m] = X[(size_t)(mBase + m) * HID + kb + kk];
        }
#pragma unroll
        for (int i = 0; i < (BK * BN) / NTHREADS; i++) {
            int idx = tid + i * NTHREADS;
            int n = idx % BN, kk = idx / BN;
            Bs[kk][n] = W[(size_t)(kb + kk) * ATT + n];
        }
        __syncthreads();
        tile_mma(As, Bs, acc, ty, tx);
        __syncthreads();
    }
#pragma unroll
    for (int i = 0; i < TM; i++) {
        int m = mBase + ty * TM + i;
#pragma unroll
        for (int j = 0; j < TN; j++) {
            int n = tx * TN + j;
            C[(size_t)m * ATT + n] = (acc[i][j] + bias[n]) * scale;
        }
    }
}

// ---------------------------------------------------------------------------
// 2) scores[v,q,k] = sum_a qh[v,q,a] * kh[v,k,a]     (B consumed transposed)
// ---------------------------------------------------------------------------
__global__ __launch_bounds__(NTHREADS) void scores_kernel() {
    const int v = blockIdx.z;
    const float* Q = g_qh + (size_t)v * SEQ * ATT;
    const float* K = g_kh + (size_t)v * SEQ * ATT;
    float* C = g_scores + (size_t)v * SEQ * SEQ;

    __shared__ float As[BK][BM + PAD];
    __shared__ float Bs[BK][BN + PAD];
    const int tid = threadIdx.x;
    const int tx = tid % (BN / TN);
    const int ty = tid / (BN / TN);
    const int mBase = blockIdx.x * BM;
    const int nBase = blockIdx.y * BN;

    float acc[TM][TN];
#pragma unroll
    for (int i = 0; i < TM; i++)
#pragma unroll
        for (int j = 0; j < TN; j++) acc[i][j] = 0.f;

    for (int kb = 0; kb < ATT; kb += BK) {
#pragma unroll
        for (int i = 0; i < (BM * BK) / NTHREADS; i++) {
            int idx = tid + i * NTHREADS;
            int kk = idx % BK, m = idx / BK;
            As[kk][m] = Q[(size_t)(mBase + m) * ATT + kb + kk];
        }
#pragma unroll
        for (int i = 0; i < (BK * BN) / NTHREADS; i++) {
            int idx = tid + i * NTHREADS;
            int kk = idx % BK, n = idx / BK;
            Bs[kk][n] = K[(size_t)(nBase + n) * ATT + kb + kk];
        }
        __syncthreads();
        tile_mma(As, Bs, acc, ty, tx);
        __syncthreads();
    }
#pragma unroll
    for (int i = 0; i < TM; i++) {
        int m = mBase + ty * TM + i;
#pragma unroll
        for (int j = 0; j < TN; j++) {
            int n = nBase + tx * TN + j;
            C[(size_t)m * SEQ + n] = acc[i][j];
        }
    }
}

// ---------------------------------------------------------------------------
// 3) row softmax (in place) + post-softmax bias add. One block per row.
// ---------------------------------------------------------------------------
__global__ __launch_bounds__(NTHREADS) void softmax_bias_kernel(
    const float* __restrict__ bias) {
    const size_t row = blockIdx.x;            // 0 .. VIEW*SEQ-1
    float* p = g_scores + row * SEQ;
    const float* b = bias + row * SEQ;
    const int tid = threadIdx.x;

    float vreg[SEQ / NTHREADS];               // 8
    float lmax = -1e30f;
#pragma unroll
    for (int i = 0; i < SEQ / NTHREADS; i++) {
        vreg[i] = p[tid + i * NTHREADS];
        lmax = fmaxf(lmax, vreg[i]);
    }
    __shared__ float red[NTHREADS / 32];
#pragma unroll
    for (int off = 16; off; off >>= 1)
        lmax = fmaxf(lmax, __shfl_xor_sync(0xffffffffu, lmax, off));
    if ((tid & 31) == 0) red[tid >> 5] = lmax;
    __syncthreads();
    float m = red[0];
#pragma unroll
    for (int w = 1; w < NTHREADS / 32; w++) m = fmaxf(m, red[w]);

    float lsum = 0.f;
#pragma unroll
    for (int i = 0; i < SEQ / NTHREADS; i++) {
        vreg[i] = __expf(vreg[i] - m);
        lsum += vreg[i];
    }
#pragma unroll
    for (int off = 16; off; off >>= 1)
        lsum += __shfl_xor_sync(0xffffffffu, lsum, off);
    __syncthreads();                          // done reading red (max phase)
    if ((tid & 31) == 0) red[tid >> 5] = lsum;
    __syncthreads();
    float s = 0.f;
#pragma unroll
    for (int w = 0; w < NTHREADS / 32; w++) s += red[w];
    const float inv = 1.f / s;
#pragma unroll
    for (int i = 0; i < SEQ / NTHREADS; i++)
        p[tid + i * NTHREADS] = vreg[i] * inv + b[tid + i * NTHREADS];
}

// ---------------------------------------------------------------------------
// 4) x[v,q,a] = sum_k attn[v,q,k] * vh[v,k,a]
// ---------------------------------------------------------------------------
__global__ __launch_bounds__(NTHREADS) void attnv_kernel() {
    const int v = blockIdx.z;
    const float* Amat = g_scores + (size_t)v * SEQ * SEQ;
    const float* B = g_vh + (size_t)v * SEQ * ATT;
    float* C = g_x + (size_t)v * SEQ * ATT;

    __shared__ float As[BK][BM + PAD];
    __shared__ float Bs[BK][BN + PAD];
    const int tid = threadIdx.x;
    const int tx = tid % (BN / TN);
    const int ty = tid / (BN / TN);
    const int mBase = blockIdx.x * BM;

    float acc[TM][TN];
#pragma unroll
    for (int i = 0; i < TM; i++)
#pragma unroll
        for (int j = 0; j < TN; j++) acc[i][j] = 0.f;

    for (int kb = 0; kb < SEQ; kb += BK) {
#pragma unroll
        for (int i = 0; i < (BM * BK) / NTHREADS; i++) {
            int idx = tid + i * NTHREADS;
            int kk = idx % BK, m = idx / BK;
            As[kk][m] = Amat[(size_t)(mBase + m) * SEQ + kb + kk];
        }
#pragma unroll
        for (int i = 0; i < (BK * BN) / NTHREADS; i++) {
            int idx = tid + i * NTHREADS;
            int n = idx % BN, kk = idx / BN;
            Bs[kk][n] = B[(size_t)(kb + kk) * ATT + n];
        }
        __syncthreads();
        tile_mma(As, Bs, acc, ty, tx);
        __syncthreads();
    }
#pragma unroll
    for (int i = 0; i < TM; i++) {
        int m = mBase + ty * TM + i;
#pragma unroll
        for (int j = 0; j < TN; j++) {
            int n = tx * TN + j;
            C[(size_t)m * ATT + n] = acc[i][j];
        }
    }
}

// ---------------------------------------------------------------------------
// 5) out[s,h] = sum_c xT[s,c] * wo[c,h] + bo[h],  xT[s, v*128+a] = g_x[v][s][a]
// ---------------------------------------------------------------------------
__global__ __launch_bounds__(NTHREADS) void out_kernel(
    const float* __restrict__ wo, const float* __restrict__ bo,
    float* __restrict__ out) {
    __shared__ float As[BK][BM + PAD];
    __shared__ float Bs[BK][BN + PAD];
    const int tid = threadIdx.x;
    const int tx = tid % (BN / TN);
    const int ty = tid / (BN / TN);
    const int mBase = blockIdx.x * BM;   // along SEQ
    const int nBase = blockIdx.y * BN;   // along HID

    float acc[TM][TN];
#pragma unroll
    for (int i = 0; i < TM; i++)
#pragma unroll
        for (int j = 0; j < TN; j++) acc[i][j] = 0.f;

    for (int kb = 0; kb < VIEW * ATT; kb += BK) {
#pragma unroll
        for (int i = 0; i < (BM * BK) / NTHREADS; i++) {
            int idx = tid + i * NTHREADS;
            int kk = idx % BK, m = idx / BK;
            int c = kb + kk;                       // v*128 + a
            As[kk][m] = g_x[((size_t)(c >> 7) * SEQ + (mBase + m)) * ATT + (c & 127)];
        }
#pragma unroll
        for (int i = 0; i < (BK * BN) / NTHREADS; i++) {
            int idx = tid + i * NTHREADS;
            int n = idx % BN, kk = idx / BN;
            Bs[kk][n] = wo[(size_t)(kb + kk) * HID + nBase + n];
        }
        __syncthreads();
        tile_mma(As, Bs, acc, ty, tx);
        __syncthreads();
    }
#pragma unroll
    for (int i = 0; i < TM; i++) {
        int m = mBase + ty * TM + i;
#pragma unroll
        for (int j = 0; j < TN; j++) {
            int n = nBase + tx * TN + j;
            out[(size_t)m * HID + n] = acc[i][j] + bo[n];
        }
    }
}

// ---------------------------------------------------------------------------
extern "C" void kernel_launch(void* const* d_in, const int* in_sizes, int n_in,
                              void* d_out, int out_size) {
    const float* q         = (const float*)d_in[0];
    const float* k         = (const float*)d_in[1];
    const float* v         = (const float*)d_in[2];
    const float* attn_bias = (const float*)d_in[3];
    const float* wq        = (const float*)d_in[4];
    const float* bq        = (const float*)d_in[5];
    const float* wk        = (const float*)d_in[6];
    const float* bk        = (const float*)d_in[7];
    const float* wv        = (const float*)d_in[8];
    const float* bv        = (const float*)d_in[9];
    const float* wo        = (const float*)d_in[10];
    const float* bo        = (const float*)d_in[11];
    float* out = (float*)d_out;

    dim3 blk(NTHREADS);
    proj_kernel<<<dim3((VIEW * SEQ) / BM, 1, 3), blk>>>(q, k, v, wq, bq, wk, bk, wv, bv);
    scores_kernel<<<dim3(SEQ / BM, SEQ / BN, VIEW), blk>>>();
    softmax_bias_kernel<<<dim3(VIEW * SEQ), blk>>>(attn_bias);
    attnv_kernel<<<dim3(SEQ / BM, 1, VIEW), blk>>>();
    out_kernel<<<dim3(SEQ / BM, HID / BN), blk>>>(wo, bo, out);
}

// round 4
// speedup vs baseline: 2.7078x; 2.7078x over previous
#include <cuda_runtime.h>
#include <cuda_bf16.h>
#include <cstdint>
#include <math.h>

#define VIEW 8
#define SEQ  2048
#define HID  1024
#define ATT  128
#define SCALE 0.08838834764831845f   // ATT^-0.5

using bf16 = __nv_bfloat16;
using bf162 = __nv_bfloat162;

// ======================= device scratch (no allocs allowed) =================
__device__ __align__(256) bf16 g_q_hi[VIEW*SEQ*HID], g_q_lo[VIEW*SEQ*HID];
__device__ __align__(256) bf16 g_k_hi[VIEW*SEQ*HID], g_k_lo[VIEW*SEQ*HID];
__device__ __align__(256) bf16 g_v_hi[VIEW*SEQ*HID], g_v_lo[VIEW*SEQ*HID];
__device__ __align__(256) bf16 g_wqT_h[ATT*HID], g_wqT_l[ATT*HID];      // [n=128][k=1024]
__device__ __align__(256) bf16 g_wkT_h[ATT*HID], g_wkT_l[ATT*HID];
__device__ __align__(256) bf16 g_wvT_h[ATT*HID], g_wvT_l[ATT*HID];
__device__ __align__(256) bf16 g_woT_h[HID*HID], g_woT_l[HID*HID];      // [h=1024][c=1024]
__device__ __align__(256) bf16 g_qh_h[VIEW*SEQ*ATT], g_qh_l[VIEW*SEQ*ATT];
__device__ __align__(256) bf16 g_kh_h[VIEW*SEQ*ATT], g_kh_l[VIEW*SEQ*ATT];
__device__ __align__(256) float g_vh[VIEW*SEQ*ATT];
__device__ __align__(256) bf16 g_vhT_h[VIEW*ATT*SEQ], g_vhT_l[VIEW*ATT*SEQ]; // per view [a][s]
__device__ __align__(256) float g_scores[(size_t)VIEW*SEQ*SEQ];          // 134MB
__device__ __align__(256) bf16 g_attn_h[(size_t)VIEW*SEQ*SEQ], g_attn_l[(size_t)VIEW*SEQ*SEQ];
__device__ __align__(256) bf16 g_x_h[VIEW*SEQ*ATT], g_x_l[VIEW*SEQ*ATT];

// ======================= helpers ===========================================
__device__ __forceinline__ uint32_t smem_u32(const void* p) {
    uint32_t a;
    asm("{ .reg .u64 t; cvta.to.shared.u64 t, %1; cvt.u32.u64 %0, t; }" : "=r"(a) : "l"(p));
    return a;
}
__device__ __forceinline__ void split2(float x, bf16& h, bf16& l) {
    h = __float2bfloat16(x);
    l = __float2bfloat16(x - __bfloat162float(h));
}

#define CP_ASYNC16(saddr, gptr) \
    asm volatile("cp.async.cg.shared.global [%0], [%1], 16;" \
                 :: "r"(saddr), "l"(__cvta_generic_to_global(gptr)) : "memory")
#define CP_COMMIT() asm volatile("cp.async.commit_group;" ::: "memory")
#define CP_WAIT0()  asm volatile("cp.async.wait_group 0;" ::: "memory")
#define CP_WAIT1()  asm volatile("cp.async.wait_group 1;" ::: "memory")

#define LDSM4(R, addr) \
    asm volatile("ldmatrix.sync.aligned.m8n8.x4.shared.b16 {%0,%1,%2,%3}, [%4];" \
                 : "=r"((R)[0]), "=r"((R)[1]), "=r"((R)[2]), "=r"((R)[3]) : "r"(addr))

#define MMA16816(C, A, b0, b1) \
    asm volatile("mma.sync.aligned.m16n8k16.row.col.f32.bf16.bf16.f32 " \
                 "{%0,%1,%2,%3},{%4,%5,%6,%7},{%8,%9},{%0,%1,%2,%3};" \
                 : "+f"((C)[0]), "+f"((C)[1]), "+f"((C)[2]), "+f"((C)[3]) \
                 : "r"((A)[0]), "r"((A)[1]), "r"((A)[2]), "r"((A)[3]), "r"(b0), "r"(b1))

// ======================= conversion kernels ================================
__global__ void split_inputs_kernel(const float* __restrict__ q,
                                    const float* __restrict__ k,
                                    const float* __restrict__ v) {
    const float* src = blockIdx.z == 0 ? q : blockIdx.z == 1 ? k : v;
    bf16* dh = blockIdx.z == 0 ? g_q_hi : blockIdx.z == 1 ? g_k_hi : g_v_hi;
    bf16* dl = blockIdx.z == 0 ? g_q_lo : blockIdx.z == 1 ? g_k_lo : g_v_lo;
    size_t i = (size_t)blockIdx.x * blockDim.x + threadIdx.x;  // float4 index
    float4 x = reinterpret_cast<const float4*>(src)[i];
    bf16 h0,l0,h1,l1,h2,l2,h3,l3;
    split2(x.x,h0,l0); split2(x.y,h1,l1); split2(x.z,h2,l2); split2(x.w,h3,l3);
    bf162* ph = reinterpret_cast<bf162*>(dh);
    bf162* pl = reinterpret_cast<bf162*>(dl);
    bf162 a; a.x=h0; a.y=h1; ph[i*2] = a;   a.x=h2; a.y=h3; ph[i*2+1] = a;
    bf162 b; b.x=l0; b.y=l1; pl[i*2] = b;   b.x=l2; b.y=l3; pl[i*2+1] = b;
}

// Transpose+split WEIGHTS (device globals selected by mode — device-side only!)
// in: [R=HID][C], out: [C][R].  grid (C/32, R/32), block (32,8)
__global__ void transpose_split_w_kernel(const float* __restrict__ in, int mode) {
    __shared__ float t[32][33];
    bf16 *dh, *dl; int C;
    if (mode == 0)      { dh = g_wqT_h; dl = g_wqT_l; C = ATT; }
    else if (mode == 1) { dh = g_wkT_h; dl = g_wkT_l; C = ATT; }
    else if (mode == 2) { dh = g_wvT_h; dl = g_wvT_l; C = ATT; }
    else                { dh = g_woT_h; dl = g_woT_l; C = HID; }
    const int R = HID;
    int c0 = blockIdx.x * 32, r0 = blockIdx.y * 32;
    int tx = threadIdx.x, ty = threadIdx.y;
#pragma unroll
    for (int i = 0; i < 4; i++)
        t[ty + i*8][tx] = in[(size_t)(r0 + ty + i*8) * C + c0 + tx];
    __syncthreads();
#pragma unroll
    for (int i = 0; i < 4; i++) {
        float x = t[tx][ty + i*8];
        bf16 h, l; split2(x, h, l);
        size_t o = (size_t)(c0 + ty + i*8) * R + r0 + tx;
        dh[o] = h; dl[o] = l;
    }
}

// Transpose+split vh (fp32 [v][s][a] -> bf16 hi/lo [v][a][s]); grid (4,64,8)
__global__ void transpose_split_vh_kernel() {
    __shared__ float t[32][33];
    const int z = blockIdx.z;
    const float* src = g_vh + (size_t)z * SEQ * ATT;
    bf16* dh = g_vhT_h + (size_t)z * ATT * SEQ;
    bf16* dl = g_vhT_l + (size_t)z * ATT * SEQ;
    int c0 = blockIdx.x * 32, r0 = blockIdx.y * 32;   // c over ATT, r over SEQ
    int tx = threadIdx.x, ty = threadIdx.y;
#pragma unroll
    for (int i = 0; i < 4; i++)
        t[ty + i*8][tx] = src[(size_t)(r0 + ty + i*8) * ATT + c0 + tx];
    __syncthreads();
#pragma unroll
    for (int i = 0; i < 4; i++) {
        float x = t[tx][ty + i*8];
        bf16 h, l; split2(x, h, l);
        size_t o = (size_t)(c0 + ty + i*8) * SEQ + r0 + tx;
        dh[o] = h; dl[o] = l;
    }
}

// ======================= warp-MMA GEMM (bf16x3, 128x128 tile) ==============
#define GT 256
#define KC 32
#define TILE_BYTES 8192                    // 128 rows x 32 bf16
#define BUF_BYTES (4 * TILE_BYTES)         // Ah Al Bh Bl
#define SMEM_GEMM (2 * BUF_BYTES)          // 64 KB double-buffered

// swizzled smem offset of (row, 16B-chunk): rows are 64B (4 chunks)
__device__ __forceinline__ uint32_t swz(int row, int chunk) {
    return (uint32_t)(row * 64 + ((chunk ^ ((row >> 1) & 3)) * 16));
}

// async-load one 128x32 bf16 tile (row-major source, k-contiguous)
__device__ __forceinline__ void load_tile_async(uint32_t sbase,
                                                const bf16* __restrict__ src,
                                                size_t row0, size_t ld) {
    int t = threadIdx.x;
#pragma unroll
    for (int i = 0; i < 2; i++) {
        int id = t + i * 256;
        int row = id >> 2, c = id & 3;
        const bf16* g = src + (row0 + row) * ld + c * 8;
        CP_ASYNC16(sbase + swz(row, c), g);
    }
}

// STAGE 0: proj (z: 0=q,1=k,2=v)  A [16384x1024], B wT [128x1024], K=1024
// STAGE 1: scores                 A qh, B kh, K=128
// STAGE 2: attnv                  A attn, B vhT [128x2048], K=2048
// STAGE 3: out proj               A x (chunked across views), B woT, K=1024
template <int STAGE>
__global__ __launch_bounds__(GT, 1)
void gemm_kernel(const float* __restrict__ p0, const float* __restrict__ p1,
                 const float* __restrict__ p2, float* __restrict__ pout) {
    extern __shared__ char smem[];
    const uint32_t sb = smem_u32(smem);
    const int tid = threadIdx.x, wid = tid >> 5, lane = tid & 31;
    const int wm = wid & 1, wn = wid >> 1;       // warp grid 2 (M) x 4 (N)

    // ---- stage config ----
    const bf16 *Ah0 = nullptr, *Al0 = nullptr, *Bh0 = nullptr, *Bl0 = nullptr;
    size_t ldA = 0, ldB = 0, rowA0 = 0, rowB0 = 0;
    int K_TOTAL = 0;
    if constexpr (STAGE == 0) {
        int z = blockIdx.z;
        Ah0 = z == 0 ? g_q_hi : z == 1 ? g_k_hi : g_v_hi;
        Al0 = z == 0 ? g_q_lo : z == 1 ? g_k_lo : g_v_lo;
        Bh0 = z == 0 ? g_wqT_h : z == 1 ? g_wkT_h : g_wvT_h;
        Bl0 = z == 0 ? g_wqT_l : z == 1 ? g_wkT_l : g_wvT_l;
        ldA = HID; ldB = HID; rowA0 = (size_t)blockIdx.x * 128; K_TOTAL = HID;
    } else if constexpr (STAGE == 1) {
        size_t z = blockIdx.z;
        Ah0 = g_qh_h + z * SEQ * ATT; Al0 = g_qh_l + z * SEQ * ATT;
        Bh0 = g_kh_h + z * SEQ * ATT; Bl0 = g_kh_l + z * SEQ * ATT;
        ldA = ATT; ldB = ATT;
        rowA0 = (size_t)blockIdx.x * 128; rowB0 = (size_t)blockIdx.y * 128; K_TOTAL = ATT;
    } else if constexpr (STAGE == 2) {
        size_t z = blockIdx.z;
        Ah0 = g_attn_h + z * (size_t)SEQ * SEQ; Al0 = g_attn_l + z * (size_t)SEQ * SEQ;
        Bh0 = g_vhT_h + z * (size_t)ATT * SEQ;  Bl0 = g_vhT_l + z * (size_t)ATT * SEQ;
        ldA = SEQ; ldB = SEQ;
        rowA0 = (size_t)blockIdx.x * 128; K_TOTAL = SEQ;
    } else {
        Bh0 = g_woT_h; Bl0 = g_woT_l;
        ldA = ATT; ldB = HID;
        rowA0 = (size_t)blockIdx.x * 128; rowB0 = (size_t)blockIdx.y * 128; K_TOTAL = HID;
    }
    const int nc = K_TOTAL / KC;

    auto load_chunk = [&](int c, int buf) {
        const int kb = c * KC;
        const uint32_t base = sb + buf * BUF_BYTES;
        const bf16 *pAh, *pAl;
        if constexpr (STAGE == 3) {
            size_t voff = (size_t)(kb >> 7) * (SEQ * ATT) + (kb & 127);
            pAh = g_x_h + voff; pAl = g_x_l + voff;
        } else {
            pAh = Ah0 + kb; pAl = Al0 + kb;
        }
        load_tile_async(base,                  pAh,      rowA0, ldA);
        load_tile_async(base + TILE_BYTES,     pAl,      rowA0, ldA);
        load_tile_async(base + 2 * TILE_BYTES, Bh0 + kb, rowB0, ldB);
        load_tile_async(base + 3 * TILE_BYTES, Bl0 + kb, rowB0, ldB);
    };

    float acc[4][4][4];
#pragma unroll
    for (int a = 0; a < 4; a++)
#pragma unroll
        for (int b = 0; b < 4; b++)
#pragma unroll
            for (int r2 = 0; r2 < 4; r2++) acc[a][b][r2] = 0.f;

    // per-thread ldmatrix row/chunk bases
    const int j8 = lane >> 3, r8 = lane & 7;
    const int aRowB = wm * 64 + (j8 & 1) * 8 + r8;   // + mt*16
    const int aChB  = (j8 >> 1);                     // + c0
    const int bRowB = wn * 32 + (j8 >> 1) * 8 + r8;  // + g*16
    const int bChB  = (j8 & 1);                      // + c0

    load_chunk(0, 0);
    CP_COMMIT();

    for (int c = 0; c < nc; c++) {
        if (c + 1 < nc) {
            load_chunk(c + 1, (c + 1) & 1);
            CP_COMMIT();
            CP_WAIT1();
        } else {
            CP_WAIT0();
        }
        __syncthreads();

        const uint32_t base = sb + (c & 1) * BUF_BYTES;
        const uint32_t aB = base, alB = base + TILE_BYTES;
        const uint32_t bB = base + 2 * TILE_BYTES, blB = base + 3 * TILE_BYTES;
#pragma unroll
        for (int s = 0; s < 2; s++) {
            const int c0 = 2 * s;
            uint32_t ah[4][4], al[4][4], bh[2][4], bl[2][4];
#pragma unroll
            for (int mt = 0; mt < 4; mt++) {
                LDSM4(ah[mt], aB  + swz(aRowB + mt * 16, aChB + c0));
                LDSM4(al[mt], alB + swz(aRowB + mt * 16, aChB + c0));
            }
#pragma unroll
            for (int g = 0; g < 2; g++) {
                LDSM4(bh[g], bB  + swz(bRowB + g * 16, bChB + c0));
                LDSM4(bl[g], blB + swz(bRowB + g * 16, bChB + c0));
            }
#pragma unroll
            for (int mt = 0; mt < 4; mt++)
#pragma unroll
                for (int nt = 0; nt < 4; nt++) {
                    const int g = nt >> 1, p = (nt & 1) * 2;
                    MMA16816(acc[mt][nt], ah[mt], bh[g][p], bh[g][p + 1]);
                    MMA16816(acc[mt][nt], ah[mt], bl[g][p], bl[g][p + 1]);
                    MMA16816(acc[mt][nt], al[mt], bh[g][p], bh[g][p + 1]);
                }
        }
        __syncthreads();
    }

    // ---- epilogue ----
    const int gid = lane >> 2, tig = lane & 3;
#pragma unroll
    for (int mt = 0; mt < 4; mt++) {
#pragma unroll
        for (int h = 0; h < 2; h++) {
            const int m = (int)(blockIdx.x * 128) + wm * 64 + mt * 16 + gid + h * 8;
#pragma unroll
            for (int nt = 0; nt < 4; nt++) {
                const int n = wn * 32 + nt * 8 + tig * 2;
                float v0 = acc[mt][nt][h * 2];
                float v1 = acc[mt][nt][h * 2 + 1];
                if constexpr (STAGE == 0) {
                    int z = blockIdx.z;
                    const float* bias = z == 0 ? p0 : z == 1 ? p1 : p2;
                    if (z == 2) {
                        float2 w; w.x = v0 + bias[n]; w.y = v1 + bias[n + 1];
                        *reinterpret_cast<float2*>(g_vh + (size_t)m * ATT + n) = w;
                    } else {
                        float scl = (z == 0) ? SCALE : 1.f;
                        v0 = (v0 + bias[n]) * scl; v1 = (v1 + bias[n + 1]) * scl;
                        bf16 h0, l0, h1, l1; split2(v0, h0, l0); split2(v1, h1, l1);
                        bf162 hh; hh.x = h0; hh.y = h1;
                        bf162 ll; ll.x = l0; ll.y = l1;
                        bf16* dh = z == 0 ? g_qh_h : g_kh_h;
                        bf16* dl = z == 0 ? g_qh_l : g_kh_l;
                        size_t o = (size_t)m * ATT + n;
                        *reinterpret_cast<bf162*>(dh + o) = hh;
                        *reinterpret_cast<bf162*>(dl + o) = ll;
                    }
                } else if constexpr (STAGE == 1) {
                    size_t z = blockIdx.z;
                    float2 w; w.x = v0; w.y = v1;
                    *reinterpret_cast<float2*>(g_scores + (z * SEQ + m) * (size_t)SEQ
                                               + blockIdx.y * 128 + n) = w;
                } else if constexpr (STAGE == 2) {
                    size_t z = blockIdx.z;
                    bf16 h0, l0, h1, l1; split2(v0, h0, l0); split2(v1, h1, l1);
                    bf162 hh; hh.x = h0; hh.y = h1;
                    bf162 ll; ll.x = l0; ll.y = l1;
                    size_t o = (z * SEQ + m) * (size_t)ATT + n;
                    *reinterpret_cast<bf162*>(g_x_h + o) = hh;
                    *reinterpret_cast<bf162*>(g_x_l + o) = ll;
                } else {
                    const int ng = (int)(blockIdx.y * 128) + n;
                    float2 w; w.x = v0 + p0[ng]; w.y = v1 + p0[ng + 1];
                    *reinterpret_cast<float2*>(pout + (size_t)m * HID + ng) = w;
                }
            }
        }
    }
}

// ======================= softmax + post-softmax bias -> attn hi/lo =========
#define SMT 256
__global__ __launch_bounds__(SMT) void softmax_bias_kernel(const float* __restrict__ bias) {
    const size_t row = blockIdx.x;            // 0 .. VIEW*SEQ-1
    const float* p = g_scores + row * SEQ;
    const float* b = bias + row * SEQ;
    const int tid = threadIdx.x;

    float vreg[SEQ / SMT];
    float lmax = -1e30f;
#pragma unroll
    for (int i = 0; i < SEQ / SMT; i++) {
        vreg[i] = p[tid + i * SMT];
        lmax = fmaxf(lmax, vreg[i]);
    }
    __shared__ float red[SMT / 32];
#pragma unroll
    for (int off = 16; off; off >>= 1)
        lmax = fmaxf(lmax, __shfl_xor_sync(0xffffffffu, lmax, off));
    if ((tid & 31) == 0) red[tid >> 5] = lmax;
    __syncthreads();
    float m = red[0];
#pragma unroll
    for (int w = 1; w < SMT / 32; w++) m = fmaxf(m, red[w]);

    float lsum = 0.f;
#pragma unroll
    for (int i = 0; i < SEQ / SMT; i++) {
        vreg[i] = __expf(vreg[i] - m);
        lsum += vreg[i];
    }
#pragma unroll
    for (int off = 16; off; off >>= 1)
        lsum += __shfl_xor_sync(0xffffffffu, lsum, off);
    __syncthreads();
    if ((tid & 31) == 0) red[tid >> 5] = lsum;
    __syncthreads();
    float s = 0.f;
#pragma unroll
    for (int w = 0; w < SMT / 32; w++) s += red[w];
    const float inv = 1.f / s;
#pragma unroll
    for (int i = 0; i < SEQ / SMT; i++) {
        int idx = tid + i * SMT;
        float val = vreg[i] * inv + b[idx];
        bf16 h, l; split2(val, h, l);
        g_attn_h[row * SEQ + idx] = h;
        g_attn_l[row * SEQ + idx] = l;
    }
}

// ======================= launch ============================================
extern "C" void kernel_launch(void* const* d_in, const int* in_sizes, int n_in,
                              void* d_out, int out_size) {
    const float* q         = (const float*)d_in[0];
    const float* k         = (const float*)d_in[1];
    const float* v         = (const float*)d_in[2];
    const float* attn_bias = (const float*)d_in[3];
    const float* wq        = (const float*)d_in[4];
    const float* bq        = (const float*)d_in[5];
    const float* wk        = (const float*)d_in[6];
    const float* bk        = (const float*)d_in[7];
    const float* wv        = (const float*)d_in[8];
    const float* bv        = (const float*)d_in[9];
    const float* wo        = (const float*)d_in[10];
    const float* bo        = (const float*)d_in[11];
    float* out = (float*)d_out;

    cudaFuncSetAttribute(gemm_kernel<0>, cudaFuncAttributeMaxDynamicSharedMemorySize, SMEM_GEMM);
    cudaFuncSetAttribute(gemm_kernel<1>, cudaFuncAttributeMaxDynamicSharedMemorySize, SMEM_GEMM);
    cudaFuncSetAttribute(gemm_kernel<2>, cudaFuncAttributeMaxDynamicSharedMemorySize, SMEM_GEMM);
    cudaFuncSetAttribute(gemm_kernel<3>, cudaFuncAttributeMaxDynamicSharedMemorySize, SMEM_GEMM);

    // 1) split inputs into bf16 hi/lo
    split_inputs_kernel<<<dim3((VIEW * SEQ * HID / 4) / 256, 1, 3), 256>>>(q, k, v);
    // 2) transpose+split weights: wT[n][k] (device globals referenced device-side)
    transpose_split_w_kernel<<<dim3(ATT / 32, HID / 32), dim3(32, 8)>>>(wq, 0);
    transpose_split_w_kernel<<<dim3(ATT / 32, HID / 32), dim3(32, 8)>>>(wk, 1);
    transpose_split_w_kernel<<<dim3(ATT / 32, HID / 32), dim3(32, 8)>>>(wv, 2);
    transpose_split_w_kernel<<<dim3(HID / 32, HID / 32), dim3(32, 8)>>>(wo, 3);
    // 3) projections -> qh/kh (bf16 hi/lo), vh (fp32)
    gemm_kernel<0><<<dim3(VIEW * SEQ / 128, 1, 3), GT, SMEM_GEMM>>>(bq, bk, bv, nullptr);
    // 4) transpose+split vh -> vhT[a][s]
    transpose_split_vh_kernel<<<dim3(ATT / 32, SEQ / 32, VIEW), dim3(32, 8)>>>();
    // 5) scores (fp32)
    gemm_kernel<1><<<dim3(SEQ / 128, SEQ / 128, VIEW), GT, SMEM_GEMM>>>(nullptr, nullptr, nullptr, nullptr);
    // 6) softmax + bias -> attn hi/lo
    softmax_bias_kernel<<<dim3(VIEW * SEQ), SMT>>>(attn_bias);
    // 7) attn @ vh -> x hi/lo
    gemm_kernel<2><<<dim3(SEQ / 128, 1, VIEW), GT, SMEM_GEMM>>>(nullptr, nullptr, nullptr, nullptr);
    // 8) output projection
    gemm_kernel<3><<<dim3(SEQ / 128, HID / 128, 1), GT, SMEM_GEMM>>>(bo, nullptr, nullptr, out);
}

// round 5
// speedup vs baseline: 3.0278x; 1.1182x over previous
#include <cuda_runtime.h>
#include <cuda_bf16.h>
#include <cstdint>
#include <math.h>

#define VIEW 8
#define SEQ  2048
#define HID  1024
#define ATT  128
#define SCALE 0.08838834764831845f   // ATT^-0.5

using bf16 = __nv_bfloat16;
using bf162 = __nv_bfloat162;

// ======================= device scratch (no allocs allowed) =================
__device__ __align__(256) bf16 g_wqT_h[ATT*HID], g_wqT_l[ATT*HID];      // [n=128][k=1024]
__device__ __align__(256) bf16 g_wkT_h[ATT*HID], g_wkT_l[ATT*HID];
__device__ __align__(256) bf16 g_wvT_h[ATT*HID], g_wvT_l[ATT*HID];
__device__ __align__(256) bf16 g_woT_h[HID*HID], g_woT_l[HID*HID];      // [h=1024][c=1024]
__device__ __align__(256) bf16 g_qh_h[VIEW*SEQ*ATT], g_qh_l[VIEW*SEQ*ATT];
__device__ __align__(256) bf16 g_kh_h[VIEW*SEQ*ATT], g_kh_l[VIEW*SEQ*ATT];
__device__ __align__(256) bf16 g_vh_h[VIEW*SEQ*ATT], g_vh_l[VIEW*SEQ*ATT]; // [v][s][a]
__device__ __align__(256) float g_scores[(size_t)VIEW*SEQ*SEQ];          // 134MB
__device__ __align__(256) bf16 g_attn_h[(size_t)VIEW*SEQ*SEQ], g_attn_l[(size_t)VIEW*SEQ*SEQ];
__device__ __align__(256) bf16 g_x_h[VIEW*SEQ*ATT], g_x_l[VIEW*SEQ*ATT];

// ======================= helpers ===========================================
__device__ __forceinline__ uint32_t smem_u32(const void* p) {
    uint32_t a;
    asm("{ .reg .u64 t; cvta.to.shared.u64 t, %1; cvt.u32.u64 %0, t; }" : "=r"(a) : "l"(p));
    return a;
}
__device__ __forceinline__ void split2(float x, bf16& h, bf16& l) {
    h = __float2bfloat16(x);
    l = __float2bfloat16(x - __bfloat162float(h));
}
__device__ __forceinline__ void split_pack(float a, float b, uint32_t& uh, uint32_t& ul) {
    bf16 ha, la, hb, lb; split2(a, ha, la); split2(b, hb, lb);
    bf162 H; H.x = ha; H.y = hb; uh = *reinterpret_cast<uint32_t*>(&H);
    bf162 L; L.x = la; L.y = lb; ul = *reinterpret_cast<uint32_t*>(&L);
}

#define CP_ASYNC16(saddr, gptr) \
    asm volatile("cp.async.cg.shared.global [%0], [%1], 16;" \
                 :: "r"(saddr), "l"(__cvta_generic_to_global(gptr)) : "memory")
#define CP_COMMIT() asm volatile("cp.async.commit_group;" ::: "memory")
#define CP_WAIT0()  asm volatile("cp.async.wait_group 0;" ::: "memory")
#define CP_WAIT1()  asm volatile("cp.async.wait_group 1;" ::: "memory")

#define LDSM4(R, addr) \
    asm volatile("ldmatrix.sync.aligned.m8n8.x4.shared.b16 {%0,%1,%2,%3}, [%4];" \
                 : "=r"((R)[0]), "=r"((R)[1]), "=r"((R)[2]), "=r"((R)[3]) : "r"(addr))
#define LDSM4T(R, addr) \
    asm volatile("ldmatrix.sync.aligned.m8n8.x4.trans.shared.b16 {%0,%1,%2,%3}, [%4];" \
                 : "=r"((R)[0]), "=r"((R)[1]), "=r"((R)[2]), "=r"((R)[3]) : "r"(addr))

#define MMA16816(C, A, b0, b1) \
    asm volatile("mma.sync.aligned.m16n8k16.row.col.f32.bf16.bf16.f32 " \
                 "{%0,%1,%2,%3},{%4,%5,%6,%7},{%8,%9},{%0,%1,%2,%3};" \
                 : "+f"((C)[0]), "+f"((C)[1]), "+f"((C)[2]), "+f"((C)[3]) \
                 : "r"((A)[0]), "r"((A)[1]), "r"((A)[2]), "r"((A)[3]), "r"(b0), "r"(b1))

// ======================= weight transpose+split ============================
// in: [R=HID][C], out: [C][R].  grid (C/32, R/32), block (32,8)
__global__ void transpose_split_w_kernel(const float* __restrict__ in, int mode) {
    __shared__ float t[32][33];
    bf16 *dh, *dl; int C;
    if (mode == 0)      { dh = g_wqT_h; dl = g_wqT_l; C = ATT; }
    else if (mode == 1) { dh = g_wkT_h; dl = g_wkT_l; C = ATT; }
    else if (mode == 2) { dh = g_wvT_h; dl = g_wvT_l; C = ATT; }
    else                { dh = g_woT_h; dl = g_woT_l; C = HID; }
    const int R = HID;
    int c0 = blockIdx.x * 32, r0 = blockIdx.y * 32;
    int tx = threadIdx.x, ty = threadIdx.y;
#pragma unroll
    for (int i = 0; i < 4; i++)
        t[ty + i*8][tx] = in[(size_t)(r0 + ty + i*8) * C + c0 + tx];
    __syncthreads();
#pragma unroll
    for (int i = 0; i < 4; i++) {
        float x = t[tx][ty + i*8];
        bf16 h, l; split2(x, h, l);
        size_t o = (size_t)(c0 + ty + i*8) * R + r0 + tx;
        dh[o] = h; dl[o] = l;
    }
}

// ======================= warp-MMA GEMM (bf16x3, 128x128 tile) ==============
#define GT 256
#define KC 32
#define TILE_BYTES 8192                     // 128 rows x 32 bf16 (64B rows)
#define ABUF_BYTES 16384                    // Ah + Al
#define FP_BYTES 16384                      // 128 rows x 32 fp32 (128B rows)
#define SMEM_GEMM_STD 65536                 // A dbl 32K + B dbl 32K
#define SMEM_GEMM_S0  81920                 // fp dbl 32K + Ahl 16K + B dbl 32K

// swizzled smem offset (64B rows, 4 x 16B chunks)
__device__ __forceinline__ uint32_t swz(int row, int chunk) {
    return (uint32_t)(row * 64 + ((chunk ^ ((row >> 1) & 3)) * 16));
}
// swizzled smem offset (256B rows, 16 x 16B chunks) for vh tiles
__device__ __forceinline__ uint32_t swz256(int row, int chunk) {
    return (uint32_t)(row * 256 + ((chunk ^ (row & 7)) * 16));
}
// swizzled fp32 staging (128B rows, 8 x 16B chunks)
__device__ __forceinline__ uint32_t swzfp(int row, int chunk) {
    return (uint32_t)(row * 128 + ((chunk ^ (row & 7)) * 16));
}

// async-load one 128x32 bf16 tile (row-major source, k-contiguous, 64B rows)
__device__ __forceinline__ void load_tile_async(uint32_t sbase,
                                                const bf16* __restrict__ src,
                                                size_t row0, size_t ld) {
    int t = threadIdx.x;
#pragma unroll
    for (int i = 0; i < 2; i++) {
        int id = t + i * 256;
        int row = id >> 2, c = id & 3;
        CP_ASYNC16(sbase + swz(row, c), src + (row0 + row) * ld + c * 8);
    }
}
// async-load one 32x128 bf16 tile (vh chunk; 256B rows)
__device__ __forceinline__ void load_vtile_async(uint32_t sbase,
                                                 const bf16* __restrict__ src,
                                                 size_t row0) {
    int t = threadIdx.x;
#pragma unroll
    for (int i = 0; i < 2; i++) {
        int id = t + i * 256;
        int row = id >> 4, c = id & 15;
        CP_ASYNC16(sbase + swz256(row, c), src + (row0 + row) * ATT + c * 8);
    }
}
// async-load one 128x32 fp32 tile (128B rows)
__device__ __forceinline__ void load_fp_async(uint32_t sbase,
                                              const float* __restrict__ src,
                                              size_t row0, size_t ld) {
    int t = threadIdx.x;
#pragma unroll
    for (int i = 0; i < 4; i++) {
        int id = t + i * 256;
        int row = id >> 3, c = id & 7;
        CP_ASYNC16(sbase + swzfp(row, c), src + (row0 + row) * ld + c * 4);
    }
}

// STAGE 0: proj (z: 0=q,1=k,2=v)  A = fp32 input [16384x1024] (split in-kernel), B wT, K=1024
// STAGE 1: scores                 A qh, B kh, K=128
// STAGE 2: attnv                  A attn, B vh [s][a] via ldmatrix.trans, K=2048
// STAGE 3: out proj               A x (chunked across views), B woT, K=1024
template <int STAGE>
__global__ __launch_bounds__(GT, 1)
void gemm_kernel(const float* __restrict__ i0, const float* __restrict__ i1,
                 const float* __restrict__ i2, const float* __restrict__ b0,
                 const float* __restrict__ b1, const float* __restrict__ b2,
                 float* __restrict__ pout) {
    extern __shared__ char smem[];
    const uint32_t sb = smem_u32(smem);
    const int tid = threadIdx.x, wid = tid >> 5, lane = tid & 31;
    const int wm = wid & 1, wn = wid >> 1;       // warp grid 2 (M) x 4 (N)

    // ---- stage config ----
    const bf16 *Ah0 = nullptr, *Al0 = nullptr, *Bh0 = nullptr, *Bl0 = nullptr;
    const float* Xf = nullptr;
    size_t ldA = 0, ldB = 0, rowA0 = 0, rowB0 = 0;
    int K_TOTAL = 0;
    if constexpr (STAGE == 0) {
        int z = blockIdx.z;
        Xf  = z == 0 ? i0 : z == 1 ? i1 : i2;
        Bh0 = z == 0 ? g_wqT_h : z == 1 ? g_wkT_h : g_wvT_h;
        Bl0 = z == 0 ? g_wqT_l : z == 1 ? g_wkT_l : g_wvT_l;
        ldA = HID; ldB = HID; rowA0 = (size_t)blockIdx.x * 128; K_TOTAL = HID;
    } else if constexpr (STAGE == 1) {
        size_t z = blockIdx.z;
        Ah0 = g_qh_h + z * SEQ * ATT; Al0 = g_qh_l + z * SEQ * ATT;
        Bh0 = g_kh_h + z * SEQ * ATT; Bl0 = g_kh_l + z * SEQ * ATT;
        ldA = ATT; ldB = ATT;
        rowA0 = (size_t)blockIdx.x * 128; rowB0 = (size_t)blockIdx.y * 128; K_TOTAL = ATT;
    } else if constexpr (STAGE == 2) {
        size_t z = blockIdx.z;
        Ah0 = g_attn_h + z * (size_t)SEQ * SEQ; Al0 = g_attn_l + z * (size_t)SEQ * SEQ;
        Bh0 = g_vh_h + z * (size_t)SEQ * ATT;   Bl0 = g_vh_l + z * (size_t)SEQ * ATT;
        ldA = SEQ;
        rowA0 = (size_t)blockIdx.x * 128; K_TOTAL = SEQ;
    } else {
        Bh0 = g_woT_h; Bl0 = g_woT_l;
        ldA = ATT; ldB = HID;
        rowA0 = (size_t)blockIdx.x * 128; rowB0 = (size_t)blockIdx.y * 128; K_TOTAL = HID;
    }
    const int nc = K_TOTAL / KC;

    // smem region bases
    const uint32_t B_OFF = (STAGE == 0) ? 49152u : 32768u;
    const uint32_t AH_OFF = 32768u, AL_OFF = 40960u;   // stage-0 converted tiles

    auto load_chunk = [&](int c, int buf) {
        const int kb = c * KC;
        if constexpr (STAGE == 0) {
            load_fp_async(sb + buf * FP_BYTES, Xf + kb, rowA0, ldA);
        } else if constexpr (STAGE == 3) {
            size_t voff = (size_t)(kb >> 7) * (SEQ * ATT) + (kb & 127);
            load_tile_async(sb + buf * ABUF_BYTES,        g_x_h + voff, rowA0, ldA);
            load_tile_async(sb + buf * ABUF_BYTES + 8192, g_x_l + voff, rowA0, ldA);
        } else {
            load_tile_async(sb + buf * ABUF_BYTES,        Ah0 + kb, rowA0, ldA);
            load_tile_async(sb + buf * ABUF_BYTES + 8192, Al0 + kb, rowA0, ldA);
        }
        if constexpr (STAGE == 2) {
            load_vtile_async(sb + B_OFF + buf * ABUF_BYTES,        Bh0, (size_t)kb);
            load_vtile_async(sb + B_OFF + buf * ABUF_BYTES + 8192, Bl0, (size_t)kb);
        } else {
            load_tile_async(sb + B_OFF + buf * ABUF_BYTES,        Bh0 + kb, rowB0, ldB);
            load_tile_async(sb + B_OFF + buf * ABUF_BYTES + 8192, Bl0 + kb, rowB0, ldB);
        }
    };

    float acc[4][4][4];
#pragma unroll
    for (int a = 0; a < 4; a++)
#pragma unroll
        for (int b = 0; b < 4; b++)
#pragma unroll
            for (int r2 = 0; r2 < 4; r2++) acc[a][b][r2] = 0.f;

    const int j8 = lane >> 3, r8 = lane & 7;
    const int aRowB = wm * 64 + (j8 & 1) * 8 + r8;   // + mt*16
    const int aChB  = (j8 >> 1);                     // + c0
    const int bRowB = wn * 32 + (j8 >> 1) * 8 + r8;  // + g*16 (non-trans B)
    const int bChB  = (j8 & 1);                      // + c0
    const int vRowB = (j8 & 1) * 8 + r8;             // + s*16 (trans B, stage 2)
    const int vChB  = wn * 4 + (j8 >> 1);            // + g*2

    load_chunk(0, 0);
    CP_COMMIT();

    for (int c = 0; c < nc; c++) {
        if (c + 1 < nc) {
            load_chunk(c + 1, (c + 1) & 1);
            CP_COMMIT();
            CP_WAIT1();
        } else {
            CP_WAIT0();
        }
        __syncthreads();

        if constexpr (STAGE == 0) {
            // convert fp staging -> Ah/Al bf16 tiles
            const char* fpb = smem + (c & 1) * FP_BYTES;
            const int row = tid >> 1, q = tid & 1;
            float4 f[4];
#pragma unroll
            for (int i = 0; i < 4; i++)
                f[i] = *reinterpret_cast<const float4*>(fpb + swzfp(row, q * 4 + i));
#pragma unroll
            for (int j = 0; j < 2; j++) {
                uint4 hh, ll;
                split_pack(f[2*j].x,   f[2*j].y,   hh.x, ll.x);
                split_pack(f[2*j].z,   f[2*j].w,   hh.y, ll.y);
                split_pack(f[2*j+1].x, f[2*j+1].y, hh.z, ll.z);
                split_pack(f[2*j+1].z, f[2*j+1].w, hh.w, ll.w);
                *reinterpret_cast<uint4*>(smem + AH_OFF + swz(row, q * 2 + j)) = hh;
                *reinterpret_cast<uint4*>(smem + AL_OFF + swz(row, q * 2 + j)) = ll;
            }
            __syncthreads();
        }

        const uint32_t aB  = (STAGE == 0) ? sb + AH_OFF : sb + (c & 1) * ABUF_BYTES;
        const uint32_t alB = (STAGE == 0) ? sb + AL_OFF : sb + (c & 1) * ABUF_BYTES + 8192;
        const uint32_t bB  = sb + B_OFF + (c & 1) * ABUF_BYTES;
        const uint32_t blB = bB + 8192;
#pragma unroll
        for (int s = 0; s < 2; s++) {
            const int c0 = 2 * s;
            uint32_t ah[4][4], al[4][4], bh[2][4], bl[2][4];
#pragma unroll
            for (int mt = 0; mt < 4; mt++) {
                LDSM4(ah[mt], aB  + swz(aRowB + mt * 16, aChB + c0));
                LDSM4(al[mt], alB + swz(aRowB + mt * 16, aChB + c0));
            }
#pragma unroll
            for (int g = 0; g < 2; g++) {
                if constexpr (STAGE == 2) {
                    LDSM4T(bh[g], bB  + swz256(s * 16 + vRowB, vChB + g * 2));
                    LDSM4T(bl[g], blB + swz256(s * 16 + vRowB, vChB + g * 2));
                } else {
                    LDSM4(bh[g], bB  + swz(bRowB + g * 16, bChB + c0));
                    LDSM4(bl[g], blB + swz(bRowB + g * 16, bChB + c0));
                }
            }
#pragma unroll
            for (int mt = 0; mt < 4; mt++)
#pragma unroll
                for (int nt = 0; nt < 4; nt++) {
                    const int g = nt >> 1, p = (nt & 1) * 2;
                    MMA16816(acc[mt][nt], ah[mt], bh[g][p], bh[g][p + 1]);
                    MMA16816(acc[mt][nt], ah[mt], bl[g][p], bl[g][p + 1]);
                    MMA16816(acc[mt][nt], al[mt], bh[g][p], bh[g][p + 1]);
                }
        }
        __syncthreads();
    }

    // ---- epilogue ----
    const int gid = lane >> 2, tig = lane & 3;
#pragma unroll
    for (int mt = 0; mt < 4; mt++) {
#pragma unroll
        for (int h = 0; h < 2; h++) {
            const int m = (int)(blockIdx.x * 128) + wm * 64 + mt * 16 + gid + h * 8;
#pragma unroll
            for (int nt = 0; nt < 4; nt++) {
                const int n = wn * 32 + nt * 8 + tig * 2;
                float v0 = acc[mt][nt][h * 2];
                float v1 = acc[mt][nt][h * 2 + 1];
                if constexpr (STAGE == 0) {
                    int z = blockIdx.z;
                    const float* bias = z == 0 ? b0 : z == 1 ? b1 : b2;
                    float scl = (z == 0) ? SCALE : 1.f;
                    v0 = (v0 + bias[n]) * scl; v1 = (v1 + bias[n + 1]) * scl;
                    bf16 h0, l0, h1, l1; split2(v0, h0, l0); split2(v1, h1, l1);
                    bf162 hh; hh.x = h0; hh.y = h1;
                    bf162 ll; ll.x = l0; ll.y = l1;
                    bf16* dh = z == 0 ? g_qh_h : z == 1 ? g_kh_h : g_vh_h;
                    bf16* dl = z == 0 ? g_qh_l : z == 1 ? g_kh_l : g_vh_l;
                    size_t o = (size_t)m * ATT + n;
                    *reinterpret_cast<bf162*>(dh + o) = hh;
                    *reinterpret_cast<bf162*>(dl + o) = ll;
                } else if constexpr (STAGE == 1) {
                    size_t z = blockIdx.z;
                    float2 w; w.x = v0; w.y = v1;
                    *reinterpret_cast<float2*>(g_scores + (z * SEQ + m) * (size_t)SEQ
                                               + blockIdx.y * 128 + n) = w;
                } else if constexpr (STAGE == 2) {
                    size_t z = blockIdx.z;
                    bf16 h0, l0, h1, l1; split2(v0, h0, l0); split2(v1, h1, l1);
                    bf162 hh; hh.x = h0; hh.y = h1;
                    bf162 ll; ll.x = l0; ll.y = l1;
                    size_t o = (z * SEQ + m) * (size_t)ATT + n;
                    *reinterpret_cast<bf162*>(g_x_h + o) = hh;
                    *reinterpret_cast<bf162*>(g_x_l + o) = ll;
                } else {
                    const int ng = (int)(blockIdx.y * 128) + n;
                    float2 w; w.x = v0 + b0[ng]; w.y = v1 + b0[ng + 1];
                    *reinterpret_cast<float2*>(pout + (size_t)m * HID + ng) = w;
                }
            }
        }
    }
}

// ======================= softmax + post-softmax bias -> attn hi/lo =========
#define SMT 256
__global__ __launch_bounds__(SMT) void softmax_bias_kernel(const float* __restrict__ bias) {
    const size_t row = blockIdx.x;            // 0 .. VIEW*SEQ-1
    const float4* p4 = reinterpret_cast<const float4*>(g_scores + row * SEQ);
    const float4* b4 = reinterpret_cast<const float4*>(bias + row * SEQ);
    const int tid = threadIdx.x;

    float4 v[2];
    float lmax = -1e30f;
#pragma unroll
    for (int i = 0; i < 2; i++) {
        v[i] = p4[tid + i * SMT];
        lmax = fmaxf(fmaxf(fmaxf(v[i].x, v[i].y), fmaxf(v[i].z, v[i].w)), lmax);
    }
    __shared__ float red[SMT / 32];
#pragma unroll
    for (int off = 16; off; off >>= 1)
        lmax = fmaxf(lmax, __shfl_xor_sync(0xffffffffu, lmax, off));
    if ((tid & 31) == 0) red[tid >> 5] = lmax;
    __syncthreads();
    float m = red[0];
#pragma unroll
    for (int w = 1; w < SMT / 32; w++) m = fmaxf(m, red[w]);

    float lsum = 0.f;
#pragma unroll
    for (int i = 0; i < 2; i++) {
        v[i].x = __expf(v[i].x - m); v[i].y = __expf(v[i].y - m);
        v[i].z = __expf(v[i].z - m); v[i].w = __expf(v[i].w - m);
        lsum += (v[i].x + v[i].y) + (v[i].z + v[i].w);
    }
#pragma unroll
    for (int off = 16; off; off >>= 1)
        lsum += __shfl_xor_sync(0xffffffffu, lsum, off);
    __syncthreads();
    if ((tid & 31) == 0) red[tid >> 5] = lsum;
    __syncthreads();
    float s = 0.f;
#pragma unroll
    for (int w = 0; w < SMT / 32; w++) s += red[w];
    const float inv = 1.f / s;
#pragma unroll
    for (int i = 0; i < 2; i++) {
        const int idx4 = tid + i * SMT;
        float4 b = b4[idx4];
        float r0 = v[i].x * inv + b.x, r1 = v[i].y * inv + b.y;
        float r2 = v[i].z * inv + b.z, r3 = v[i].w * inv + b.w;
        uint2 hh, ll;
        split_pack(r0, r1, hh.x, ll.x);
        split_pack(r2, r3, hh.y, ll.y);
        *reinterpret_cast<uint2*>(g_attn_h + row * SEQ + idx4 * 4) = hh;
        *reinterpret_cast<uint2*>(g_attn_l + row * SEQ + idx4 * 4) = ll;
    }
}

// ======================= launch ============================================
extern "C" void kernel_launch(void* const* d_in, const int* in_sizes, int n_in,
                              void* d_out, int out_size) {
    const float* q         = (const float*)d_in[0];
    const float* k         = (const float*)d_in[1];
    const float* v         = (const float*)d_in[2];
    const float* attn_bias = (const float*)d_in[3];
    const float* wq        = (const float*)d_in[4];
    const float* bq        = (const float*)d_in[5];
    const float* wk        = (const float*)d_in[6];
    const float* bk        = (const float*)d_in[7];
    const float* wv        = (const float*)d_in[8];
    const float* bv        = (const float*)d_in[9];
    const float* wo        = (const float*)d_in[10];
    const float* bo        = (const float*)d_in[11];
    float* out = (float*)d_out;

    cudaFuncSetAttribute(gemm_kernel<0>, cudaFuncAttributeMaxDynamicSharedMemorySize, SMEM_GEMM_S0);
    cudaFuncSetAttribute(gemm_kernel<1>, cudaFuncAttributeMaxDynamicSharedMemorySize, SMEM_GEMM_STD);
    cudaFuncSetAttribute(gemm_kernel<2>, cudaFuncAttributeMaxDynamicSharedMemorySize, SMEM_GEMM_STD);
    cudaFuncSetAttribute(gemm_kernel<3>, cudaFuncAttributeMaxDynamicSharedMemorySize, SMEM_GEMM_STD);

    // 1) transpose+split weights: wT[n][k] (device globals referenced device-side)
    transpose_split_w_kernel<<<dim3(ATT / 32, HID / 32), dim3(32, 8)>>>(wq, 0);
    transpose_split_w_kernel<<<dim3(ATT / 32, HID / 32), dim3(32, 8)>>>(wk, 1);
    transpose_split_w_kernel<<<dim3(ATT / 32, HID / 32), dim3(32, 8)>>>(wv, 2);
    transpose_split_w_kernel<<<dim3(HID / 32, HID / 32), dim3(32, 8)>>>(wo, 3);
    // 2) projections (fp32 inputs split in-kernel) -> qh/kh/vh bf16 hi/lo
    gemm_kernel<0><<<dim3(VIEW * SEQ / 128, 1, 3), GT, SMEM_GEMM_S0>>>(
        q, k, v, bq, bk, bv, nullptr);
    // 3) scores (fp32)
    gemm_kernel<1><<<dim3(SEQ / 128, SEQ / 128, VIEW), GT, SMEM_GEMM_STD>>>(
        nullptr, nullptr, nullptr, nullptr, nullptr, nullptr, nullptr);
    // 4) softmax + bias -> attn hi/lo
    softmax_bias_kernel<<<dim3(VIEW * SEQ), SMT>>>(attn_bias);
    // 5) attn @ vh -> x hi/lo (vh consumed via ldmatrix.trans, no transpose pass)
    gemm_kernel<2><<<dim3(SEQ / 128, 1, VIEW), GT, SMEM_GEMM_STD>>>(
        nullptr, nullptr, nullptr, nullptr, nullptr, nullptr, nullptr);
    // 6) output projection
    gemm_kernel<3><<<dim3(SEQ / 128, HID / 128, 1), GT, SMEM_GEMM_STD>>>(
        nullptr, nullptr, nullptr, bo, nullptr, nullptr, out);
}

// round 6
// speedup vs baseline: 3.0437x; 1.0053x over previous
#include <cuda_runtime.h>
#include <cuda_bf16.h>
#include <cstdint>
#include <math.h>

#define VIEW 8
#define SEQ  2048
#define HID  1024
#define ATT  128
#define SCALE 0.08838834764831845f   // ATT^-0.5

using bf16 = __nv_bfloat16;
using bf162 = __nv_bfloat162;

// ======================= device scratch (no allocs allowed) =================
__device__ __align__(256) bf16 g_wqT_h[ATT*HID], g_wqT_l[ATT*HID];      // [n=128][k=1024]
__device__ __align__(256) bf16 g_wkT_h[ATT*HID], g_wkT_l[ATT*HID];
__device__ __align__(256) bf16 g_wvT_h[ATT*HID], g_wvT_l[ATT*HID];
__device__ __align__(256) bf16 g_woT_h[HID*HID], g_woT_l[HID*HID];      // [h=1024][c=1024]
__device__ __align__(256) bf16 g_qh_h[VIEW*SEQ*ATT], g_qh_l[VIEW*SEQ*ATT];
__device__ __align__(256) bf16 g_kh_h[VIEW*SEQ*ATT], g_kh_l[VIEW*SEQ*ATT];
__device__ __align__(256) bf16 g_vh_h[VIEW*SEQ*ATT], g_vh_l[VIEW*SEQ*ATT]; // [v][s][a]
__device__ __align__(256) float g_x_bias[VIEW*SEQ*ATT];                  // bias @ vh (fp32)
__device__ __align__(256) bf16 g_x_h[VIEW*SEQ*ATT], g_x_l[VIEW*SEQ*ATT];

// ======================= helpers ===========================================
__device__ __forceinline__ uint32_t smem_u32(const void* p) {
    uint32_t a;
    asm("{ .reg .u64 t; cvta.to.shared.u64 t, %1; cvt.u32.u64 %0, t; }" : "=r"(a) : "l"(p));
    return a;
}
__device__ __forceinline__ void split2(float x, bf16& h, bf16& l) {
    h = __float2bfloat16(x);
    l = __float2bfloat16(x - __bfloat162float(h));
}
__device__ __forceinline__ void split_pack(float a, float b, uint32_t& uh, uint32_t& ul) {
    bf16 ha, la, hb, lb; split2(a, ha, la); split2(b, hb, lb);
    bf162 H; H.x = ha; H.y = hb; uh = *reinterpret_cast<uint32_t*>(&H);
    bf162 L; L.x = la; L.y = lb; ul = *reinterpret_cast<uint32_t*>(&L);
}

#define CP_ASYNC16(saddr, gptr) \
    asm volatile("cp.async.cg.shared.global [%0], [%1], 16;" \
                 :: "r"(saddr), "l"(__cvta_generic_to_global(gptr)) : "memory")
#define CP_COMMIT() asm volatile("cp.async.commit_group;" ::: "memory")
#define CP_WAIT0()  asm volatile("cp.async.wait_group 0;" ::: "memory")
#define CP_WAIT1()  asm volatile("cp.async.wait_group 1;" ::: "memory")

#define LDSM4(R, addr) \
    asm volatile("ldmatrix.sync.aligned.m8n8.x4.shared.b16 {%0,%1,%2,%3}, [%4];" \
                 : "=r"((R)[0]), "=r"((R)[1]), "=r"((R)[2]), "=r"((R)[3]) : "r"(addr))
#define LDSM4T(R, addr) \
    asm volatile("ldmatrix.sync.aligned.m8n8.x4.trans.shared.b16 {%0,%1,%2,%3}, [%4];" \
                 : "=r"((R)[0]), "=r"((R)[1]), "=r"((R)[2]), "=r"((R)[3]) : "r"(addr))

#define MMA16816(C, A, b0, b1) \
    asm volatile("mma.sync.aligned.m16n8k16.row.col.f32.bf16.bf16.f32 " \
                 "{%0,%1,%2,%3},{%4,%5,%6,%7},{%8,%9},{%0,%1,%2,%3};" \
                 : "+f"((C)[0]), "+f"((C)[1]), "+f"((C)[2]), "+f"((C)[3]) \
                 : "r"((A)[0]), "r"((A)[1]), "r"((A)[2]), "r"((A)[3]), "r"(b0), "r"(b1))

// ======================= weight transpose+split ============================
__global__ void transpose_split_w_kernel(const float* __restrict__ in, int mode) {
    __shared__ float t[32][33];
    bf16 *dh, *dl; int C;
    if (mode == 0)      { dh = g_wqT_h; dl = g_wqT_l; C = ATT; }
    else if (mode == 1) { dh = g_wkT_h; dl = g_wkT_l; C = ATT; }
    else if (mode == 2) { dh = g_wvT_h; dl = g_wvT_l; C = ATT; }
    else                { dh = g_woT_h; dl = g_woT_l; C = HID; }
    const int R = HID;
    int c0 = blockIdx.x * 32, r0 = blockIdx.y * 32;
    int tx = threadIdx.x, ty = threadIdx.y;
#pragma unroll
    for (int i = 0; i < 4; i++)
        t[ty + i*8][tx] = in[(size_t)(r0 + ty + i*8) * C + c0 + tx];
    __syncthreads();
#pragma unroll
    for (int i = 0; i < 4; i++) {
        float x = t[tx][ty + i*8];
        bf16 h, l; split2(x, h, l);
        size_t o = (size_t)(c0 + ty + i*8) * R + r0 + tx;
        dh[o] = h; dl[o] = l;
    }
}

// ======================= swizzles ==========================================
__device__ __forceinline__ uint32_t swz(int row, int chunk) {       // 64B rows
    return (uint32_t)(row * 64 + ((chunk ^ ((row >> 1) & 3)) * 16));
}
__device__ __forceinline__ uint32_t swz256(int row, int chunk) {    // 256B rows
    return (uint32_t)(row * 256 + ((chunk ^ (row & 7)) * 16));
}
__device__ __forceinline__ uint32_t swz128(int row, int chunk) {    // 128B rows
    return (uint32_t)(row * 128 + ((chunk ^ (row & 7)) * 16));
}

// ======================= GEMM template (proj / biasv / outproj) ============
#define GT 256
#define KC 32
#define TILE_BYTES 8192
#define ABUF_BYTES 16384
#define FP_BYTES 16384
#define SMEM_GEMM_STD 65536
#define SMEM_GEMM_FP  81920

__device__ __forceinline__ void load_tile_async(uint32_t sbase,
                                                const bf16* __restrict__ src,
                                                size_t row0, size_t ld) {
    int t = threadIdx.x;
#pragma unroll
    for (int i = 0; i < 2; i++) {
        int id = t + i * 256;
        int row = id >> 2, c = id & 3;
        CP_ASYNC16(sbase + swz(row, c), src + (row0 + row) * ld + c * 8);
    }
}
__device__ __forceinline__ void load_vtile_async(uint32_t sbase,
                                                 const bf16* __restrict__ src,
                                                 size_t row0) {
    int t = threadIdx.x;
#pragma unroll
    for (int i = 0; i < 2; i++) {
        int id = t + i * 256;
        int row = id >> 4, c = id & 15;
        CP_ASYNC16(sbase + swz256(row, c), src + (row0 + row) * ATT + c * 8);
    }
}
__device__ __forceinline__ void load_fp_async(uint32_t sbase,
                                              const float* __restrict__ src,
                                              size_t row0, size_t ld) {
    int t = threadIdx.x;
#pragma unroll
    for (int i = 0; i < 4; i++) {
        int id = t + i * 256;
        int row = id >> 3, c = id & 7;
        CP_ASYNC16(sbase + swz128(row, c), src + (row0 + row) * ld + c * 4);
    }
}

// STAGE 0: proj (z: 0=q,1=k,2=v)  A = fp32 input (split in-kernel), B wT, K=1024
// STAGE 2: biasv                  A = fp32 attn_bias (split in-kernel), B vh (trans), K=2048 -> g_x_bias fp32
// STAGE 3: out proj               A x (chunked across views), B woT, K=1024
template <int STAGE>
__global__ __launch_bounds__(GT, 1)
void gemm_kernel(const float* __restrict__ i0, const float* __restrict__ i1,
                 const float* __restrict__ i2, const float* __restrict__ b0,
                 const float* __restrict__ b1, const float* __restrict__ b2,
                 float* __restrict__ pout) {
    extern __shared__ char smem[];
    const uint32_t sb = smem_u32(smem);
    const int tid = threadIdx.x, wid = tid >> 5, lane = tid & 31;
    const int wm = wid & 1, wn = wid >> 1;

    const bf16 *Bh0 = nullptr, *Bl0 = nullptr;
    const float* Xf = nullptr;
    size_t ldA = 0, ldB = 0, rowA0 = 0, rowB0 = 0;
    int K_TOTAL = 0;
    if constexpr (STAGE == 0) {
        int z = blockIdx.z;
        Xf  = z == 0 ? i0 : z == 1 ? i1 : i2;
        Bh0 = z == 0 ? g_wqT_h : z == 1 ? g_wkT_h : g_wvT_h;
        Bl0 = z == 0 ? g_wqT_l : z == 1 ? g_wkT_l : g_wvT_l;
        ldA = HID; ldB = HID; rowA0 = (size_t)blockIdx.x * 128; K_TOTAL = HID;
    } else if constexpr (STAGE == 2) {
        size_t z = blockIdx.z;
        Xf  = i0 + z * (size_t)SEQ * SEQ;          // attn_bias
        Bh0 = g_vh_h + z * (size_t)SEQ * ATT;
        Bl0 = g_vh_l + z * (size_t)SEQ * ATT;
        ldA = SEQ;
        rowA0 = (size_t)blockIdx.x * 128; K_TOTAL = SEQ;
    } else {
        Bh0 = g_woT_h; Bl0 = g_woT_l;
        ldA = ATT; ldB = HID;
        rowA0 = (size_t)blockIdx.x * 128; rowB0 = (size_t)blockIdx.y * 128; K_TOTAL = HID;
    }
    const int nc = K_TOTAL / KC;
    const bool FPA = (STAGE == 0 || STAGE == 2);

    const uint32_t B_OFF = FPA ? 49152u : 32768u;
    const uint32_t AH_OFF = 32768u, AL_OFF = 40960u;

    auto load_chunk = [&](int c, int buf) {
        const int kb = c * KC;
        if constexpr (STAGE == 0 || STAGE == 2) {
            load_fp_async(sb + buf * FP_BYTES, Xf + kb, rowA0, ldA);
        } else {
            size_t voff = (size_t)(kb >> 7) * (SEQ * ATT) + (kb & 127);
            load_tile_async(sb + buf * ABUF_BYTES,        g_x_h + voff, rowA0, ldA);
            load_tile_async(sb + buf * ABUF_BYTES + 8192, g_x_l + voff, rowA0, ldA);
        }
        if constexpr (STAGE == 2) {
            load_vtile_async(sb + B_OFF + buf * ABUF_BYTES,        Bh0, (size_t)kb);
            load_vtile_async(sb + B_OFF + buf * ABUF_BYTES + 8192, Bl0, (size_t)kb);
        } else {
            load_tile_async(sb + B_OFF + buf * ABUF_BYTES,        Bh0 + kb, rowB0, ldB);
            load_tile_async(sb + B_OFF + buf * ABUF_BYTES + 8192, Bl0 + kb, rowB0, ldB);
        }
    };

    float acc[4][4][4];
#pragma unroll
    for (int a = 0; a < 4; a++)
#pragma unroll
        for (int b = 0; b < 4; b++)
#pragma unroll
            for (int r2 = 0; r2 < 4; r2++) acc[a][b][r2] = 0.f;

    const int j8 = lane >> 3, r8 = lane & 7;
    const int aRowB = wm * 64 + (j8 & 1) * 8 + r8;
    const int aChB  = (j8 >> 1);
    const int bRowB = wn * 32 + (j8 >> 1) * 8 + r8;
    const int bChB  = (j8 & 1);
    const int vRowB = (j8 & 1) * 8 + r8;
    const int vChB  = wn * 4 + (j8 >> 1);

    load_chunk(0, 0);
    CP_COMMIT();

    for (int c = 0; c < nc; c++) {
        if (c + 1 < nc) {
            load_chunk(c + 1, (c + 1) & 1);
            CP_COMMIT();
            CP_WAIT1();
        } else {
            CP_WAIT0();
        }
        __syncthreads();

        if (FPA) {
            const char* fpb = smem + (c & 1) * FP_BYTES;
            const int row = tid >> 1, q = tid & 1;
            float4 f[4];
#pragma unroll
            for (int i = 0; i < 4; i++)
                f[i] = *reinterpret_cast<const float4*>(fpb + swz128(row, q * 4 + i));
#pragma unroll
            for (int j = 0; j < 2; j++) {
                uint4 hh, ll;
                split_pack(f[2*j].x,   f[2*j].y,   hh.x, ll.x);
                split_pack(f[2*j].z,   f[2*j].w,   hh.y, ll.y);
                split_pack(f[2*j+1].x, f[2*j+1].y, hh.z, ll.z);
                split_pack(f[2*j+1].z, f[2*j+1].w, hh.w, ll.w);
                *reinterpret_cast<uint4*>(smem + AH_OFF + swz(row, q * 2 + j)) = hh;
                *reinterpret_cast<uint4*>(smem + AL_OFF + swz(row, q * 2 + j)) = ll;
            }
            __syncthreads();
        }

        const uint32_t aB  = FPA ? sb + AH_OFF : sb + (c & 1) * ABUF_BYTES;
        const uint32_t alB = FPA ? sb + AL_OFF : sb + (c & 1) * ABUF_BYTES + 8192;
        const uint32_t bB  = sb + B_OFF + (c & 1) * ABUF_BYTES;
        const uint32_t blB = bB + 8192;
#pragma unroll
        for (int s = 0; s < 2; s++) {
            const int c0 = 2 * s;
            uint32_t ah[4][4], al[4][4], bh[2][4], bl[2][4];
#pragma unroll
            for (int mt = 0; mt < 4; mt++) {
                LDSM4(ah[mt], aB  + swz(aRowB + mt * 16, aChB + c0));
                LDSM4(al[mt], alB + swz(aRowB + mt * 16, aChB + c0));
            }
#pragma unroll
            for (int g = 0; g < 2; g++) {
                if constexpr (STAGE == 2) {
                    LDSM4T(bh[g], bB  + swz256(s * 16 + vRowB, vChB + g * 2));
                    LDSM4T(bl[g], blB + swz256(s * 16 + vRowB, vChB + g * 2));
                } else {
                    LDSM4(bh[g], bB  + swz(bRowB + g * 16, bChB + c0));
                    LDSM4(bl[g], blB + swz(bRowB + g * 16, bChB + c0));
                }
            }
#pragma unroll
            for (int mt = 0; mt < 4; mt++)
#pragma unroll
                for (int nt = 0; nt < 4; nt++) {
                    const int g = nt >> 1, p = (nt & 1) * 2;
                    MMA16816(acc[mt][nt], ah[mt], bh[g][p], bh[g][p + 1]);
                    MMA16816(acc[mt][nt], ah[mt], bl[g][p], bl[g][p + 1]);
                    MMA16816(acc[mt][nt], al[mt], bh[g][p], bh[g][p + 1]);
                }
        }
        __syncthreads();
    }

    const int gid = lane >> 2, tig = lane & 3;
#pragma unroll
    for (int mt = 0; mt < 4; mt++) {
#pragma unroll
        for (int h = 0; h < 2; h++) {
            const int m = (int)(blockIdx.x * 128) + wm * 64 + mt * 16 + gid + h * 8;
#pragma unroll
            for (int nt = 0; nt < 4; nt++) {
                const int n = wn * 32 + nt * 8 + tig * 2;
                float v0 = acc[mt][nt][h * 2];
                float v1 = acc[mt][nt][h * 2 + 1];
                if constexpr (STAGE == 0) {
                    int z = blockIdx.z;
                    const float* bias = z == 0 ? b0 : z == 1 ? b1 : b2;
                    float scl = (z == 0) ? SCALE : 1.f;
                    v0 = (v0 + bias[n]) * scl; v1 = (v1 + bias[n + 1]) * scl;
                    bf16 h0, l0, h1, l1; split2(v0, h0, l0); split2(v1, h1, l1);
                    bf162 hh; hh.x = h0; hh.y = h1;
                    bf162 ll; ll.x = l0; ll.y = l1;
                    bf16* dh = z == 0 ? g_qh_h : z == 1 ? g_kh_h : g_vh_h;
                    bf16* dl = z == 0 ? g_qh_l : z == 1 ? g_kh_l : g_vh_l;
                    size_t o = (size_t)m * ATT + n;
                    *reinterpret_cast<bf162*>(dh + o) = hh;
                    *reinterpret_cast<bf162*>(dl + o) = ll;
                } else if constexpr (STAGE == 2) {
                    size_t z = blockIdx.z;
                    float2 w; w.x = v0; w.y = v1;
                    *reinterpret_cast<float2*>(g_x_bias + (z * SEQ + m) * (size_t)ATT + n) = w;
                } else {
                    const int ng = (int)(blockIdx.y * 128) + n;
                    float2 w; w.x = v0 + b0[ng]; w.y = v1 + b0[ng + 1];
                    *reinterpret_cast<float2*>(pout + (size_t)m * HID + ng) = w;
                }
            }
        }
    }
}

// ======================= flash attention (no-max, deferred normalize) ======
// grid (16, 1, 8): one 128-q block per CTA. U = sum_k exp(S)@V; x = U/rowsum + x_bias.
#define FL_QH 0u
#define FL_QL 32768u
#define FL_KB 65536u
#define FL_VB 131072u
#define FL_PH 196608u
#define FL_PL 212992u
#define FL_RS 229376u
#define FL_SMEM 231424

__global__ __launch_bounds__(256, 1) void flash_kernel() {
    extern __shared__ char smem[];
    const uint32_t sb = smem_u32(smem);
    const int tid = threadIdx.x, wid = tid >> 5, lane = tid & 31;
    const int wm = wid & 1, wn = wid >> 1;
    const size_t z = blockIdx.z;
    const size_t q0 = (size_t)blockIdx.x * 128;

    const bf16* Qh = g_qh_h + z * SEQ * ATT;
    const bf16* Ql = g_qh_l + z * SEQ * ATT;
    const bf16* Kh = g_kh_h + z * SEQ * ATT;
    const bf16* Kl = g_kh_l + z * SEQ * ATT;
    const bf16* Vh = g_vh_h + z * SEQ * ATT;
    const bf16* Vl = g_vh_l + z * SEQ * ATT;

    // load Q block (128 x 128 att, hi+lo), 256B rows
    {
        int t = tid;
#pragma unroll
        for (int i = 0; i < 8; i++) {
            int id = t + i * 256;
            int row = id >> 4, c = id & 15;
            CP_ASYNC16(sb + FL_QH + swz256(row, c), Qh + (q0 + row) * ATT + c * 8);
            CP_ASYNC16(sb + FL_QL + swz256(row, c), Ql + (q0 + row) * ATT + c * 8);
        }
    }
    auto loadKV = [&](int kt, int buf) {
        const size_t r0 = (size_t)kt * 64;
        const uint32_t kb = sb + FL_KB + buf * 32768u;
        const uint32_t vb = sb + FL_VB + buf * 32768u;
        int t = tid;
#pragma unroll
        for (int i = 0; i < 4; i++) {
            int id = t + i * 256;
            int row = id >> 4, c = id & 15;
            CP_ASYNC16(kb + swz256(row, c),          Kh + (r0 + row) * ATT + c * 8);
            CP_ASYNC16(kb + 16384 + swz256(row, c),  Kl + (r0 + row) * ATT + c * 8);
            CP_ASYNC16(vb + swz256(row, c),          Vh + (r0 + row) * ATT + c * 8);
            CP_ASYNC16(vb + 16384 + swz256(row, c),  Vl + (r0 + row) * ATT + c * 8);
        }
    };
    loadKV(0, 0);
    CP_COMMIT();

    float U[4][4][4];
#pragma unroll
    for (int a = 0; a < 4; a++)
#pragma unroll
        for (int b = 0; b < 4; b++)
#pragma unroll
            for (int r = 0; r < 4; r++) U[a][b][r] = 0.f;
    float rsum[4][2];
#pragma unroll
    for (int a = 0; a < 4; a++) { rsum[a][0] = 0.f; rsum[a][1] = 0.f; }

    const int j8 = lane >> 3, r8 = lane & 7;
    const int aRow = wm * 64 + (j8 & 1) * 8 + r8;   // + mt*16 (A frags: Q and P)
    const int aCh  = (j8 >> 1);
    const int kRow = wn * 16 + (j8 >> 1) * 8 + r8;  // K as B (n = key index, 16/warp)
    const int kCh  = (j8 & 1);
    const int vRow = (j8 & 1) * 8 + r8;             // + ks2*16 (V trans B)
    const int vCh  = wn * 4 + (j8 >> 1);
    const int gid = lane >> 2, tig = lane & 3;

    for (int kt = 0; kt < 32; kt++) {
        if (kt + 1 < 32) { loadKV(kt + 1, (kt + 1) & 1); CP_COMMIT(); CP_WAIT1(); }
        else             { CP_WAIT0(); }
        __syncthreads();

        const uint32_t kb  = sb + FL_KB + (kt & 1) * 32768u;
        const uint32_t kbl = kb + 16384;
        // ---- S = Q @ K^T  (warp tile 64q x 16s) ----
        float sacc[4][2][4];
#pragma unroll
        for (int a = 0; a < 4; a++)
#pragma unroll
            for (int b = 0; b < 2; b++)
#pragma unroll
                for (int r = 0; r < 4; r++) sacc[a][b][r] = 0.f;
#pragma unroll
        for (int ks = 0; ks < 8; ks++) {
            uint32_t qa[4][4], ql[4][4], kf[4], lf[4];
#pragma unroll
            for (int mt = 0; mt < 4; mt++) {
                LDSM4(qa[mt], sb + FL_QH + swz256(aRow + mt * 16, ks * 2 + aCh));
                LDSM4(ql[mt], sb + FL_QL + swz256(aRow + mt * 16, ks * 2 + aCh));
            }
            LDSM4(kf, kb  + swz256(kRow, ks * 2 + kCh));
            LDSM4(lf, kbl + swz256(kRow, ks * 2 + kCh));
#pragma unroll
            for (int mt = 0; mt < 4; mt++)
#pragma unroll
                for (int nt = 0; nt < 2; nt++) {
                    const int p = nt * 2;
                    MMA16816(sacc[mt][nt], qa[mt], kf[p], kf[p + 1]);
                    MMA16816(sacc[mt][nt], qa[mt], lf[p], lf[p + 1]);
                    MMA16816(sacc[mt][nt], ql[mt], kf[p], kf[p + 1]);
                }
        }
        // ---- P = exp(S), rowsum, store P to smem ----
#pragma unroll
        for (int mt = 0; mt < 4; mt++)
#pragma unroll
            for (int nt = 0; nt < 2; nt++) {
                float e0 = __expf(sacc[mt][nt][0]);
                float e1 = __expf(sacc[mt][nt][1]);
                float e2 = __expf(sacc[mt][nt][2]);
                float e3 = __expf(sacc[mt][nt][3]);
                rsum[mt][0] += e0 + e1;
                rsum[mt][1] += e2 + e3;
                uint32_t h01, l01, h23, l23;
                split_pack(e0, e1, h01, l01);
                split_pack(e2, e3, h23, l23);
                const int rlo = wm * 64 + mt * 16 + gid;
                const int chunk = wn * 2 + nt;
                uint32_t oflo = (uint32_t)(rlo * 128 + ((chunk ^ (rlo & 7)) * 16) + tig * 4);
                const int rhi = rlo + 8;
                uint32_t ofhi = (uint32_t)(rhi * 128 + ((chunk ^ (rhi & 7)) * 16) + tig * 4);
                *reinterpret_cast<uint32_t*>(smem + FL_PH + oflo) = h01;
                *reinterpret_cast<uint32_t*>(smem + FL_PL + oflo) = l01;
                *reinterpret_cast<uint32_t*>(smem + FL_PH + ofhi) = h23;
                *reinterpret_cast<uint32_t*>(smem + FL_PL + ofhi) = l23;
            }
        __syncthreads();
        // ---- U += P @ V  (warp tile 64q x 32a) ----
        const uint32_t vb  = sb + FL_VB + (kt & 1) * 32768u;
        const uint32_t vbl = vb + 16384;
#pragma unroll
        for (int ks2 = 0; ks2 < 4; ks2++) {
            uint32_t pa[4][4], pl[4][4], vh_[2][4], vl_[2][4];
#pragma unroll
            for (int mt = 0; mt < 4; mt++) {
                LDSM4(pa[mt], sb + FL_PH + swz128(aRow + mt * 16, ks2 * 2 + aCh));
                LDSM4(pl[mt], sb + FL_PL + swz128(aRow + mt * 16, ks2 * 2 + aCh));
            }
#pragma unroll
            for (int g = 0; g < 2; g++) {
                LDSM4T(vh_[g], vb  + swz256(ks2 * 16 + vRow, vCh + g * 2));
                LDSM4T(vl_[g], vbl + swz256(ks2 * 16 + vRow, vCh + g * 2));
            }
#pragma unroll
            for (int mt = 0; mt < 4; mt++)
#pragma unroll
                for (int nt = 0; nt < 4; nt++) {
                    const int g = nt >> 1, p = (nt & 1) * 2;
                    MMA16816(U[mt][nt], pa[mt], vh_[g][p], vh_[g][p + 1]);
                    MMA16816(U[mt][nt], pa[mt], vl_[g][p], vl_[g][p + 1]);
                    MMA16816(U[mt][nt], pl[mt], vh_[g][p], vh_[g][p + 1]);
                }
        }
        __syncthreads();
    }

    // ---- rowsum reduce: tig lanes, then 4 N-warps via smem ----
    float* rs = reinterpret_cast<float*>(smem + FL_RS);   // [128][4]
#pragma unroll
    for (int mt = 0; mt < 4; mt++)
#pragma unroll
        for (int h = 0; h < 2; h++) {
            float s = rsum[mt][h];
            s += __shfl_xor_sync(0xffffffffu, s, 1);
            s += __shfl_xor_sync(0xffffffffu, s, 2);
            rsum[mt][h] = s;
        }
    if (tig == 0) {
#pragma unroll
        for (int mt = 0; mt < 4; mt++)
#pragma unroll
            for (int h = 0; h < 2; h++) {
                int row = wm * 64 + mt * 16 + gid + h * 8;
                rs[row * 4 + wn] = rsum[mt][h];
            }
    }
    __syncthreads();

    // ---- epilogue: x = U / rowsum + x_bias -> split h/l ----
#pragma unroll
    for (int mt = 0; mt < 4; mt++) {
#pragma unroll
        for (int h = 0; h < 2; h++) {
            const int rowL = wm * 64 + mt * 16 + gid + h * 8;
            const float tot = rs[rowL * 4 + 0] + rs[rowL * 4 + 1]
                            + rs[rowL * 4 + 2] + rs[rowL * 4 + 3];
            const float inv = 1.f / tot;
            const size_t m = q0 + rowL;
#pragma unroll
            for (int nt = 0; nt < 4; nt++) {
                const int n = wn * 32 + nt * 8 + tig * 2;
                const size_t o = (z * SEQ + m) * (size_t)ATT + n;
                float2 xb = *reinterpret_cast<const float2*>(g_x_bias + o);
                float v0 = U[mt][nt][h * 2]     * inv + xb.x;
                float v1 = U[mt][nt][h * 2 + 1] * inv + xb.y;
                bf16 h0, l0, h1, l1; split2(v0, h0, l0); split2(v1, h1, l1);
                bf162 hh; hh.x = h0; hh.y = h1;
                bf162 ll; ll.x = l0; ll.y = l1;
                *reinterpret_cast<bf162*>(g_x_h + o) = hh;
                *reinterpret_cast<bf162*>(g_x_l + o) = ll;
            }
        }
    }
}

// ======================= launch ============================================
extern "C" void kernel_launch(void* const* d_in, const int* in_sizes, int n_in,
                              void* d_out, int out_size) {
    const float* q         = (const float*)d_in[0];
    const float* k         = (const float*)d_in[1];
    const float* v         = (const float*)d_in[2];
    const float* attn_bias = (const float*)d_in[3];
    const float* wq        = (const float*)d_in[4];
    const float* bq        = (const float*)d_in[5];
    const float* wk        = (const float*)d_in[6];
    const float* bk        = (const float*)d_in[7];
    const float* wv        = (const float*)d_in[8];
    const float* bv        = (const float*)d_in[9];
    const float* wo        = (const float*)d_in[10];
    const float* bo        = (const float*)d_in[11];
    float* out = (float*)d_out;

    cudaFuncSetAttribute(gemm_kernel<0>, cudaFuncAttributeMaxDynamicSharedMemorySize, SMEM_GEMM_FP);
    cudaFuncSetAttribute(gemm_kernel<2>, cudaFuncAttributeMaxDynamicSharedMemorySize, SMEM_GEMM_FP);
    cudaFuncSetAttribute(gemm_kernel<3>, cudaFuncAttributeMaxDynamicSharedMemorySize, SMEM_GEMM_STD);
    cudaFuncSetAttribute(flash_kernel,   cudaFuncAttributeMaxDynamicSharedMemorySize, FL_SMEM);

    // 1) weights -> wT hi/lo
    transpose_split_w_kernel<<<dim3(ATT / 32, HID / 32), dim3(32, 8)>>>(wq, 0);
    transpose_split_w_kernel<<<dim3(ATT / 32, HID / 32), dim3(32, 8)>>>(wk, 1);
    transpose_split_w_kernel<<<dim3(ATT / 32, HID / 32), dim3(32, 8)>>>(wv, 2);
    transpose_split_w_kernel<<<dim3(HID / 32, HID / 32), dim3(32, 8)>>>(wo, 3);
    // 2) projections -> qh/kh/vh hi/lo
    gemm_kernel<0><<<dim3(VIEW * SEQ / 128, 1, 3), GT, SMEM_GEMM_FP>>>(
        q, k, v, bq, bk, bv, nullptr);
    // 3) bias @ vh -> g_x_bias (fp32)
    gemm_kernel<2><<<dim3(SEQ / 128, 1, VIEW), GT, SMEM_GEMM_FP>>>(
        attn_bias, nullptr, nullptr, nullptr, nullptr, nullptr, nullptr);
    // 4) flash: softmax(QK^T) @ V + x_bias -> x hi/lo
    flash_kernel<<<dim3(SEQ / 128, 1, VIEW), 256, FL_SMEM>>>();
    // 5) output projection
    gemm_kernel<3><<<dim3(SEQ / 128, HID / 128, 1), GT, SMEM_GEMM_STD>>>(
        nullptr, nullptr, nullptr, bo, nullptr, nullptr, out);
}

// round 7
// speedup vs baseline: 3.2124x; 1.0554x over previous
#include <cuda_runtime.h>
#include <cuda_bf16.h>
#include <cstdint>
#include <math.h>

#define VIEW 8
#define SEQ  2048
#define HID  1024
#define ATT  128
#define SCALE 0.08838834764831845f   // ATT^-0.5

using bf16 = __nv_bfloat16;
using bf162 = __nv_bfloat162;

// ======================= device scratch (no allocs allowed) =================
__device__ __align__(256) bf16 g_wqT_h[ATT*HID], g_wqT_l[ATT*HID];      // [n=128][k=1024]
__device__ __align__(256) bf16 g_wkT_h[ATT*HID], g_wkT_l[ATT*HID];
__device__ __align__(256) bf16 g_wvT_h[ATT*HID], g_wvT_l[ATT*HID];
__device__ __align__(256) bf16 g_woT_h[HID*HID], g_woT_l[HID*HID];      // [h=1024][c=1024]
__device__ __align__(256) bf16 g_qh_h[VIEW*SEQ*ATT], g_qh_l[VIEW*SEQ*ATT];
__device__ __align__(256) bf16 g_kh_h[VIEW*SEQ*ATT], g_kh_l[VIEW*SEQ*ATT];
__device__ __align__(256) bf16 g_vh_h[VIEW*SEQ*ATT], g_vh_l[VIEW*SEQ*ATT]; // [v][s][a]
__device__ __align__(256) float g_x_bias[VIEW*SEQ*ATT];                  // bias @ vh (fp32)
__device__ __align__(256) bf16 g_x_h[VIEW*SEQ*ATT], g_x_l[VIEW*SEQ*ATT];

// ======================= helpers ===========================================
__device__ __forceinline__ uint32_t smem_u32(const void* p) {
    uint32_t a;
    asm("{ .reg .u64 t; cvta.to.shared.u64 t, %1; cvt.u32.u64 %0, t; }" : "=r"(a) : "l"(p));
    return a;
}
__device__ __forceinline__ void split2(float x, bf16& h, bf16& l) {
    h = __float2bfloat16(x);
    l = __float2bfloat16(x - __bfloat162float(h));
}
__device__ __forceinline__ void split_pack(float a, float b, uint32_t& uh, uint32_t& ul) {
    bf16 ha, la, hb, lb; split2(a, ha, la); split2(b, hb, lb);
    bf162 H; H.x = ha; H.y = hb; uh = *reinterpret_cast<uint32_t*>(&H);
    bf162 L; L.x = la; L.y = lb; ul = *reinterpret_cast<uint32_t*>(&L);
}

#define CP_ASYNC16(saddr, gptr) \
    asm volatile("cp.async.cg.shared.global [%0], [%1], 16;" \
                 :: "r"(saddr), "l"(__cvta_generic_to_global(gptr)) : "memory")
#define CP_COMMIT() asm volatile("cp.async.commit_group;" ::: "memory")
#define CP_WAIT0()  asm volatile("cp.async.wait_group 0;" ::: "memory")
#define CP_WAIT1()  asm volatile("cp.async.wait_group 1;" ::: "memory")

#define LDSM4(R, addr) \
    asm volatile("ldmatrix.sync.aligned.m8n8.x4.shared.b16 {%0,%1,%2,%3}, [%4];" \
                 : "=r"((R)[0]), "=r"((R)[1]), "=r"((R)[2]), "=r"((R)[3]) : "r"(addr))
#define LDSM4T(R, addr) \
    asm volatile("ldmatrix.sync.aligned.m8n8.x4.trans.shared.b16 {%0,%1,%2,%3}, [%4];" \
                 : "=r"((R)[0]), "=r"((R)[1]), "=r"((R)[2]), "=r"((R)[3]) : "r"(addr))

#define MMA16816(C, A, b0, b1) \
    asm volatile("mma.sync.aligned.m16n8k16.row.col.f32.bf16.bf16.f32 " \
                 "{%0,%1,%2,%3},{%4,%5,%6,%7},{%8,%9},{%0,%1,%2,%3};" \
                 : "+f"((C)[0]), "+f"((C)[1]), "+f"((C)[2]), "+f"((C)[3]) \
                 : "r"((A)[0]), "r"((A)[1]), "r"((A)[2]), "r"((A)[3]), "r"(b0), "r"(b1))

// ======================= fused weight transpose+split (ONE launch) =========
// grid (32, 32, 4); z = which weight; z<3 uses only blockIdx.x<4 (C=128)
__global__ void transpose_split_w_all(const float* __restrict__ wq,
                                      const float* __restrict__ wk,
                                      const float* __restrict__ wv,
                                      const float* __restrict__ wo) {
    const int mode = blockIdx.z;
    const float* in;
    bf16 *dh, *dl; int C;
    if (mode == 0)      { in = wq; dh = g_wqT_h; dl = g_wqT_l; C = ATT; }
    else if (mode == 1) { in = wk; dh = g_wkT_h; dl = g_wkT_l; C = ATT; }
    else if (mode == 2) { in = wv; dh = g_wvT_h; dl = g_wvT_l; C = ATT; }
    else                { in = wo; dh = g_woT_h; dl = g_woT_l; C = HID; }
    if ((int)blockIdx.x * 32 >= C) return;
    __shared__ float t[32][33];
    const int R = HID;
    int c0 = blockIdx.x * 32, r0 = blockIdx.y * 32;
    int tx = threadIdx.x, ty = threadIdx.y;
#pragma unroll
    for (int i = 0; i < 4; i++)
        t[ty + i*8][tx] = in[(size_t)(r0 + ty + i*8) * C + c0 + tx];
    __syncthreads();
#pragma unroll
    for (int i = 0; i < 4; i++) {
        float x = t[tx][ty + i*8];
        bf16 h, l; split2(x, h, l);
        size_t o = (size_t)(c0 + ty + i*8) * R + r0 + tx;
        dh[o] = h; dl[o] = l;
    }
}

// ======================= swizzles ==========================================
__device__ __forceinline__ uint32_t swz(int row, int chunk) {       // 64B rows
    return (uint32_t)(row * 64 + ((chunk ^ ((row >> 1) & 3)) * 16));
}
__device__ __forceinline__ uint32_t swz256(int row, int chunk) {    // 256B rows
    return (uint32_t)(row * 256 + ((chunk ^ (row & 7)) * 16));
}
__device__ __forceinline__ uint32_t swz128(int row, int chunk) {    // 128B rows
    return (uint32_t)(row * 128 + ((chunk ^ (row & 7)) * 16));
}

// ======================= GEMM template (proj / biasv / outproj) ============
#define GT 256
#define KC 32
#define TILE_BYTES 8192
#define ABUF_BYTES 16384
#define FP_BYTES 16384
#define SMEM_GEMM_STD 65536
#define SMEM_GEMM_FP  81920

__device__ __forceinline__ void load_tile_async(uint32_t sbase,
                                                const bf16* __restrict__ src,
                                                size_t row0, size_t ld) {
    int t = threadIdx.x;
#pragma unroll
    for (int i = 0; i < 2; i++) {
        int id = t + i * 256;
        int row = id >> 2, c = id & 3;
        CP_ASYNC16(sbase + swz(row, c), src + (row0 + row) * ld + c * 8);
    }
}
__device__ __forceinline__ void load_vtile_async(uint32_t sbase,
                                                 const bf16* __restrict__ src,
                                                 size_t row0) {
    int t = threadIdx.x;
#pragma unroll
    for (int i = 0; i < 2; i++) {
        int id = t + i * 256;
        int row = id >> 4, c = id & 15;
        CP_ASYNC16(sbase + swz256(row, c), src + (row0 + row) * ATT + c * 8);
    }
}
__device__ __forceinline__ void load_fp_async(uint32_t sbase,
                                              const float* __restrict__ src,
                                              size_t row0, size_t ld) {
    int t = threadIdx.x;
#pragma unroll
    for (int i = 0; i < 4; i++) {
        int id = t + i * 256;
        int row = id >> 3, c = id & 7;
        CP_ASYNC16(sbase + swz128(row, c), src + (row0 + row) * ld + c * 4);
    }
}

// STAGE 0: proj (z: 0=q,1=k,2=v)  A = fp32 input (split in-kernel), B wT, K=1024
// STAGE 2: biasv                  A = fp32 attn_bias (split in-kernel), B vh (trans), K=2048 -> g_x_bias fp32
// STAGE 3: out proj               A x (chunked across views), B woT, K=1024
template <int STAGE>
__global__ __launch_bounds__(GT, 2)
void gemm_kernel(const float* __restrict__ i0, const float* __restrict__ i1,
                 const float* __restrict__ i2, const float* __restrict__ b0,
                 const float* __restrict__ b1, const float* __restrict__ b2,
                 float* __restrict__ pout) {
    extern __shared__ char smem[];
    const uint32_t sb = smem_u32(smem);
    const int tid = threadIdx.x, wid = tid >> 5, lane = tid & 31;
    const int wm = wid & 1, wn = wid >> 1;

    const bf16 *Bh0 = nullptr, *Bl0 = nullptr;
    const float* Xf = nullptr;
    size_t ldA = 0, ldB = 0, rowA0 = 0, rowB0 = 0;
    int K_TOTAL = 0;
    if constexpr (STAGE == 0) {
        int z = blockIdx.z;
        Xf  = z == 0 ? i0 : z == 1 ? i1 : i2;
        Bh0 = z == 0 ? g_wqT_h : z == 1 ? g_wkT_h : g_wvT_h;
        Bl0 = z == 0 ? g_wqT_l : z == 1 ? g_wkT_l : g_wvT_l;
        ldA = HID; ldB = HID; rowA0 = (size_t)blockIdx.x * 128; K_TOTAL = HID;
    } else if constexpr (STAGE == 2) {
        size_t z = blockIdx.z;
        Xf  = i0 + z * (size_t)SEQ * SEQ;          // attn_bias
        Bh0 = g_vh_h + z * (size_t)SEQ * ATT;
        Bl0 = g_vh_l + z * (size_t)SEQ * ATT;
        ldA = SEQ;
        rowA0 = (size_t)blockIdx.x * 128; K_TOTAL = SEQ;
    } else {
        Bh0 = g_woT_h; Bl0 = g_woT_l;
        ldA = ATT; ldB = HID;
        rowA0 = (size_t)blockIdx.x * 128; rowB0 = (size_t)blockIdx.y * 128; K_TOTAL = HID;
    }
    const int nc = K_TOTAL / KC;
    const bool FPA = (STAGE == 0 || STAGE == 2);

    const uint32_t B_OFF = FPA ? 49152u : 32768u;
    const uint32_t AH_OFF = 32768u, AL_OFF = 40960u;

    auto load_chunk = [&](int c, int buf) {
        const int kb = c * KC;
        if constexpr (STAGE == 0 || STAGE == 2) {
            load_fp_async(sb + buf * FP_BYTES, Xf + kb, rowA0, ldA);
        } else {
            size_t voff = (size_t)(kb >> 7) * (SEQ * ATT) + (kb & 127);
            load_tile_async(sb + buf * ABUF_BYTES,        g_x_h + voff, rowA0, ldA);
            load_tile_async(sb + buf * ABUF_BYTES + 8192, g_x_l + voff, rowA0, ldA);
        }
        if constexpr (STAGE == 2) {
            load_vtile_async(sb + B_OFF + buf * ABUF_BYTES,        Bh0, (size_t)kb);
            load_vtile_async(sb + B_OFF + buf * ABUF_BYTES + 8192, Bl0, (size_t)kb);
        } else {
            load_tile_async(sb + B_OFF + buf * ABUF_BYTES,        Bh0 + kb, rowB0, ldB);
            load_tile_async(sb + B_OFF + buf * ABUF_BYTES + 8192, Bl0 + kb, rowB0, ldB);
        }
    };

    float acc[4][4][4];
#pragma unroll
    for (int a = 0; a < 4; a++)
#pragma unroll
        for (int b = 0; b < 4; b++)
#pragma unroll
            for (int r2 = 0; r2 < 4; r2++) acc[a][b][r2] = 0.f;

    const int j8 = lane >> 3, r8 = lane & 7;
    const int aRowB = wm * 64 + (j8 & 1) * 8 + r8;
    const int aChB  = (j8 >> 1);
    const int bRowB = wn * 32 + (j8 >> 1) * 8 + r8;
    const int bChB  = (j8 & 1);
    const int vRowB = (j8 & 1) * 8 + r8;
    const int vChB  = wn * 4 + (j8 >> 1);

    load_chunk(0, 0);
    CP_COMMIT();

    for (int c = 0; c < nc; c++) {
        if (c + 1 < nc) {
            load_chunk(c + 1, (c + 1) & 1);
            CP_COMMIT();
            CP_WAIT1();
        } else {
            CP_WAIT0();
        }
        __syncthreads();

        if (FPA) {
            const char* fpb = smem + (c & 1) * FP_BYTES;
            const int row = tid >> 1, q = tid & 1;
            float4 f[4];
#pragma unroll
            for (int i = 0; i < 4; i++)
                f[i] = *reinterpret_cast<const float4*>(fpb + swz128(row, q * 4 + i));
#pragma unroll
            for (int j = 0; j < 2; j++) {
                uint4 hh, ll;
                split_pack(f[2*j].x,   f[2*j].y,   hh.x, ll.x);
                split_pack(f[2*j].z,   f[2*j].w,   hh.y, ll.y);
                split_pack(f[2*j+1].x, f[2*j+1].y, hh.z, ll.z);
                split_pack(f[2*j+1].z, f[2*j+1].w, hh.w, ll.w);
                *reinterpret_cast<uint4*>(smem + AH_OFF + swz(row, q * 2 + j)) = hh;
                *reinterpret_cast<uint4*>(smem + AL_OFF + swz(row, q * 2 + j)) = ll;
            }
            __syncthreads();
        }

        const uint32_t aB  = FPA ? sb + AH_OFF : sb + (c & 1) * ABUF_BYTES;
        const uint32_t alB = FPA ? sb + AL_OFF : sb + (c & 1) * ABUF_BYTES + 8192;
        const uint32_t bB  = sb + B_OFF + (c & 1) * ABUF_BYTES;
        const uint32_t blB = bB + 8192;
#pragma unroll
        for (int s = 0; s < 2; s++) {
            const int c0 = 2 * s;
            uint32_t ah[4][4], al[4][4], bh[2][4], bl[2][4];
#pragma unroll
            for (int mt = 0; mt < 4; mt++) {
                LDSM4(ah[mt], aB  + swz(aRowB + mt * 16, aChB + c0));
                LDSM4(al[mt], alB + swz(aRowB + mt * 16, aChB + c0));
            }
#pragma unroll
            for (int g = 0; g < 2; g++) {
                if constexpr (STAGE == 2) {
                    LDSM4T(bh[g], bB  + swz256(s * 16 + vRowB, vChB + g * 2));
                    LDSM4T(bl[g], blB + swz256(s * 16 + vRowB, vChB + g * 2));
                } else {
                    LDSM4(bh[g], bB  + swz(bRowB + g * 16, bChB + c0));
                    LDSM4(bl[g], blB + swz(bRowB + g * 16, bChB + c0));
                }
            }
#pragma unroll
            for (int mt = 0; mt < 4; mt++)
#pragma unroll
                for (int nt = 0; nt < 4; nt++) {
                    const int g = nt >> 1, p = (nt & 1) * 2;
                    MMA16816(acc[mt][nt], ah[mt], bh[g][p], bh[g][p + 1]);
                    MMA16816(acc[mt][nt], ah[mt], bl[g][p], bl[g][p + 1]);
                    MMA16816(acc[mt][nt], al[mt], bh[g][p], bh[g][p + 1]);
                }
        }
        __syncthreads();
    }

    const int gid = lane >> 2, tig = lane & 3;
#pragma unroll
    for (int mt = 0; mt < 4; mt++) {
#pragma unroll
        for (int h = 0; h < 2; h++) {
            const int m = (int)(blockIdx.x * 128) + wm * 64 + mt * 16 + gid + h * 8;
#pragma unroll
            for (int nt = 0; nt < 4; nt++) {
                const int n = wn * 32 + nt * 8 + tig * 2;
                float v0 = acc[mt][nt][h * 2];
                float v1 = acc[mt][nt][h * 2 + 1];
                if constexpr (STAGE == 0) {
                    int z = blockIdx.z;
                    const float* bias = z == 0 ? b0 : z == 1 ? b1 : b2;
                    float scl = (z == 0) ? SCALE : 1.f;
                    v0 = (v0 + bias[n]) * scl; v1 = (v1 + bias[n + 1]) * scl;
                    bf16 h0, l0, h1, l1; split2(v0, h0, l0); split2(v1, h1, l1);
                    bf162 hh; hh.x = h0; hh.y = h1;
                    bf162 ll; ll.x = l0; ll.y = l1;
                    bf16* dh = z == 0 ? g_qh_h : z == 1 ? g_kh_h : g_vh_h;
                    bf16* dl = z == 0 ? g_qh_l : z == 1 ? g_kh_l : g_vh_l;
                    size_t o = (size_t)m * ATT + n;
                    *reinterpret_cast<bf162*>(dh + o) = hh;
                    *reinterpret_cast<bf162*>(dl + o) = ll;
                } else if constexpr (STAGE == 2) {
                    size_t z = blockIdx.z;
                    float2 w; w.x = v0; w.y = v1;
                    *reinterpret_cast<float2*>(g_x_bias + (z * SEQ + m) * (size_t)ATT + n) = w;
                } else {
                    const int ng = (int)(blockIdx.y * 128) + n;
                    float2 w; w.x = v0 + b0[ng]; w.y = v1 + b0[ng + 1];
                    *reinterpret_cast<float2*>(pout + (size_t)m * HID + ng) = w;
                }
            }
        }
    }
}

// ======================= flash attention (no-max, deferred normalize) ======
#define FL_QH 0u
#define FL_QL 32768u
#define FL_KB 65536u
#define FL_VB 131072u
#define FL_PH 196608u
#define FL_PL 212992u
#define FL_RS 229376u
#define FL_SMEM 231424

__global__ __launch_bounds__(256, 1) void flash_kernel() {
    extern __shared__ char smem[];
    const uint32_t sb = smem_u32(smem);
    const int tid = threadIdx.x, wid = tid >> 5, lane = tid & 31;
    const int wm = wid & 1, wn = wid >> 1;
    const size_t z = blockIdx.z;
    const size_t q0 = (size_t)blockIdx.x * 128;

    const bf16* Qh = g_qh_h + z * SEQ * ATT;
    const bf16* Ql = g_qh_l + z * SEQ * ATT;
    const bf16* Kh = g_kh_h + z * SEQ * ATT;
    const bf16* Kl = g_kh_l + z * SEQ * ATT;
    const bf16* Vh = g_vh_h + z * SEQ * ATT;
    const bf16* Vl = g_vh_l + z * SEQ * ATT;

    {
        int t = tid;
#pragma unroll
        for (int i = 0; i < 8; i++) {
            int id = t + i * 256;
            int row = id >> 4, c = id & 15;
            CP_ASYNC16(sb + FL_QH + swz256(row, c), Qh + (q0 + row) * ATT + c * 8);
            CP_ASYNC16(sb + FL_QL + swz256(row, c), Ql + (q0 + row) * ATT + c * 8);
        }
    }
    auto loadKV = [&](int kt, int buf) {
        const size_t r0 = (size_t)kt * 64;
        const uint32_t kb = sb + FL_KB + buf * 32768u;
        const uint32_t vb = sb + FL_VB + buf * 32768u;
        int t = tid;
#pragma unroll
        for (int i = 0; i < 4; i++) {
            int id = t + i * 256;
            int row = id >> 4, c = id & 15;
            CP_ASYNC16(kb + swz256(row, c),          Kh + (r0 + row) * ATT + c * 8);
            CP_ASYNC16(kb + 16384 + swz256(row, c),  Kl + (r0 + row) * ATT + c * 8);
            CP_ASYNC16(vb + swz256(row, c),          Vh + (r0 + row) * ATT + c * 8);
            CP_ASYNC16(vb + 16384 + swz256(row, c),  Vl + (r0 + row) * ATT + c * 8);
        }
    };
    loadKV(0, 0);
    CP_COMMIT();

    float U[4][4][4];
#pragma unroll
    for (int a = 0; a < 4; a++)
#pragma unroll
        for (int b = 0; b < 4; b++)
#pragma unroll
            for (int r = 0; r < 4; r++) U[a][b][r] = 0.f;
    float rsum[4][2];
#pragma unroll
    for (int a = 0; a < 4; a++) { rsum[a][0] = 0.f; rsum[a][1] = 0.f; }

    const int j8 = lane >> 3, r8 = lane & 7;
    const int aRow = wm * 64 + (j8 & 1) * 8 + r8;
    const int aCh  = (j8 >> 1);
    const int kRow = wn * 16 + (j8 >> 1) * 8 + r8;
    const int kCh  = (j8 & 1);
    const int vRow = (j8 & 1) * 8 + r8;
    const int vCh  = wn * 4 + (j8 >> 1);
    const int gid = lane >> 2, tig = lane & 3;

    for (int kt = 0; kt < 32; kt++) {
        if (kt + 1 < 32) { loadKV(kt + 1, (kt + 1) & 1); CP_COMMIT(); CP_WAIT1(); }
        else             { CP_WAIT0(); }
        __syncthreads();

        const uint32_t kb  = sb + FL_KB + (kt & 1) * 32768u;
        const uint32_t kbl = kb + 16384;
        float sacc[4][2][4];
#pragma unroll
        for (int a = 0; a < 4; a++)
#pragma unroll
            for (int b = 0; b < 2; b++)
#pragma unroll
                for (int r = 0; r < 4; r++) sacc[a][b][r] = 0.f;
#pragma unroll
        for (int ks = 0; ks < 8; ks++) {
            uint32_t qa[4][4], ql[4][4], kf[4], lf[4];
#pragma unroll
            for (int mt = 0; mt < 4; mt++) {
                LDSM4(qa[mt], sb + FL_QH + swz256(aRow + mt * 16, ks * 2 + aCh));
                LDSM4(ql[mt], sb + FL_QL + swz256(aRow + mt * 16, ks * 2 + aCh));
            }
            LDSM4(kf, kb  + swz256(kRow, ks * 2 + kCh));
            LDSM4(lf, kbl + swz256(kRow, ks * 2 + kCh));
#pragma unroll
            for (int mt = 0; mt < 4; mt++)
#pragma unroll
                for (int nt = 0; nt < 2; nt++) {
                    const int p = nt * 2;
                    MMA16816(sacc[mt][nt], qa[mt], kf[p], kf[p + 1]);
                    MMA16816(sacc[mt][nt], qa[mt], lf[p], lf[p + 1]);
                    MMA16816(sacc[mt][nt], ql[mt], kf[p], kf[p + 1]);
                }
        }
#pragma unroll
        for (int mt = 0; mt < 4; mt++)
#pragma unroll
            for (int nt = 0; nt < 2; nt++) {
                float e0 = __expf(sacc[mt][nt][0]);
                float e1 = __expf(sacc[mt][nt][1]);
                float e2 = __expf(sacc[mt][nt][2]);
                float e3 = __expf(sacc[mt][nt][3]);
                rsum[mt][0] += e0 + e1;
                rsum[mt][1] += e2 + e3;
                uint32_t h01, l01, h23, l23;
                split_pack(e0, e1, h01, l01);
                split_pack(e2, e3, h23, l23);
                const int rlo = wm * 64 + mt * 16 + gid;
                const int chunk = wn * 2 + nt;
                uint32_t oflo = (uint32_t)(rlo * 128 + ((chunk ^ (rlo & 7)) * 16) + tig * 4);
                const int rhi = rlo + 8;
                uint32_t ofhi = (uint32_t)(rhi * 128 + ((chunk ^ (rhi & 7)) * 16) + tig * 4);
                *reinterpret_cast<uint32_t*>(smem + FL_PH + oflo) = h01;
                *reinterpret_cast<uint32_t*>(smem + FL_PL + oflo) = l01;
                *reinterpret_cast<uint32_t*>(smem + FL_PH + ofhi) = h23;
                *reinterpret_cast<uint32_t*>(smem + FL_PL + ofhi) = l23;
            }
        __syncthreads();
        const uint32_t vb  = sb + FL_VB + (kt & 1) * 32768u;
        const uint32_t vbl = vb + 16384;
#pragma unroll
        for (int ks2 = 0; ks2 < 4; ks2++) {
            uint32_t pa[4][4], pl[4][4], vh_[2][4], vl_[2][4];
#pragma unroll
            for (int mt = 0; mt < 4; mt++) {
                LDSM4(pa[mt], sb + FL_PH + swz128(aRow + mt * 16, ks2 * 2 + aCh));
                LDSM4(pl[mt], sb + FL_PL + swz128(aRow + mt * 16, ks2 * 2 + aCh));
            }
#pragma unroll
            for (int g = 0; g < 2; g++) {
                LDSM4T(vh_[g], vb  + swz256(ks2 * 16 + vRow, vCh + g * 2));
                LDSM4T(vl_[g], vbl + swz256(ks2 * 16 + vRow, vCh + g * 2));
            }
#pragma unroll
            for (int mt = 0; mt < 4; mt++)
#pragma unroll
                for (int nt = 0; nt < 4; nt++) {
                    const int g = nt >> 1, p = (nt & 1) * 2;
                    MMA16816(U[mt][nt], pa[mt], vh_[g][p], vh_[g][p + 1]);
                    MMA16816(U[mt][nt], pa[mt], vl_[g][p], vl_[g][p + 1]);
                    MMA16816(U[mt][nt], pl[mt], vh_[g][p], vh_[g][p + 1]);
                }
        }
        __syncthreads();
    }

    float* rs = reinterpret_cast<float*>(smem + FL_RS);   // [128][4]
#pragma unroll
    for (int mt = 0; mt < 4; mt++)
#pragma unroll
        for (int h = 0; h < 2; h++) {
            float s = rsum[mt][h];
            s += __shfl_xor_sync(0xffffffffu, s, 1);
            s += __shfl_xor_sync(0xffffffffu, s, 2);
            rsum[mt][h] = s;
        }
    if (tig == 0) {
#pragma unroll
        for (int mt = 0; mt < 4; mt++)
#pragma unroll
            for (int h = 0; h < 2; h++) {
                int row = wm * 64 + mt * 16 + gid + h * 8;
                rs[row * 4 + wn] = rsum[mt][h];
            }
    }
    __syncthreads();

#pragma unroll
    for (int mt = 0; mt < 4; mt++) {
#pragma unroll
        for (int h = 0; h < 2; h++) {
            const int rowL = wm * 64 + mt * 16 + gid + h * 8;
            const float tot = rs[rowL * 4 + 0] + rs[rowL * 4 + 1]
                            + rs[rowL * 4 + 2] + rs[rowL * 4 + 3];
            const float inv = 1.f / tot;
            const size_t m = q0 + rowL;
#pragma unroll
            for (int nt = 0; nt < 4; nt++) {
                const int n = wn * 32 + nt * 8 + tig * 2;
                const size_t o = (z * SEQ + m) * (size_t)ATT + n;
                float2 xb = *reinterpret_cast<const float2*>(g_x_bias + o);
                float v0 = U[mt][nt][h * 2]     * inv + xb.x;
                float v1 = U[mt][nt][h * 2 + 1] * inv + xb.y;
                bf16 h0, l0, h1, l1; split2(v0, h0, l0); split2(v1, h1, l1);
                bf162 hh; hh.x = h0; hh.y = h1;
                bf162 ll; ll.x = l0; ll.y = l1;
                *reinterpret_cast<bf162*>(g_x_h + o) = hh;
                *reinterpret_cast<bf162*>(g_x_l + o) = ll;
            }
        }
    }
}

// ======================= launch ============================================
extern "C" void kernel_launch(void* const* d_in, const int* in_sizes, int n_in,
                              void* d_out, int out_size) {
    const float* q         = (const float*)d_in[0];
    const float* k         = (const float*)d_in[1];
    const float* v         = (const float*)d_in[2];
    const float* attn_bias = (const float*)d_in[3];
    const float* wq        = (const float*)d_in[4];
    const float* bq        = (const float*)d_in[5];
    const float* wk        = (const float*)d_in[6];
    const float* bk        = (const float*)d_in[7];
    const float* wv        = (const float*)d_in[8];
    const float* bv        = (const float*)d_in[9];
    const float* wo        = (const float*)d_in[10];
    const float* bo        = (const float*)d_in[11];
    float* out = (float*)d_out;

    cudaFuncSetAttribute(gemm_kernel<0>, cudaFuncAttributeMaxDynamicSharedMemorySize, SMEM_GEMM_FP);
    cudaFuncSetAttribute(gemm_kernel<2>, cudaFuncAttributeMaxDynamicSharedMemorySize, SMEM_GEMM_FP);
    cudaFuncSetAttribute(gemm_kernel<3>, cudaFuncAttributeMaxDynamicSharedMemorySize, SMEM_GEMM_STD);
    cudaFuncSetAttribute(flash_kernel,   cudaFuncAttributeMaxDynamicSharedMemorySize, FL_SMEM);

    // 1) weights -> wT hi/lo (single launch)
    transpose_split_w_all<<<dim3(32, 32, 4), dim3(32, 8)>>>(wq, wk, wv, wo);
    // 2) projections -> qh/kh/vh hi/lo
    gemm_kernel<0><<<dim3(VIEW * SEQ / 128, 1, 3), GT, SMEM_GEMM_FP>>>(
        q, k, v, bq, bk, bv, nullptr);
    // 3) bias @ vh -> g_x_bias (fp32)
    gemm_kernel<2><<<dim3(SEQ / 128, 1, VIEW), GT, SMEM_GEMM_FP>>>(
        attn_bias, nullptr, nullptr, nullptr, nullptr, nullptr, nullptr);
    // 4) flash: softmax(QK^T) @ V + x_bias -> x hi/lo
    flash_kernel<<<dim3(SEQ / 128, 1, VIEW), 256, FL_SMEM>>>();
    // 5) output projection
    gemm_kernel<3><<<dim3(SEQ / 128, HID / 128, 1), GT, SMEM_GEMM_STD>>>(
        nullptr, nullptr, nullptr, bo, nullptr, nullptr, out);
}

// round 8
// speedup vs baseline: 3.3206x; 1.0337x over previous
#include <cuda_runtime.h>
#include <cuda_bf16.h>
#include <cstdint>
#include <math.h>

#define VIEW 8
#define SEQ  2048
#define HID  1024
#define ATT  128
#define SCALE 0.08838834764831845f   // ATT^-0.5

using bf16 = __nv_bfloat16;
using bf162 = __nv_bfloat162;

// ======================= device scratch (no allocs allowed) =================
__device__ __align__(256) bf16 g_wqT_h[ATT*HID], g_wqT_l[ATT*HID];
__device__ __align__(256) bf16 g_wkT_h[ATT*HID], g_wkT_l[ATT*HID];
__device__ __align__(256) bf16 g_wvT_h[ATT*HID], g_wvT_l[ATT*HID];
__device__ __align__(256) bf16 g_woT_h[HID*HID], g_woT_l[HID*HID];
__device__ __align__(256) bf16 g_qh_h[VIEW*SEQ*ATT], g_qh_l[VIEW*SEQ*ATT];
__device__ __align__(256) bf16 g_kh_h[VIEW*SEQ*ATT], g_kh_l[VIEW*SEQ*ATT];
__device__ __align__(256) bf16 g_vh_h[VIEW*SEQ*ATT], g_vh_l[VIEW*SEQ*ATT];
__device__ __align__(256) float g_x_bias[VIEW*SEQ*ATT];
__device__ __align__(256) bf16 g_x_h[VIEW*SEQ*ATT], g_x_l[VIEW*SEQ*ATT];

// ======================= helpers ===========================================
__device__ __forceinline__ uint32_t smem_u32(const void* p) {
    uint32_t a;
    asm("{ .reg .u64 t; cvta.to.shared.u64 t, %1; cvt.u32.u64 %0, t; }" : "=r"(a) : "l"(p));
    return a;
}
__device__ __forceinline__ void split2(float x, bf16& h, bf16& l) {
    h = __float2bfloat16(x);
    l = __float2bfloat16(x - __bfloat162float(h));
}
__device__ __forceinline__ void split_pack(float a, float b, uint32_t& uh, uint32_t& ul) {
    bf16 ha, la, hb, lb; split2(a, ha, la); split2(b, hb, lb);
    bf162 H; H.x = ha; H.y = hb; uh = *reinterpret_cast<uint32_t*>(&H);
    bf162 L; L.x = la; L.y = lb; ul = *reinterpret_cast<uint32_t*>(&L);
}

#define CP_ASYNC16(saddr, gptr) \
    asm volatile("cp.async.cg.shared.global [%0], [%1], 16;" \
                 :: "r"(saddr), "l"(__cvta_generic_to_global(gptr)) : "memory")
#define CP_COMMIT() asm volatile("cp.async.commit_group;" ::: "memory")
#define CP_WAIT0()  asm volatile("cp.async.wait_group 0;" ::: "memory")
#define CP_WAIT1()  asm volatile("cp.async.wait_group 1;" ::: "memory")

#define LDSM4(R, addr) \
    asm volatile("ldmatrix.sync.aligned.m8n8.x4.shared.b16 {%0,%1,%2,%3}, [%4];" \
                 : "=r"((R)[0]), "=r"((R)[1]), "=r"((R)[2]), "=r"((R)[3]) : "r"(addr))
#define LDSM4T(R, addr) \
    asm volatile("ldmatrix.sync.aligned.m8n8.x4.trans.shared.b16 {%0,%1,%2,%3}, [%4];" \
                 : "=r"((R)[0]), "=r"((R)[1]), "=r"((R)[2]), "=r"((R)[3]) : "r"(addr))

#define MMA16816(C, A, b0, b1) \
    asm volatile("mma.sync.aligned.m16n8k16.row.col.f32.bf16.bf16.f32 " \
                 "{%0,%1,%2,%3},{%4,%5,%6,%7},{%8,%9},{%0,%1,%2,%3};" \
                 : "+f"((C)[0]), "+f"((C)[1]), "+f"((C)[2]), "+f"((C)[3]) \
                 : "r"((A)[0]), "r"((A)[1]), "r"((A)[2]), "r"((A)[3]), "r"(b0), "r"(b1))

// ======================= fused weight transpose+split ======================
__global__ void transpose_split_w_all(const float* __restrict__ wq,
                                      const float* __restrict__ wk,
                                      const float* __restrict__ wv,
                                      const float* __restrict__ wo) {
    const int mode = blockIdx.z;
    const float* in;
    bf16 *dh, *dl; int C;
    if (mode == 0)      { in = wq; dh = g_wqT_h; dl = g_wqT_l; C = ATT; }
    else if (mode == 1) { in = wk; dh = g_wkT_h; dl = g_wkT_l; C = ATT; }
    else if (mode == 2) { in = wv; dh = g_wvT_h; dl = g_wvT_l; C = ATT; }
    else                { in = wo; dh = g_woT_h; dl = g_woT_l; C = HID; }
    if ((int)blockIdx.x * 32 >= C) return;
    __shared__ float t[32][33];
    const int R = HID;
    int c0 = blockIdx.x * 32, r0 = blockIdx.y * 32;
    int tx = threadIdx.x, ty = threadIdx.y;
#pragma unroll
    for (int i = 0; i < 4; i++)
        t[ty + i*8][tx] = in[(size_t)(r0 + ty + i*8) * C + c0 + tx];
    __syncthreads();
#pragma unroll
    for (int i = 0; i < 4; i++) {
        float x = t[tx][ty + i*8];
        bf16 h, l; split2(x, h, l);
        size_t o = (size_t)(c0 + ty + i*8) * R + r0 + tx;
        dh[o] = h; dl[o] = l;
    }
}

// ======================= swizzles ==========================================
__device__ __forceinline__ uint32_t swz(int row, int chunk) {       // 64B rows
    return (uint32_t)(row * 64 + ((chunk ^ ((row >> 1) & 3)) * 16));
}
__device__ __forceinline__ uint32_t swz256(int row, int chunk) {    // 256B rows
    return (uint32_t)(row * 256 + ((chunk ^ (row & 7)) * 16));
}
__device__ __forceinline__ uint32_t swz128(int row, int chunk) {    // 128B rows
    return (uint32_t)(row * 128 + ((chunk ^ (row & 7)) * 16));
}

// ======================= GEMM template =====================================
#define GT 256
#define KC 32

template <int ROWS>
__device__ __forceinline__ void load_tile_async(uint32_t sbase,
                                                const bf16* __restrict__ src,
                                                size_t row0, size_t ld) {
    int t = threadIdx.x;
#pragma unroll
    for (int i = 0; i < ROWS / 64; i++) {
        int id = t + i * 256;
        int row = id >> 2, c = id & 3;
        CP_ASYNC16(sbase + swz(row, c), src + (row0 + row) * ld + c * 8);
    }
}
__device__ __forceinline__ void load_vtile_async(uint32_t sbase,
                                                 const bf16* __restrict__ src,
                                                 size_t row0) {
    int t = threadIdx.x;
#pragma unroll
    for (int i = 0; i < 2; i++) {
        int id = t + i * 256;
        int row = id >> 4, c = id & 15;
        CP_ASYNC16(sbase + swz256(row, c), src + (row0 + row) * ATT + c * 8);
    }
}
template <int ROWS>
__device__ __forceinline__ void load_fp_async(uint32_t sbase,
                                              const float* __restrict__ src,
                                              size_t row0, size_t ld) {
    int t = threadIdx.x;
#pragma unroll
    for (int i = 0; i < ROWS / 32; i++) {
        int id = t + i * 256;
        int row = id >> 3, c = id & 7;
        CP_ASYNC16(sbase + swz128(row, c), src + (row0 + row) * ld + c * 4);
    }
}

// STAGE 0: proj (MT=128)  A = fp32 input, B wT, K=1024
// STAGE 2: biasv (MT=64)  A = fp32 attn_bias, B vh (trans), K=2048 -> g_x_bias
// STAGE 3: outproj (MT=64) A x, B woT, K=1024
template <int STAGE>
__global__ __launch_bounds__(GT, 2)
void gemm_kernel(const float* __restrict__ i0, const float* __restrict__ i1,
                 const float* __restrict__ i2, const float* __restrict__ b0,
                 const float* __restrict__ b1, const float* __restrict__ b2,
                 float* __restrict__ pout) {
    constexpr int MT  = (STAGE == 0) ? 128 : 64;
    constexpr int MTI = MT / 32;                  // A-frags per warp (m dir)
    constexpr bool FPA = (STAGE == 0 || STAGE == 2);
    constexpr uint32_t A_T  = MT * 64;            // one bf16 A tile bytes
    constexpr uint32_t FPB  = MT * 128;           // fp32 staging tile bytes
    constexpr uint32_t AH_OFF = FPA ? 2 * FPB : 0;            // (FPA layout)
    constexpr uint32_t AL_OFF = AH_OFF + A_T;
    constexpr uint32_t B_OFF  = FPA ? (2 * FPB + 2 * A_T) : (4 * A_T);

    extern __shared__ char smem[];
    const uint32_t sb = smem_u32(smem);
    const int tid = threadIdx.x, wid = tid >> 5, lane = tid & 31;
    const int wm = wid & 1, wn = wid >> 1;

    const bf16 *Bh0 = nullptr, *Bl0 = nullptr;
    const float* Xf = nullptr;
    size_t ldA = 0, ldB = 0, rowA0 = 0, rowB0 = 0;
    int K_TOTAL = 0;
    if constexpr (STAGE == 0) {
        int z = blockIdx.z;
        Xf  = z == 0 ? i0 : z == 1 ? i1 : i2;
        Bh0 = z == 0 ? g_wqT_h : z == 1 ? g_wkT_h : g_wvT_h;
        Bl0 = z == 0 ? g_wqT_l : z == 1 ? g_wkT_l : g_wvT_l;
        ldA = HID; ldB = HID; rowA0 = (size_t)blockIdx.x * MT; K_TOTAL = HID;
    } else if constexpr (STAGE == 2) {
        size_t z = blockIdx.z;
        Xf  = i0 + z * (size_t)SEQ * SEQ;
        Bh0 = g_vh_h + z * (size_t)SEQ * ATT;
        Bl0 = g_vh_l + z * (size_t)SEQ * ATT;
        ldA = SEQ;
        rowA0 = (size_t)blockIdx.x * MT; K_TOTAL = SEQ;
    } else {
        Bh0 = g_woT_h; Bl0 = g_woT_l;
        ldA = ATT; ldB = HID;
        rowA0 = (size_t)blockIdx.x * MT; rowB0 = (size_t)blockIdx.y * 128; K_TOTAL = HID;
    }
    const int nc = K_TOTAL / KC;

    auto load_chunk = [&](int c, int buf) {
        const int kb = c * KC;
        if constexpr (FPA) {
            load_fp_async<MT>(sb + buf * FPB, Xf + kb, rowA0, ldA);
        } else {
            size_t voff = (size_t)(kb >> 7) * (SEQ * ATT) + (kb & 127);
            load_tile_async<MT>(sb + buf * (2 * A_T),       g_x_h + voff, rowA0, ldA);
            load_tile_async<MT>(sb + buf * (2 * A_T) + A_T, g_x_l + voff, rowA0, ldA);
        }
        if constexpr (STAGE == 2) {
            load_vtile_async(sb + B_OFF + buf * 16384u,        Bh0, (size_t)kb);
            load_vtile_async(sb + B_OFF + buf * 16384u + 8192, Bl0, (size_t)kb);
        } else {
            load_tile_async<128>(sb + B_OFF + buf * 16384u,        Bh0 + kb, rowB0, ldB);
            load_tile_async<128>(sb + B_OFF + buf * 16384u + 8192, Bl0 + kb, rowB0, ldB);
        }
    };

    float acc[MTI][4][4];
#pragma unroll
    for (int a = 0; a < MTI; a++)
#pragma unroll
        for (int b = 0; b < 4; b++)
#pragma unroll
            for (int r2 = 0; r2 < 4; r2++) acc[a][b][r2] = 0.f;

    const int j8 = lane >> 3, r8 = lane & 7;
    const int aRowB = wm * (MT / 2) + (j8 & 1) * 8 + r8;
    const int aChB  = (j8 >> 1);
    const int bRowB = wn * 32 + (j8 >> 1) * 8 + r8;
    const int bChB  = (j8 & 1);
    const int vRowB = (j8 & 1) * 8 + r8;
    const int vChB  = wn * 4 + (j8 >> 1);

    load_chunk(0, 0);
    CP_COMMIT();

    for (int c = 0; c < nc; c++) {
        if (c + 1 < nc) {
            load_chunk(c + 1, (c + 1) & 1);
            CP_COMMIT();
            CP_WAIT1();
        } else {
            CP_WAIT0();
        }
        __syncthreads();

        if constexpr (FPA) {
            const char* fpb = smem + (c & 1) * FPB;
            if constexpr (MT == 128) {
                const int row = tid >> 1, q = tid & 1;
                float4 f[4];
#pragma unroll
                for (int i = 0; i < 4; i++)
                    f[i] = *reinterpret_cast<const float4*>(fpb + swz128(row, q * 4 + i));
#pragma unroll
                for (int j = 0; j < 2; j++) {
                    uint4 hh, ll;
                    split_pack(f[2*j].x,   f[2*j].y,   hh.x, ll.x);
                    split_pack(f[2*j].z,   f[2*j].w,   hh.y, ll.y);
                    split_pack(f[2*j+1].x, f[2*j+1].y, hh.z, ll.z);
                    split_pack(f[2*j+1].z, f[2*j+1].w, hh.w, ll.w);
                    *reinterpret_cast<uint4*>(smem + AH_OFF + swz(row, q * 2 + j)) = hh;
                    *reinterpret_cast<uint4*>(smem + AL_OFF + swz(row, q * 2 + j)) = ll;
                }
            } else {
                const int row = tid >> 2, q = tid & 3;
                float4 f0 = *reinterpret_cast<const float4*>(fpb + swz128(row, q * 2));
                float4 f1 = *reinterpret_cast<const float4*>(fpb + swz128(row, q * 2 + 1));
                uint4 hh, ll;
                split_pack(f0.x, f0.y, hh.x, ll.x);
                split_pack(f0.z, f0.w, hh.y, ll.y);
                split_pack(f1.x, f1.y, hh.z, ll.z);
                split_pack(f1.z, f1.w, hh.w, ll.w);
                *reinterpret_cast<uint4*>(smem + AH_OFF + swz(row, q)) = hh;
                *reinterpret_cast<uint4*>(smem + AL_OFF + swz(row, q)) = ll;
            }
            __syncthreads();
        }

        const uint32_t aB  = FPA ? sb + AH_OFF : sb + (c & 1) * (2 * A_T);
        const uint32_t alB = FPA ? sb + AL_OFF : sb + (c & 1) * (2 * A_T) + A_T;
        const uint32_t bB  = sb + B_OFF + (c & 1) * 16384u;
        const uint32_t blB = bB + 8192;
#pragma unroll
        for (int s = 0; s < 2; s++) {
            const int c0 = 2 * s;
            uint32_t ah[MTI][4], al[MTI][4], bh[2][4], bl[2][4];
#pragma unroll
            for (int mt = 0; mt < MTI; mt++) {
                LDSM4(ah[mt], aB  + swz(aRowB + mt * 16, aChB + c0));
                LDSM4(al[mt], alB + swz(aRowB + mt * 16, aChB + c0));
            }
#pragma unroll
            for (int g = 0; g < 2; g++) {
                if constexpr (STAGE == 2) {
                    LDSM4T(bh[g], bB  + swz256(s * 16 + vRowB, vChB + g * 2));
                    LDSM4T(bl[g], blB + swz256(s * 16 + vRowB, vChB + g * 2));
                } else {
                    LDSM4(bh[g], bB  + swz(bRowB + g * 16, bChB + c0));
                    LDSM4(bl[g], blB + swz(bRowB + g * 16, bChB + c0));
                }
            }
#pragma unroll
            for (int mt = 0; mt < MTI; mt++)
#pragma unroll
                for (int nt = 0; nt < 4; nt++) {
                    const int g = nt >> 1, p = (nt & 1) * 2;
                    MMA16816(acc[mt][nt], ah[mt], bh[g][p], bh[g][p + 1]);
                    MMA16816(acc[mt][nt], ah[mt], bl[g][p], bl[g][p + 1]);
                    MMA16816(acc[mt][nt], al[mt], bh[g][p], bh[g][p + 1]);
                }
        }
        __syncthreads();
    }

    const int gid = lane >> 2, tig = lane & 3;
#pragma unroll
    for (int mt = 0; mt < MTI; mt++) {
#pragma unroll
        for (int h = 0; h < 2; h++) {
            const int m = (int)(blockIdx.x * MT) + wm * (MT / 2) + mt * 16 + gid + h * 8;
#pragma unroll
            for (int nt = 0; nt < 4; nt++) {
                const int n = wn * 32 + nt * 8 + tig * 2;
                float v0 = acc[mt][nt][h * 2];
                float v1 = acc[mt][nt][h * 2 + 1];
                if constexpr (STAGE == 0) {
                    int z = blockIdx.z;
                    const float* bias = z == 0 ? b0 : z == 1 ? b1 : b2;
                    float scl = (z == 0) ? SCALE : 1.f;
                    v0 = (v0 + bias[n]) * scl; v1 = (v1 + bias[n + 1]) * scl;
                    bf16 h0, l0, h1, l1; split2(v0, h0, l0); split2(v1, h1, l1);
                    bf162 hh; hh.x = h0; hh.y = h1;
                    bf162 ll; ll.x = l0; ll.y = l1;
                    bf16* dh = z == 0 ? g_qh_h : z == 1 ? g_kh_h : g_vh_h;
                    bf16* dl = z == 0 ? g_qh_l : z == 1 ? g_kh_l : g_vh_l;
                    size_t o = (size_t)m * ATT + n;
                    *reinterpret_cast<bf162*>(dh + o) = hh;
                    *reinterpret_cast<bf162*>(dl + o) = ll;
                } else if constexpr (STAGE == 2) {
                    size_t z = blockIdx.z;
                    float2 w; w.x = v0; w.y = v1;
                    *reinterpret_cast<float2*>(g_x_bias + (z * SEQ + m) * (size_t)ATT + n) = w;
                } else {
                    const int ng = (int)(blockIdx.y * 128) + n;
                    float2 w; w.x = v0 + b0[ng]; w.y = v1 + b0[ng + 1];
                    *reinterpret_cast<float2*>(pout + (size_t)m * HID + ng) = w;
                }
            }
        }
    }
}

// ======================= flash attention (512 threads, 16 warps) ===========
#define FL_QH 0u
#define FL_QL 32768u
#define FL_KB 65536u
#define FL_VB 131072u
#define FL_PH 196608u
#define FL_PL 212992u
#define FL_RS 229376u
#define FL_SMEM 231424

__global__ __launch_bounds__(512, 1) void flash_kernel() {
    extern __shared__ char smem[];
    const uint32_t sb = smem_u32(smem);
    const int tid = threadIdx.x, wid = tid >> 5, lane = tid & 31;
    const int wm = wid & 3, wn = wid >> 2;      // 4 (M) x 4 (N)
    const size_t z = blockIdx.z;
    const size_t q0 = (size_t)blockIdx.x * 128;

    const bf16* Qh = g_qh_h + z * SEQ * ATT;
    const bf16* Ql = g_qh_l + z * SEQ * ATT;
    const bf16* Kh = g_kh_h + z * SEQ * ATT;
    const bf16* Kl = g_kh_l + z * SEQ * ATT;
    const bf16* Vh = g_vh_h + z * SEQ * ATT;
    const bf16* Vl = g_vh_l + z * SEQ * ATT;

    {
        int t = tid;
#pragma unroll
        for (int i = 0; i < 4; i++) {
            int id = t + i * 512;
            int row = id >> 4, c = id & 15;
            CP_ASYNC16(sb + FL_QH + swz256(row, c), Qh + (q0 + row) * ATT + c * 8);
            CP_ASYNC16(sb + FL_QL + swz256(row, c), Ql + (q0 + row) * ATT + c * 8);
        }
    }
    auto loadKV = [&](int kt, int buf) {
        const size_t r0 = (size_t)kt * 64;
        const uint32_t kb = sb + FL_KB + buf * 32768u;
        const uint32_t vb = sb + FL_VB + buf * 32768u;
        int t = tid;
#pragma unroll
        for (int i = 0; i < 2; i++) {
            int id = t + i * 512;
            int row = id >> 4, c = id & 15;
            CP_ASYNC16(kb + swz256(row, c),          Kh + (r0 + row) * ATT + c * 8);
            CP_ASYNC16(kb + 16384 + swz256(row, c),  Kl + (r0 + row) * ATT + c * 8);
            CP_ASYNC16(vb + swz256(row, c),          Vh + (r0 + row) * ATT + c * 8);
            CP_ASYNC16(vb + 16384 + swz256(row, c),  Vl + (r0 + row) * ATT + c * 8);
        }
    };
    loadKV(0, 0);
    CP_COMMIT();

    float U[2][4][4];
#pragma unroll
    for (int a = 0; a < 2; a++)
#pragma unroll
        for (int b = 0; b < 4; b++)
#pragma unroll
            for (int r = 0; r < 4; r++) U[a][b][r] = 0.f;
    float rsum[2][2];
#pragma unroll
    for (int a = 0; a < 2; a++) { rsum[a][0] = 0.f; rsum[a][1] = 0.f; }

    const int j8 = lane >> 3, r8 = lane & 7;
    const int aRow = wm * 32 + (j8 & 1) * 8 + r8;   // + mt*16
    const int aCh  = (j8 >> 1);
    const int kRow = wn * 16 + (j8 >> 1) * 8 + r8;
    const int kCh  = (j8 & 1);
    const int vRow = (j8 & 1) * 8 + r8;
    const int vCh  = wn * 4 + (j8 >> 1);
    const int gid = lane >> 2, tig = lane & 3;

    for (int kt = 0; kt < 32; kt++) {
        if (kt + 1 < 32) { loadKV(kt + 1, (kt + 1) & 1); CP_COMMIT(); CP_WAIT1(); }
        else             { CP_WAIT0(); }
        __syncthreads();

        const uint32_t kb  = sb + FL_KB + (kt & 1) * 32768u;
        const uint32_t kbl = kb + 16384;
        float sacc[2][2][4];
#pragma unroll
        for (int a = 0; a < 2; a++)
#pragma unroll
            for (int b = 0; b < 2; b++)
#pragma unroll
                for (int r = 0; r < 4; r++) sacc[a][b][r] = 0.f;
#pragma unroll
        for (int ks = 0; ks < 8; ks++) {
            uint32_t qa[2][4], ql[2][4], kf[4], lf[4];
#pragma unroll
            for (int mt = 0; mt < 2; mt++) {
                LDSM4(qa[mt], sb + FL_QH + swz256(aRow + mt * 16, ks * 2 + aCh));
                LDSM4(ql[mt], sb + FL_QL + swz256(aRow + mt * 16, ks * 2 + aCh));
            }
            LDSM4(kf, kb  + swz256(kRow, ks * 2 + kCh));
            LDSM4(lf, kbl + swz256(kRow, ks * 2 + kCh));
#pragma unroll
            for (int mt = 0; mt < 2; mt++)
#pragma unroll
                for (int nt = 0; nt < 2; nt++) {
                    const int p = nt * 2;
                    MMA16816(sacc[mt][nt], qa[mt], kf[p], kf[p + 1]);
                    MMA16816(sacc[mt][nt], qa[mt], lf[p], lf[p + 1]);
                    MMA16816(sacc[mt][nt], ql[mt], kf[p], kf[p + 1]);
                }
        }
#pragma unroll
        for (int mt = 0; mt < 2; mt++)
#pragma unroll
            for (int nt = 0; nt < 2; nt++) {
                float e0 = __expf(sacc[mt][nt][0]);
                float e1 = __expf(sacc[mt][nt][1]);
                float e2 = __expf(sacc[mt][nt][2]);
                float e3 = __expf(sacc[mt][nt][3]);
                rsum[mt][0] += e0 + e1;
                rsum[mt][1] += e2 + e3;
                uint32_t h01, l01, h23, l23;
                split_pack(e0, e1, h01, l01);
                split_pack(e2, e3, h23, l23);
                const int rlo = wm * 32 + mt * 16 + gid;
                const int chunk = wn * 2 + nt;
                uint32_t oflo = (uint32_t)(rlo * 128 + ((chunk ^ (rlo & 7)) * 16) + tig * 4);
                const int rhi = rlo + 8;
                uint32_t ofhi = (uint32_t)(rhi * 128 + ((chunk ^ (rhi & 7)) * 16) + tig * 4);
                *reinterpret_cast<uint32_t*>(smem + FL_PH + oflo) = h01;
                *reinterpret_cast<uint32_t*>(smem + FL_PL + oflo) = l01;
                *reinterpret_cast<uint32_t*>(smem + FL_PH + ofhi) = h23;
                *reinterpret_cast<uint32_t*>(smem + FL_PL + ofhi) = l23;
            }
        __syncthreads();
        const uint32_t vb  = sb + FL_VB + (kt & 1) * 32768u;
        const uint32_t vbl = vb + 16384;
#pragma unroll
        for (int ks2 = 0; ks2 < 4; ks2++) {
            uint32_t pa[2][4], pl[2][4], vh_[2][4], vl_[2][4];
#pragma unroll
            for (int mt = 0; mt < 2; mt++) {
                LDSM4(pa[mt], sb + FL_PH + swz128(aRow + mt * 16, ks2 * 2 + aCh));
                LDSM4(pl[mt], sb + FL_PL + swz128(aRow + mt * 16, ks2 * 2 + aCh));
            }
#pragma unroll
            for (int g = 0; g < 2; g++) {
                LDSM4T(vh_[g], vb  + swz256(ks2 * 16 + vRow, vCh + g * 2));
                LDSM4T(vl_[g], vbl + swz256(ks2 * 16 + vRow, vCh + g * 2));
            }
#pragma unroll
            for (int mt = 0; mt < 2; mt++)
#pragma unroll
                for (int nt = 0; nt < 4; nt++) {
                    const int g = nt >> 1, p = (nt & 1) * 2;
                    MMA16816(U[mt][nt], pa[mt], vh_[g][p], vh_[g][p + 1]);
                    MMA16816(U[mt][nt], pa[mt], vl_[g][p], vl_[g][p + 1]);
                    MMA16816(U[mt][nt], pl[mt], vh_[g][p], vh_[g][p + 1]);
                }
        }
        __syncthreads();
    }

    float* rs = reinterpret_cast<float*>(smem + FL_RS);   // [128][4]
#pragma unroll
    for (int mt = 0; mt < 2; mt++)
#pragma unroll
        for (int h = 0; h < 2; h++) {
            float s = rsum[mt][h];
            s += __shfl_xor_sync(0xffffffffu, s, 1);
            s += __shfl_xor_sync(0xffffffffu, s, 2);
            rsum[mt][h] = s;
        }
    if (tig == 0) {
#pragma unroll
        for (int mt = 0; mt < 2; mt++)
#pragma unroll
            for (int h = 0; h < 2; h++) {
                int row = wm * 32 + mt * 16 + gid + h * 8;
                rs[row * 4 + wn] = rsum[mt][h];
            }
    }
    __syncthreads();

#pragma unroll
    for (int mt = 0; mt < 2; mt++) {
#pragma unroll
        for (int h = 0; h < 2; h++) {
            const int rowL = wm * 32 + mt * 16 + gid + h * 8;
            const float tot = rs[rowL * 4 + 0] + rs[rowL * 4 + 1]
                            + rs[rowL * 4 + 2] + rs[rowL * 4 + 3];
            const float inv = 1.f / tot;
            const size_t m = q0 + rowL;
#pragma unroll
            for (int nt = 0; nt < 4; nt++) {
                const int n = wn * 32 + nt * 8 + tig * 2;
                const size_t o = (z * SEQ + m) * (size_t)ATT + n;
                float2 xb = *reinterpret_cast<const float2*>(g_x_bias + o);
                float v0 = U[mt][nt][h * 2]     * inv + xb.x;
                float v1 = U[mt][nt][h * 2 + 1] * inv + xb.y;
                bf16 h0, l0, h1, l1; split2(v0, h0, l0); split2(v1, h1, l1);
                bf162 hh; hh.x = h0; hh.y = h1;
                bf162 ll; ll.x = l0; ll.y = l1;
                *reinterpret_cast<bf162*>(g_x_h + o) = hh;
                *reinterpret_cast<bf162*>(g_x_l + o) = ll;
            }
        }
    }
}

// ======================= launch ============================================
extern "C" void kernel_launch(void* const* d_in, const int* in_sizes, int n_in,
                              void* d_out, int out_size) {
    const float* q         = (const float*)d_in[0];
    const float* k         = (const float*)d_in[1];
    const float* v         = (const float*)d_in[2];
    const float* attn_bias = (const float*)d_in[3];
    const float* wq        = (const float*)d_in[4];
    const float* bq        = (const float*)d_in[5];
    const float* wk        = (const float*)d_in[6];
    const float* bk        = (const float*)d_in[7];
    const float* wv        = (const float*)d_in[8];
    const float* bv        = (const float*)d_in[9];
    const float* wo        = (const float*)d_in[10];
    const float* bo        = (const float*)d_in[11];
    float* out = (float*)d_out;

    cudaFuncSetAttribute(gemm_kernel<0>, cudaFuncAttributeMaxDynamicSharedMemorySize, 81920);
    cudaFuncSetAttribute(gemm_kernel<2>, cudaFuncAttributeMaxDynamicSharedMemorySize, 57344);
    cudaFuncSetAttribute(gemm_kernel<3>, cudaFuncAttributeMaxDynamicSharedMemorySize, 49152);
    cudaFuncSetAttribute(flash_kernel,   cudaFuncAttributeMaxDynamicSharedMemorySize, FL_SMEM);

    // 1) weights -> wT hi/lo (single launch)
    transpose_split_w_all<<<dim3(32, 32, 4), dim3(32, 8)>>>(wq, wk, wv, wo);
    // 2) projections -> qh/kh/vh hi/lo  (MT=128, grid 384)
    gemm_kernel<0><<<dim3(VIEW * SEQ / 128, 1, 3), GT, 81920>>>(
        q, k, v, bq, bk, bv, nullptr);
    // 3) bias @ vh -> g_x_bias (MT=64, grid 256)
    gemm_kernel<2><<<dim3(SEQ / 64, 1, VIEW), GT, 57344>>>(
        attn_bias, nullptr, nullptr, nullptr, nullptr, nullptr, nullptr);
    // 4) flash (512 threads)
    flash_kernel<<<dim3(SEQ / 128, 1, VIEW), 512, FL_SMEM>>>();
    // 5) output projection (MT=64, grid 256)
    gemm_kernel<3><<<dim3(SEQ / 64, HID / 128), GT, 49152>>>(
        nullptr, nullptr, nullptr, bo, nullptr, nullptr, out);
}

// round 9
// speedup vs baseline: 3.3507x; 1.0091x over previous
#include <cuda_runtime.h>
#include <cuda_bf16.h>
#include <cstdint>
#include <math.h>

#define VIEW 8
#define SEQ  2048
#define HID  1024
#define ATT  128
#define SCALE 0.08838834764831845f   // ATT^-0.5

using bf16 = __nv_bfloat16;
using bf162 = __nv_bfloat162;

// ======================= device scratch (no allocs allowed) =================
__device__ __align__(256) bf16 g_wqT_h[ATT*HID], g_wqT_l[ATT*HID];
__device__ __align__(256) bf16 g_wkT_h[ATT*HID], g_wkT_l[ATT*HID];
__device__ __align__(256) bf16 g_wvT_h[ATT*HID], g_wvT_l[ATT*HID];
__device__ __align__(256) bf16 g_woT_h[HID*HID], g_woT_l[HID*HID];
__device__ __align__(256) bf16 g_qh_h[VIEW*SEQ*ATT], g_qh_l[VIEW*SEQ*ATT];
__device__ __align__(256) bf16 g_kh_h[VIEW*SEQ*ATT], g_kh_l[VIEW*SEQ*ATT];
__device__ __align__(256) bf16 g_vh_h[VIEW*SEQ*ATT], g_vh_l[VIEW*SEQ*ATT];
__device__ __align__(256) float g_x_bias[VIEW*SEQ*ATT];
__device__ __align__(256) bf16 g_x_h[VIEW*SEQ*ATT], g_x_l[VIEW*SEQ*ATT];

// ======================= helpers ===========================================
__device__ __forceinline__ uint32_t smem_u32(const void* p) {
    uint32_t a;
    asm("{ .reg .u64 t; cvta.to.shared.u64 t, %1; cvt.u32.u64 %0, t; }" : "=r"(a) : "l"(p));
    return a;
}
__device__ __forceinline__ void split2(float x, bf16& h, bf16& l) {
    h = __float2bfloat16(x);
    l = __float2bfloat16(x - __bfloat162float(h));
}
__device__ __forceinline__ void split_pack(float a, float b, uint32_t& uh, uint32_t& ul) {
    bf16 ha, la, hb, lb; split2(a, ha, la); split2(b, hb, lb);
    bf162 H; H.x = ha; H.y = hb; uh = *reinterpret_cast<uint32_t*>(&H);
    bf162 L; L.x = la; L.y = lb; ul = *reinterpret_cast<uint32_t*>(&L);
}

#define CP_ASYNC16(saddr, gptr) \
    asm volatile("cp.async.cg.shared.global [%0], [%1], 16;" \
                 :: "r"(saddr), "l"(__cvta_generic_to_global(gptr)) : "memory")
#define CP_COMMIT() asm volatile("cp.async.commit_group;" ::: "memory")
#define CP_WAIT0()  asm volatile("cp.async.wait_group 0;" ::: "memory")
#define CP_WAIT1()  asm volatile("cp.async.wait_group 1;" ::: "memory")

#define LDSM4(R, addr) \
    asm volatile("ldmatrix.sync.aligned.m8n8.x4.shared.b16 {%0,%1,%2,%3}, [%4];" \
                 : "=r"((R)[0]), "=r"((R)[1]), "=r"((R)[2]), "=r"((R)[3]) : "r"(addr))
#define LDSM4T(R, addr) \
    asm volatile("ldmatrix.sync.aligned.m8n8.x4.trans.shared.b16 {%0,%1,%2,%3}, [%4];" \
                 : "=r"((R)[0]), "=r"((R)[1]), "=r"((R)[2]), "=r"((R)[3]) : "r"(addr))

#define MMA16816(C, A, b0, b1) \
    asm volatile("mma.sync.aligned.m16n8k16.row.col.f32.bf16.bf16.f32 " \
                 "{%0,%1,%2,%3},{%4,%5,%6,%7},{%8,%9},{%0,%1,%2,%3};" \
                 : "+f"((C)[0]), "+f"((C)[1]), "+f"((C)[2]), "+f"((C)[3]) \
                 : "r"((A)[0]), "r"((A)[1]), "r"((A)[2]), "r"((A)[3]), "r"(b0), "r"(b1))

// ======================= fused weight transpose+split ======================
__global__ void transpose_split_w_all(const float* __restrict__ wq,
                                      const float* __restrict__ wk,
                                      const float* __restrict__ wv,
                                      const float* __restrict__ wo) {
    const int mode = blockIdx.z;
    const float* in;
    bf16 *dh, *dl; int C;
    if (mode == 0)      { in = wq; dh = g_wqT_h; dl = g_wqT_l; C = ATT; }
    else if (mode == 1) { in = wk; dh = g_wkT_h; dl = g_wkT_l; C = ATT; }
    else if (mode == 2) { in = wv; dh = g_wvT_h; dl = g_wvT_l; C = ATT; }
    else                { in = wo; dh = g_woT_h; dl = g_woT_l; C = HID; }
    if ((int)blockIdx.x * 32 >= C) return;
    __shared__ float t[32][33];
    const int R = HID;
    int c0 = blockIdx.x * 32, r0 = blockIdx.y * 32;
    int tx = threadIdx.x, ty = threadIdx.y;
#pragma unroll
    for (int i = 0; i < 4; i++)
        t[ty + i*8][tx] = in[(size_t)(r0 + ty + i*8) * C + c0 + tx];
    __syncthreads();
#pragma unroll
    for (int i = 0; i < 4; i++) {
        float x = t[tx][ty + i*8];
        bf16 h, l; split2(x, h, l);
        size_t o = (size_t)(c0 + ty + i*8) * R + r0 + tx;
        dh[o] = h; dl[o] = l;
    }
}

// ======================= swizzles ==========================================
__device__ __forceinline__ uint32_t swz(int row, int chunk) {       // 64B rows
    return (uint32_t)(row * 64 + ((chunk ^ ((row >> 1) & 3)) * 16));
}
__device__ __forceinline__ uint32_t swz256(int row, int chunk) {    // 256B rows
    return (uint32_t)(row * 256 + ((chunk ^ (row & 7)) * 16));
}
__device__ __forceinline__ uint32_t swz128(int row, int chunk) {    // 128B rows
    return (uint32_t)(row * 128 + ((chunk ^ (row & 7)) * 16));
}

// ======================= GEMM template =====================================
#define GT 256
#define KC 32

template <int ROWS>
__device__ __forceinline__ void load_tile_async(uint32_t sbase,
                                                const bf16* __restrict__ src,
                                                size_t row0, size_t ld) {
    int t = threadIdx.x;
#pragma unroll
    for (int i = 0; i < ROWS / 64; i++) {
        int id = t + i * 256;
        int row = id >> 2, c = id & 3;
        CP_ASYNC16(sbase + swz(row, c), src + (row0 + row) * ld + c * 8);
    }
}
__device__ __forceinline__ void load_vtile_async(uint32_t sbase,
                                                 const bf16* __restrict__ src,
                                                 size_t row0) {
    int t = threadIdx.x;
#pragma unroll
    for (int i = 0; i < 2; i++) {
        int id = t + i * 256;
        int row = id >> 4, c = id & 15;
        CP_ASYNC16(sbase + swz256(row, c), src + (row0 + row) * ATT + c * 8);
    }
}
template <int ROWS>
__device__ __forceinline__ void load_fp_async(uint32_t sbase,
                                              const float* __restrict__ src,
                                              size_t row0, size_t ld) {
    int t = threadIdx.x;
#pragma unroll
    for (int i = 0; i < ROWS / 32; i++) {
        int id = t + i * 256;
        int row = id >> 3, c = id & 7;
        CP_ASYNC16(sbase + swz128(row, c), src + (row0 + row) * ld + c * 4);
    }
}

// STAGE 0: proj (MT=128)  A = fp32 input, B wT, K=1024  (z = blockIdx.z + zbase)
// STAGE 2: biasv (MT=64)  A = fp32 attn_bias, B vh (trans), K=2048 -> g_x_bias
// STAGE 3: outproj (MT=64) A x, B woT, K=1024
template <int STAGE>
__global__ __launch_bounds__(GT, 2)
void gemm_kernel(const float* __restrict__ i0, const float* __restrict__ i1,
                 const float* __restrict__ i2, const float* __restrict__ b0,
                 const float* __restrict__ b1, const float* __restrict__ b2,
                 float* __restrict__ pout, int zbase) {
    constexpr int MT  = (STAGE == 0) ? 128 : 64;
    constexpr int MTI = MT / 32;
    constexpr bool FPA = (STAGE == 0 || STAGE == 2);
    constexpr uint32_t A_T  = MT * 64;
    constexpr uint32_t FPB  = MT * 128;
    constexpr uint32_t AH_OFF = FPA ? 2 * FPB : 0;
    constexpr uint32_t AL_OFF = AH_OFF + A_T;
    constexpr uint32_t B_OFF  = FPA ? (2 * FPB + 2 * A_T) : (4 * A_T);

    extern __shared__ char smem[];
    const uint32_t sb = smem_u32(smem);
    const int tid = threadIdx.x, wid = tid >> 5, lane = tid & 31;
    const int wm = wid & 1, wn = wid >> 1;

    const bf16 *Bh0 = nullptr, *Bl0 = nullptr;
    const float* Xf = nullptr;
    size_t ldA = 0, ldB = 0, rowA0 = 0, rowB0 = 0;
    int K_TOTAL = 0;
    if constexpr (STAGE == 0) {
        int z = blockIdx.z + zbase;
        Xf  = z == 0 ? i0 : z == 1 ? i1 : i2;
        Bh0 = z == 0 ? g_wqT_h : z == 1 ? g_wkT_h : g_wvT_h;
        Bl0 = z == 0 ? g_wqT_l : z == 1 ? g_wkT_l : g_wvT_l;
        ldA = HID; ldB = HID; rowA0 = (size_t)blockIdx.x * MT; K_TOTAL = HID;
    } else if constexpr (STAGE == 2) {
        size_t z = blockIdx.z;
        Xf  = i0 + z * (size_t)SEQ * SEQ;
        Bh0 = g_vh_h + z * (size_t)SEQ * ATT;
        Bl0 = g_vh_l + z * (size_t)SEQ * ATT;
        ldA = SEQ;
        rowA0 = (size_t)blockIdx.x * MT; K_TOTAL = SEQ;
    } else {
        Bh0 = g_woT_h; Bl0 = g_woT_l;
        ldA = ATT; ldB = HID;
        rowA0 = (size_t)blockIdx.x * MT; rowB0 = (size_t)blockIdx.y * 128; K_TOTAL = HID;
    }
    const int nc = K_TOTAL / KC;

    auto load_chunk = [&](int c, int buf) {
        const int kb = c * KC;
        if constexpr (FPA) {
            load_fp_async<MT>(sb + buf * FPB, Xf + kb, rowA0, ldA);
        } else {
            size_t voff = (size_t)(kb >> 7) * (SEQ * ATT) + (kb & 127);
            load_tile_async<MT>(sb + buf * (2 * A_T),       g_x_h + voff, rowA0, ldA);
            load_tile_async<MT>(sb + buf * (2 * A_T) + A_T, g_x_l + voff, rowA0, ldA);
        }
        if constexpr (STAGE == 2) {
            load_vtile_async(sb + B_OFF + buf * 16384u,        Bh0, (size_t)kb);
            load_vtile_async(sb + B_OFF + buf * 16384u + 8192, Bl0, (size_t)kb);
        } else {
            load_tile_async<128>(sb + B_OFF + buf * 16384u,        Bh0 + kb, rowB0, ldB);
            load_tile_async<128>(sb + B_OFF + buf * 16384u + 8192, Bl0 + kb, rowB0, ldB);
        }
    };

    float acc[MTI][4][4];
#pragma unroll
    for (int a = 0; a < MTI; a++)
#pragma unroll
        for (int b = 0; b < 4; b++)
#pragma unroll
            for (int r2 = 0; r2 < 4; r2++) acc[a][b][r2] = 0.f;

    const int j8 = lane >> 3, r8 = lane & 7;
    const int aRowB = wm * (MT / 2) + (j8 & 1) * 8 + r8;
    const int aChB  = (j8 >> 1);
    const int bRowB = wn * 32 + (j8 >> 1) * 8 + r8;
    const int bChB  = (j8 & 1);
    const int vRowB = (j8 & 1) * 8 + r8;
    const int vChB  = wn * 4 + (j8 >> 1);

    load_chunk(0, 0);
    CP_COMMIT();

    for (int c = 0; c < nc; c++) {
        if (c + 1 < nc) {
            load_chunk(c + 1, (c + 1) & 1);
            CP_COMMIT();
            CP_WAIT1();
        } else {
            CP_WAIT0();
        }
        __syncthreads();

        if constexpr (FPA) {
            const char* fpb = smem + (c & 1) * FPB;
            if constexpr (MT == 128) {
                const int row = tid >> 1, q = tid & 1;
                float4 f[4];
#pragma unroll
                for (int i = 0; i < 4; i++)
                    f[i] = *reinterpret_cast<const float4*>(fpb + swz128(row, q * 4 + i));
#pragma unroll
                for (int j = 0; j < 2; j++) {
                    uint4 hh, ll;
                    split_pack(f[2*j].x,   f[2*j].y,   hh.x, ll.x);
                    split_pack(f[2*j].z,   f[2*j].w,   hh.y, ll.y);
                    split_pack(f[2*j+1].x, f[2*j+1].y, hh.z, ll.z);
                    split_pack(f[2*j+1].z, f[2*j+1].w, hh.w, ll.w);
                    *reinterpret_cast<uint4*>(smem + AH_OFF + swz(row, q * 2 + j)) = hh;
                    *reinterpret_cast<uint4*>(smem + AL_OFF + swz(row, q * 2 + j)) = ll;
                }
            } else {
                const int row = tid >> 2, q = tid & 3;
                float4 f0 = *reinterpret_cast<const float4*>(fpb + swz128(row, q * 2));
                float4 f1 = *reinterpret_cast<const float4*>(fpb + swz128(row, q * 2 + 1));
                uint4 hh, ll;
                split_pack(f0.x, f0.y, hh.x, ll.x);
                split_pack(f0.z, f0.w, hh.y, ll.y);
                split_pack(f1.x, f1.y, hh.z, ll.z);
                split_pack(f1.z, f1.w, hh.w, ll.w);
                *reinterpret_cast<uint4*>(smem + AH_OFF + swz(row, q)) = hh;
                *reinterpret_cast<uint4*>(smem + AL_OFF + swz(row, q)) = ll;
            }
            __syncthreads();
        }

        const uint32_t aB  = FPA ? sb + AH_OFF : sb + (c & 1) * (2 * A_T);
        const uint32_t alB = FPA ? sb + AL_OFF : sb + (c & 1) * (2 * A_T) + A_T;
        const uint32_t bB  = sb + B_OFF + (c & 1) * 16384u;
        const uint32_t blB = bB + 8192;
#pragma unroll
        for (int s = 0; s < 2; s++) {
            const int c0 = 2 * s;
            uint32_t ah[MTI][4], al[MTI][4], bh[2][4], bl[2][4];
#pragma unroll
            for (int mt = 0; mt < MTI; mt++) {
                LDSM4(ah[mt], aB  + swz(aRowB + mt * 16, aChB + c0));
                LDSM4(al[mt], alB + swz(aRowB + mt * 16, aChB + c0));
            }
#pragma unroll
            for (int g = 0; g < 2; g++) {
                if constexpr (STAGE == 2) {
                    LDSM4T(bh[g], bB  + swz256(s * 16 + vRowB, vChB + g * 2));
                    LDSM4T(bl[g], blB + swz256(s * 16 + vRowB, vChB + g * 2));
                } else {
                    LDSM4(bh[g], bB  + swz(bRowB + g * 16, bChB + c0));
                    LDSM4(bl[g], blB + swz(bRowB + g * 16, bChB + c0));
                }
            }
#pragma unroll
            for (int mt = 0; mt < MTI; mt++)
#pragma unroll
                for (int nt = 0; nt < 4; nt++) {
                    const int g = nt >> 1, p = (nt & 1) * 2;
                    MMA16816(acc[mt][nt], ah[mt], bh[g][p], bh[g][p + 1]);
                    MMA16816(acc[mt][nt], ah[mt], bl[g][p], bl[g][p + 1]);
                    MMA16816(acc[mt][nt], al[mt], bh[g][p], bh[g][p + 1]);
                }
        }
        __syncthreads();
    }

    const int gid = lane >> 2, tig = lane & 3;
#pragma unroll
    for (int mt = 0; mt < MTI; mt++) {
#pragma unroll
        for (int h = 0; h < 2; h++) {
            const int m = (int)(blockIdx.x * MT) + wm * (MT / 2) + mt * 16 + gid + h * 8;
#pragma unroll
            for (int nt = 0; nt < 4; nt++) {
                const int n = wn * 32 + nt * 8 + tig * 2;
                float v0 = acc[mt][nt][h * 2];
                float v1 = acc[mt][nt][h * 2 + 1];
                if constexpr (STAGE == 0) {
                    int z = blockIdx.z + zbase;
                    const float* bias = z == 0 ? b0 : z == 1 ? b1 : b2;
                    float scl = (z == 0) ? SCALE : 1.f;
                    v0 = (v0 + bias[n]) * scl; v1 = (v1 + bias[n + 1]) * scl;
                    bf16 h0, l0, h1, l1; split2(v0, h0, l0); split2(v1, h1, l1);
                    bf162 hh; hh.x = h0; hh.y = h1;
                    bf162 ll; ll.x = l0; ll.y = l1;
                    bf16* dh = z == 0 ? g_qh_h : z == 1 ? g_kh_h : g_vh_h;
                    bf16* dl = z == 0 ? g_qh_l : z == 1 ? g_kh_l : g_vh_l;
                    size_t o = (size_t)m * ATT + n;
                    *reinterpret_cast<bf162*>(dh + o) = hh;
                    *reinterpret_cast<bf162*>(dl + o) = ll;
                } else if constexpr (STAGE == 2) {
                    size_t z = blockIdx.z;
                    float2 w; w.x = v0; w.y = v1;
                    *reinterpret_cast<float2*>(g_x_bias + (z * SEQ + m) * (size_t)ATT + n) = w;
                } else {
                    const int ng = (int)(blockIdx.y * 128) + n;
                    float2 w; w.x = v0 + b0[ng]; w.y = v1 + b0[ng + 1];
                    *reinterpret_cast<float2*>(pout + (size_t)m * HID + ng) = w;
                }
            }
        }
    }
}

// ======================= flash attention (512 threads, 16 warps) ===========
#define FL_QH 0u
#define FL_QL 32768u
#define FL_KB 65536u
#define FL_VB 131072u
#define FL_PH 196608u
#define FL_PL 212992u
#define FL_RS 229376u
#define FL_SMEM 231424

__global__ __launch_bounds__(512, 1) void flash_kernel() {
    extern __shared__ char smem[];
    const uint32_t sb = smem_u32(smem);
    const int tid = threadIdx.x, wid = tid >> 5, lane = tid & 31;
    const int wm = wid & 3, wn = wid >> 2;      // 4 (M) x 4 (N)
    const size_t z = blockIdx.z;
    const size_t q0 = (size_t)blockIdx.x * 128;

    const bf16* Qh = g_qh_h + z * SEQ * ATT;
    const bf16* Ql = g_qh_l + z * SEQ * ATT;
    const bf16* Kh = g_kh_h + z * SEQ * ATT;
    const bf16* Kl = g_kh_l + z * SEQ * ATT;
    const bf16* Vh = g_vh_h + z * SEQ * ATT;
    const bf16* Vl = g_vh_l + z * SEQ * ATT;

    {
        int t = tid;
#pragma unroll
        for (int i = 0; i < 4; i++) {
            int id = t + i * 512;
            int row = id >> 4, c = id & 15;
            CP_ASYNC16(sb + FL_QH + swz256(row, c), Qh + (q0 + row) * ATT + c * 8);
            CP_ASYNC16(sb + FL_QL + swz256(row, c), Ql + (q0 + row) * ATT + c * 8);
        }
    }
    auto loadKV = [&](int kt, int buf) {
        const size_t r0 = (size_t)kt * 64;
        const uint32_t kb = sb + FL_KB + buf * 32768u;
        const uint32_t vb = sb + FL_VB + buf * 32768u;
        int t = tid;
#pragma unroll
        for (int i = 0; i < 2; i++) {
            int id = t + i * 512;
            int row = id >> 4, c = id & 15;
            CP_ASYNC16(kb + swz256(row, c),          Kh + (r0 + row) * ATT + c * 8);
            CP_ASYNC16(kb + 16384 + swz256(row, c),  Kl + (r0 + row) * ATT + c * 8);
            CP_ASYNC16(vb + swz256(row, c),          Vh + (r0 + row) * ATT + c * 8);
            CP_ASYNC16(vb + 16384 + swz256(row, c),  Vl + (r0 + row) * ATT + c * 8);
        }
    };
    loadKV(0, 0);
    CP_COMMIT();

    float U[2][4][4];
#pragma unroll
    for (int a = 0; a < 2; a++)
#pragma unroll
        for (int b = 0; b < 4; b++)
#pragma unroll
            for (int r = 0; r < 4; r++) U[a][b][r] = 0.f;
    float rsum[2][2];
#pragma unroll
    for (int a = 0; a < 2; a++) { rsum[a][0] = 0.f; rsum[a][1] = 0.f; }

    const int j8 = lane >> 3, r8 = lane & 7;
    const int aRow = wm * 32 + (j8 & 1) * 8 + r8;
    const int aCh  = (j8 >> 1);
    const int kRow = wn * 16 + (j8 >> 1) * 8 + r8;
    const int kCh  = (j8 & 1);
    const int vRow = (j8 & 1) * 8 + r8;
    const int vCh  = wn * 4 + (j8 >> 1);
    const int gid = lane >> 2, tig = lane & 3;

    for (int kt = 0; kt < 32; kt++) {
        // wait current tile (incl. Q on kt=0), make visible, then prefetch next.
        CP_WAIT0();
        __syncthreads();
        if (kt + 1 < 32) { loadKV(kt + 1, (kt + 1) & 1); CP_COMMIT(); }

        const uint32_t kb  = sb + FL_KB + (kt & 1) * 32768u;
        const uint32_t kbl = kb + 16384;
        float sacc[2][2][4];
#pragma unroll
        for (int a = 0; a < 2; a++)
#pragma unroll
            for (int b = 0; b < 2; b++)
#pragma unroll
                for (int r = 0; r < 4; r++) sacc[a][b][r] = 0.f;
#pragma unroll
        for (int ks = 0; ks < 8; ks++) {
            uint32_t qa[2][4], ql[2][4], kf[4], lf[4];
#pragma unroll
            for (int mt = 0; mt < 2; mt++) {
                LDSM4(qa[mt], sb + FL_QH + swz256(aRow + mt * 16, ks * 2 + aCh));
                LDSM4(ql[mt], sb + FL_QL + swz256(aRow + mt * 16, ks * 2 + aCh));
            }
            LDSM4(kf, kb  + swz256(kRow, ks * 2 + kCh));
            LDSM4(lf, kbl + swz256(kRow, ks * 2 + kCh));
#pragma unroll
            for (int mt = 0; mt < 2; mt++)
#pragma unroll
                for (int nt = 0; nt < 2; nt++) {
                    const int p = nt * 2;
                    MMA16816(sacc[mt][nt], qa[mt], kf[p], kf[p + 1]);
                    MMA16816(sacc[mt][nt], qa[mt], lf[p], lf[p + 1]);
                    MMA16816(sacc[mt][nt], ql[mt], kf[p], kf[p + 1]);
                }
        }
#pragma unroll
        for (int mt = 0; mt < 2; mt++)
#pragma unroll
            for (int nt = 0; nt < 2; nt++) {
                float e0 = __expf(sacc[mt][nt][0]);
                float e1 = __expf(sacc[mt][nt][1]);
                float e2 = __expf(sacc[mt][nt][2]);
                float e3 = __expf(sacc[mt][nt][3]);
                rsum[mt][0] += e0 + e1;
                rsum[mt][1] += e2 + e3;
                uint32_t h01, l01, h23, l23;
                split_pack(e0, e1, h01, l01);
                split_pack(e2, e3, h23, l23);
                const int rlo = wm * 32 + mt * 16 + gid;
                const int chunk = wn * 2 + nt;
                uint32_t oflo = (uint32_t)(rlo * 128 + ((chunk ^ (rlo & 7)) * 16) + tig * 4);
                const int rhi = rlo + 8;
                uint32_t ofhi = (uint32_t)(rhi * 128 + ((chunk ^ (rhi & 7)) * 16) + tig * 4);
                *reinterpret_cast<uint32_t*>(smem + FL_PH + oflo) = h01;
                *reinterpret_cast<uint32_t*>(smem + FL_PL + oflo) = l01;
                *reinterpret_cast<uint32_t*>(smem + FL_PH + ofhi) = h23;
                *reinterpret_cast<uint32_t*>(smem + FL_PL + ofhi) = l23;
            }
        __syncthreads();
        const uint32_t vb  = sb + FL_VB + (kt & 1) * 32768u;
        const uint32_t vbl = vb + 16384;
#pragma unroll
        for (int ks2 = 0; ks2 < 4; ks2++) {
            uint32_t pa[2][4], pl[2][4], vh_[2][4], vl_[2][4];
#pragma unroll
            for (int mt = 0; mt < 2; mt++) {
                LDSM4(pa[mt], sb + FL_PH + swz128(aRow + mt * 16, ks2 * 2 + aCh));
                LDSM4(pl[mt], sb + FL_PL + swz128(aRow + mt * 16, ks2 * 2 + aCh));
            }
#pragma unroll
            for (int g = 0; g < 2; g++) {
                LDSM4T(vh_[g], vb  + swz256(ks2 * 16 + vRow, vCh + g * 2));
                LDSM4T(vl_[g], vbl + swz256(ks2 * 16 + vRow, vCh + g * 2));
            }
#pragma unroll
            for (int mt = 0; mt < 2; mt++)
#pragma unroll
                for (int nt = 0; nt < 4; nt++) {
                    const int g = nt >> 1, p = (nt & 1) * 2;
                    MMA16816(U[mt][nt], pa[mt], vh_[g][p], vh_[g][p + 1]);
                    MMA16816(U[mt][nt], pa[mt], vl_[g][p], vl_[g][p + 1]);
                    MMA16816(U[mt][nt], pl[mt], vh_[g][p], vh_[g][p + 1]);
                }
        }
    }
    __syncthreads();

    float* rs = reinterpret_cast<float*>(smem + FL_RS);   // [128][4]
#pragma unroll
    for (int mt = 0; mt < 2; mt++)
#pragma unroll
        for (int h = 0; h < 2; h++) {
            float s = rsum[mt][h];
            s += __shfl_xor_sync(0xffffffffu, s, 1);
            s += __shfl_xor_sync(0xffffffffu, s, 2);
            rsum[mt][h] = s;
        }
    if (tig == 0) {
#pragma unroll
        for (int mt = 0; mt < 2; mt++)
#pragma unroll
            for (int h = 0; h < 2; h++) {
                int row = wm * 32 + mt * 16 + gid + h * 8;
                rs[row * 4 + wn] = rsum[mt][h];
            }
    }
    __syncthreads();

#pragma unroll
    for (int mt = 0; mt < 2; mt++) {
#pragma unroll
        for (int h = 0; h < 2; h++) {
            const int rowL = wm * 32 + mt * 16 + gid + h * 8;
            const float tot = rs[rowL * 4 + 0] + rs[rowL * 4 + 1]
                            + rs[rowL * 4 + 2] + rs[rowL * 4 + 3];
            const float inv = 1.f / tot;
            const size_t m = q0 + rowL;
#pragma unroll
            for (int nt = 0; nt < 4; nt++) {
                const int n = wn * 32 + nt * 8 + tig * 2;
                const size_t o = (z * SEQ + m) * (size_t)ATT + n;
                float2 xb = *reinterpret_cast<const float2*>(g_x_bias + o);
                float v0 = U[mt][nt][h * 2]     * inv + xb.x;
                float v1 = U[mt][nt][h * 2 + 1] * inv + xb.y;
                bf16 h0, l0, h1, l1; split2(v0, h0, l0); split2(v1, h1, l1);
                bf162 hh; hh.x = h0; hh.y = h1;
                bf162 ll; ll.x = l0; ll.y = l1;
                *reinterpret_cast<bf162*>(g_x_h + o) = hh;
                *reinterpret_cast<bf162*>(g_x_l + o) = ll;
            }
        }
    }
}

// ======================= launch ============================================
extern "C" void kernel_launch(void* const* d_in, const int* in_sizes, int n_in,
                              void* d_out, int out_size) {
    const float* q         = (const float*)d_in[0];
    const float* k         = (const float*)d_in[1];
    const float* v         = (const float*)d_in[2];
    const float* attn_bias = (const float*)d_in[3];
    const float* wq        = (const float*)d_in[4];
    const float* bq        = (const float*)d_in[5];
    const float* wk        = (const float*)d_in[6];
    const float* bk        = (const float*)d_in[7];
    const float* wv        = (const float*)d_in[8];
    const float* bv        = (const float*)d_in[9];
    const float* wo        = (const float*)d_in[10];
    const float* bo        = (const float*)d_in[11];
    float* out = (float*)d_out;

    // one-time host resources (created on first call, before graph capture;
    // captured work is identical on every call)
    static bool s_init = false;
    static cudaStream_t s2;
    static cudaEvent_t evT, ev2;
    if (!s_init) {
        s_init = true;
        cudaStreamCreateWithFlags(&s2, cudaStreamNonBlocking);
        cudaEventCreateWithFlags(&evT, cudaEventDisableTiming);
        cudaEventCreateWithFlags(&ev2, cudaEventDisableTiming);
        cudaFuncSetAttribute(gemm_kernel<0>, cudaFuncAttributeMaxDynamicSharedMemorySize, 81920);
        cudaFuncSetAttribute(gemm_kernel<2>, cudaFuncAttributeMaxDynamicSharedMemorySize, 57344);
        cudaFuncSetAttribute(gemm_kernel<3>, cudaFuncAttributeMaxDynamicSharedMemorySize, 49152);
        cudaFuncSetAttribute(flash_kernel,   cudaFuncAttributeMaxDynamicSharedMemorySize, FL_SMEM);
    }

    // 1) weights -> wT hi/lo
    transpose_split_w_all<<<dim3(32, 32, 4), dim3(32, 8)>>>(wq, wk, wv, wo);
    cudaEventRecord(evT, 0);
    cudaStreamWaitEvent(s2, evT, 0);

    // side stream: v-projection then bias@vh (independent of q/k path)
    gemm_kernel<0><<<dim3(VIEW * SEQ / 128, 1, 1), GT, 81920, s2>>>(
        q, k, v, bq, bk, bv, nullptr, 2);
    gemm_kernel<2><<<dim3(SEQ / 64, 1, VIEW), GT, 57344, s2>>>(
        attn_bias, nullptr, nullptr, nullptr, nullptr, nullptr, nullptr, 0);
    cudaEventRecord(ev2, s2);

    // main stream: q,k projections (overlaps with side stream)
    gemm_kernel<0><<<dim3(VIEW * SEQ / 128, 1, 2), GT, 81920>>>(
        q, k, v, bq, bk, bv, nullptr, 0);

    cudaStreamWaitEvent(0, ev2, 0);
    // 4) flash (512 threads)
    flash_kernel<<<dim3(SEQ / 128, 1, VIEW), 512, FL_SMEM>>>();
    // 5) output projection
    gemm_kernel<3><<<dim3(SEQ / 64, HID / 128), GT, 49152>>>(
        nullptr, nullptr, nullptr, bo, nullptr, nullptr, out, 0);
}

// round 11
// speedup vs baseline: 3.8744x; 1.1563x over previous
#include <cuda_runtime.h>
#include <cuda_bf16.h>
#include <cuda_fp16.h>
#include <cstdint>
#include <math.h>

#define VIEW 8
#define SEQ  2048
#define HID  1024
#define ATT  128
#define SCALE 0.08838834764831845f   // ATT^-0.5

using bf16 = __nv_bfloat16;
using bf162 = __nv_bfloat162;

// ======================= device scratch (no allocs allowed) =================
__device__ __align__(256) bf16 g_wqT_h[ATT*HID], g_wqT_l[ATT*HID];
__device__ __align__(256) bf16 g_wkT_h[ATT*HID], g_wkT_l[ATT*HID];
__device__ __align__(256) bf16 g_wvT_h[ATT*HID], g_wvT_l[ATT*HID];
__device__ __align__(256) bf16 g_woT_h[HID*HID], g_woT_l[HID*HID];
__device__ __align__(256) bf16 g_qh_h[VIEW*SEQ*ATT], g_qh_l[VIEW*SEQ*ATT];
__device__ __align__(256) bf16 g_kh_h[VIEW*SEQ*ATT], g_kh_l[VIEW*SEQ*ATT];
__device__ __align__(256) __half g_vh_h[VIEW*SEQ*ATT], g_vh_l[VIEW*SEQ*ATT]; // fp16 now
__device__ __align__(256) float g_x_bias[VIEW*SEQ*ATT];
__device__ __align__(256) bf16 g_x_h[VIEW*SEQ*ATT], g_x_l[VIEW*SEQ*ATT];

// ======================= helpers ===========================================
__device__ __forceinline__ uint32_t smem_u32(const void* p) {
    uint32_t a;
    asm("{ .reg .u64 t; cvta.to.shared.u64 t, %1; cvt.u32.u64 %0, t; }" : "=r"(a) : "l"(p));
    return a;
}
__device__ __forceinline__ void split2(float x, bf16& h, bf16& l) {
    h = __float2bfloat16(x);
    l = __float2bfloat16(x - __bfloat162float(h));
}
__device__ __forceinline__ void split2h(float x, __half& h, __half& l) {
    h = __float2half_rn(x);
    l = __float2half_rn(x - __half2float(h));
}
__device__ __forceinline__ void split_pack(float a, float b, uint32_t& uh, uint32_t& ul) {
    bf16 ha, la, hb, lb; split2(a, ha, la); split2(b, hb, lb);
    bf162 H; H.x = ha; H.y = hb; uh = *reinterpret_cast<uint32_t*>(&H);
    bf162 L; L.x = la; L.y = lb; ul = *reinterpret_cast<uint32_t*>(&L);
}

#define CP_ASYNC16(saddr, gptr) \
    asm volatile("cp.async.cg.shared.global [%0], [%1], 16;" \
                 :: "r"(saddr), "l"(__cvta_generic_to_global(gptr)) : "memory")
#define CP_COMMIT() asm volatile("cp.async.commit_group;" ::: "memory")
#define CP_WAIT0()  asm volatile("cp.async.wait_group 0;" ::: "memory")
#define CP_WAIT1()  asm volatile("cp.async.wait_group 1;" ::: "memory")

#define LDSM4(R, addr) \
    asm volatile("ldmatrix.sync.aligned.m8n8.x4.shared.b16 {%0,%1,%2,%3}, [%4];" \
                 : "=r"((R)[0]), "=r"((R)[1]), "=r"((R)[2]), "=r"((R)[3]) : "r"(addr))
#define LDSM4T(R, addr) \
    asm volatile("ldmatrix.sync.aligned.m8n8.x4.trans.shared.b16 {%0,%1,%2,%3}, [%4];" \
                 : "=r"((R)[0]), "=r"((R)[1]), "=r"((R)[2]), "=r"((R)[3]) : "r"(addr))

#define MMA16816(C, A, b0, b1) \
    asm volatile("mma.sync.aligned.m16n8k16.row.col.f32.bf16.bf16.f32 " \
                 "{%0,%1,%2,%3},{%4,%5,%6,%7},{%8,%9},{%0,%1,%2,%3};" \
                 : "+f"((C)[0]), "+f"((C)[1]), "+f"((C)[2]), "+f"((C)[3]) \
                 : "r"((A)[0]), "r"((A)[1]), "r"((A)[2]), "r"((A)[3]), "r"(b0), "r"(b1))
#define MMA16816F(C, A, b0, b1) \
    asm volatile("mma.sync.aligned.m16n8k16.row.col.f32.f16.f16.f32 " \
                 "{%0,%1,%2,%3},{%4,%5,%6,%7},{%8,%9},{%0,%1,%2,%3};" \
                 : "+f"((C)[0]), "+f"((C)[1]), "+f"((C)[2]), "+f"((C)[3]) \
                 : "r"((A)[0]), "r"((A)[1]), "r"((A)[2]), "r"((A)[3]), "r"(b0), "r"(b1))

// ======================= fused weight transpose+split ======================
__global__ void transpose_split_w_all(const float* __restrict__ wq,
                                      const float* __restrict__ wk,
                                      const float* __restrict__ wv,
                                      const float* __restrict__ wo) {
    const int mode = blockIdx.z;
    const float* in;
    bf16 *dh, *dl; int C;
    if (mode == 0)      { in = wq; dh = g_wqT_h; dl = g_wqT_l; C = ATT; }
    else if (mode == 1) { in = wk; dh = g_wkT_h; dl = g_wkT_l; C = ATT; }
    else if (mode == 2) { in = wv; dh = g_wvT_h; dl = g_wvT_l; C = ATT; }
    else                { in = wo; dh = g_woT_h; dl = g_woT_l; C = HID; }
    if ((int)blockIdx.x * 32 >= C) return;
    __shared__ float t[32][33];
    const int R = HID;
    int c0 = blockIdx.x * 32, r0 = blockIdx.y * 32;
    int tx = threadIdx.x, ty = threadIdx.y;
#pragma unroll
    for (int i = 0; i < 4; i++)
        t[ty + i*8][tx] = in[(size_t)(r0 + ty + i*8) * C + c0 + tx];
    __syncthreads();
#pragma unroll
    for (int i = 0; i < 4; i++) {
        float x = t[tx][ty + i*8];
        bf16 h, l; split2(x, h, l);
        size_t o = (size_t)(c0 + ty + i*8) * R + r0 + tx;
        dh[o] = h; dl[o] = l;
    }
}

// ======================= swizzles ==========================================
__device__ __forceinline__ uint32_t swz(int row, int chunk) {       // 64B rows
    return (uint32_t)(row * 64 + ((chunk ^ ((row >> 1) & 3)) * 16));
}
__device__ __forceinline__ uint32_t swz256(int row, int chunk) {    // 256B rows
    return (uint32_t)(row * 256 + ((chunk ^ (row & 7)) * 16));
}
__device__ __forceinline__ uint32_t swz128(int row, int chunk) {    // 128B rows
    return (uint32_t)(row * 128 + ((chunk ^ (row & 7)) * 16));
}

// ======================= GEMM template =====================================
#define GT 256
#define KC 32

template <int ROWS>
__device__ __forceinline__ void load_tile_async(uint32_t sbase,
                                                const bf16* __restrict__ src,
                                                size_t row0, size_t ld) {
    int t = threadIdx.x;
#pragma unroll
    for (int i = 0; i < ROWS / 64; i++) {
        int id = t + i * 256;
        int row = id >> 2, c = id & 3;
        CP_ASYNC16(sbase + swz(row, c), src + (row0 + row) * ld + c * 8);
    }
}
__device__ __forceinline__ void load_vtile_async(uint32_t sbase,
                                                 const bf16* __restrict__ src,
                                                 size_t row0) {
    int t = threadIdx.x;
#pragma unroll
    for (int i = 0; i < 2; i++) {
        int id = t + i * 256;
        int row = id >> 4, c = id & 15;
        CP_ASYNC16(sbase + swz256(row, c), src + (row0 + row) * ATT + c * 8);
    }
}
template <int ROWS>
__device__ __forceinline__ void load_fp_async(uint32_t sbase,
                                              const float* __restrict__ src,
                                              size_t row0, size_t ld) {
    int t = threadIdx.x;
#pragma unroll
    for (int i = 0; i < ROWS / 32; i++) {
        int id = t + i * 256;
        int row = id >> 3, c = id & 7;
        CP_ASYNC16(sbase + swz128(row, c), src + (row0 + row) * ld + c * 4);
    }
}

// STAGE 0: proj (MT=128)  A = fp32 input (bf16x3 split), B wT bf16 h/l, K=1024
// STAGE 2: biasv (MT=64)  A = fp32 attn_bias -> fp16 single, B vh fp16 h/l (trans), K=2048
// STAGE 3: outproj (MT=64) A x bf16 h/l, B woT bf16 h/l, K=1024
template <int STAGE>
__global__ __launch_bounds__(GT, 2)
void gemm_kernel(const float* __restrict__ i0, const float* __restrict__ i1,
                 const float* __restrict__ i2, const float* __restrict__ b0,
                 const float* __restrict__ b1, const float* __restrict__ b2,
                 float* __restrict__ pout, int zbase) {
    constexpr int MT  = (STAGE == 0) ? 128 : 64;
    constexpr int MTI = MT / 32;
    constexpr bool FPA = (STAGE == 0 || STAGE == 2);
    constexpr bool F16A = (STAGE == 2);               // fp16-single A path
    constexpr uint32_t A_T  = MT * 64;
    constexpr uint32_t FPB  = MT * 128;
    constexpr uint32_t AH_OFF = FPA ? 2 * FPB : 0;
    constexpr uint32_t AL_OFF = AH_OFF + A_T;
    constexpr uint32_t B_OFF  = F16A ? (2 * FPB + A_T)
                               : FPA ? (2 * FPB + 2 * A_T) : (4 * A_T);

    extern __shared__ char smem[];
    const uint32_t sb = smem_u32(smem);
    const int tid = threadIdx.x, wid = tid >> 5, lane = tid & 31;
    const int wm = wid & 1, wn = wid >> 1;

    const bf16 *Bh0 = nullptr, *Bl0 = nullptr;
    const float* Xf = nullptr;
    size_t ldA = 0, ldB = 0, rowA0 = 0, rowB0 = 0;
    int K_TOTAL = 0;
    if constexpr (STAGE == 0) {
        int z = blockIdx.z + zbase;
        Xf  = z == 0 ? i0 : z == 1 ? i1 : i2;
        Bh0 = z == 0 ? g_wqT_h : z == 1 ? g_wkT_h : g_wvT_h;
        Bl0 = z == 0 ? g_wqT_l : z == 1 ? g_wkT_l : g_wvT_l;
        ldA = HID; ldB = HID; rowA0 = (size_t)blockIdx.x * MT; K_TOTAL = HID;
    } else if constexpr (STAGE == 2) {
        size_t z = blockIdx.z;
        Xf  = i0 + z * (size_t)SEQ * SEQ;
        Bh0 = reinterpret_cast<const bf16*>(g_vh_h + z * (size_t)SEQ * ATT);
        Bl0 = reinterpret_cast<const bf16*>(g_vh_l + z * (size_t)SEQ * ATT);
        ldA = SEQ;
        rowA0 = (size_t)blockIdx.x * MT; K_TOTAL = SEQ;
    } else {
        Bh0 = g_woT_h; Bl0 = g_woT_l;
        ldA = ATT; ldB = HID;
        rowA0 = (size_t)blockIdx.x * MT; rowB0 = (size_t)blockIdx.y * 128; K_TOTAL = HID;
    }
    const int nc = K_TOTAL / KC;

    auto load_chunk = [&](int c, int buf) {
        const int kb = c * KC;
        if constexpr (FPA) {
            load_fp_async<MT>(sb + buf * FPB, Xf + kb, rowA0, ldA);
        } else {
            size_t voff = (size_t)(kb >> 7) * (SEQ * ATT) + (kb & 127);
            load_tile_async<MT>(sb + buf * (2 * A_T),       g_x_h + voff, rowA0, ldA);
            load_tile_async<MT>(sb + buf * (2 * A_T) + A_T, g_x_l + voff, rowA0, ldA);
        }
        if constexpr (STAGE == 2) {
            load_vtile_async(sb + B_OFF + buf * 16384u,        Bh0, (size_t)kb);
            load_vtile_async(sb + B_OFF + buf * 16384u + 8192, Bl0, (size_t)kb);
        } else {
            load_tile_async<128>(sb + B_OFF + buf * 16384u,        Bh0 + kb, rowB0, ldB);
            load_tile_async<128>(sb + B_OFF + buf * 16384u + 8192, Bl0 + kb, rowB0, ldB);
        }
    };

    float acc[MTI][4][4];
#pragma unroll
    for (int a = 0; a < MTI; a++)
#pragma unroll
        for (int b = 0; b < 4; b++)
#pragma unroll
            for (int r2 = 0; r2 < 4; r2++) acc[a][b][r2] = 0.f;

    const int j8 = lane >> 3, r8 = lane & 7;
    const int aRowB = wm * (MT / 2) + (j8 & 1) * 8 + r8;
    const int aChB  = (j8 >> 1);
    const int bRowB = wn * 32 + (j8 >> 1) * 8 + r8;
    const int bChB  = (j8 & 1);
    const int vRowB = (j8 & 1) * 8 + r8;
    const int vChB  = wn * 4 + (j8 >> 1);

    load_chunk(0, 0);
    CP_COMMIT();

    for (int c = 0; c < nc; c++) {
        if (c + 1 < nc) {
            load_chunk(c + 1, (c + 1) & 1);
            CP_COMMIT();
            CP_WAIT1();
        } else {
            CP_WAIT0();
        }
        __syncthreads();

        if constexpr (F16A) {
            // fp32 staging -> fp16 single A tile (MT=64)
            const char* fpb = smem + (c & 1) * FPB;
            const int row = tid >> 2, q = tid & 3;
            float4 f0 = *reinterpret_cast<const float4*>(fpb + swz128(row, q * 2));
            float4 f1 = *reinterpret_cast<const float4*>(fpb + swz128(row, q * 2 + 1));
            __half2 p0 = __floats2half2_rn(f0.x, f0.y);
            __half2 p1 = __floats2half2_rn(f0.z, f0.w);
            __half2 p2 = __floats2half2_rn(f1.x, f1.y);
            __half2 p3 = __floats2half2_rn(f1.z, f1.w);
            uint4 hh;
            hh.x = *reinterpret_cast<uint32_t*>(&p0);
            hh.y = *reinterpret_cast<uint32_t*>(&p1);
            hh.z = *reinterpret_cast<uint32_t*>(&p2);
            hh.w = *reinterpret_cast<uint32_t*>(&p3);
            *reinterpret_cast<uint4*>(smem + AH_OFF + swz(row, q)) = hh;
            __syncthreads();
        } else if constexpr (FPA) {
            const char* fpb = smem + (c & 1) * FPB;
            const int row = tid >> 1, q = tid & 1;
            float4 f[4];
#pragma unroll
            for (int i = 0; i < 4; i++)
                f[i] = *reinterpret_cast<const float4*>(fpb + swz128(row, q * 4 + i));
#pragma unroll
            for (int j = 0; j < 2; j++) {
                uint4 hh, ll;
                split_pack(f[2*j].x,   f[2*j].y,   hh.x, ll.x);
                split_pack(f[2*j].z,   f[2*j].w,   hh.y, ll.y);
                split_pack(f[2*j+1].x, f[2*j+1].y, hh.z, ll.z);
                split_pack(f[2*j+1].z, f[2*j+1].w, hh.w, ll.w);
                *reinterpret_cast<uint4*>(smem + AH_OFF + swz(row, q * 2 + j)) = hh;
                *reinterpret_cast<uint4*>(smem + AL_OFF + swz(row, q * 2 + j)) = ll;
            }
            __syncthreads();
        }

        const uint32_t aB  = FPA ? sb + AH_OFF : sb + (c & 1) * (2 * A_T);
        const uint32_t alB = FPA ? sb + AL_OFF : sb + (c & 1) * (2 * A_T) + A_T;
        const uint32_t bB  = sb + B_OFF + (c & 1) * 16384u;
        const uint32_t blB = bB + 8192;
#pragma unroll
        for (int s = 0; s < 2; s++) {
            const int c0 = 2 * s;
            uint32_t ah[MTI][4], al[MTI][4], bh[2][4], bl[2][4];
#pragma unroll
            for (int mt = 0; mt < MTI; mt++) {
                LDSM4(ah[mt], aB + swz(aRowB + mt * 16, aChB + c0));
                if constexpr (!F16A)
                    LDSM4(al[mt], alB + swz(aRowB + mt * 16, aChB + c0));
            }
#pragma unroll
            for (int g = 0; g < 2; g++) {
                if constexpr (STAGE == 2) {
                    LDSM4T(bh[g], bB  + swz256(s * 16 + vRowB, vChB + g * 2));
                    LDSM4T(bl[g], blB + swz256(s * 16 + vRowB, vChB + g * 2));
                } else {
                    LDSM4(bh[g], bB  + swz(bRowB + g * 16, bChB + c0));
                    LDSM4(bl[g], blB + swz(bRowB + g * 16, bChB + c0));
                }
            }
#pragma unroll
            for (int mt = 0; mt < MTI; mt++)
#pragma unroll
                for (int nt = 0; nt < 4; nt++) {
                    const int g = nt >> 1, p = (nt & 1) * 2;
                    if constexpr (F16A) {
                        MMA16816F(acc[mt][nt], ah[mt], bh[g][p], bh[g][p + 1]);
                        MMA16816F(acc[mt][nt], ah[mt], bl[g][p], bl[g][p + 1]);
                    } else {
                        MMA16816(acc[mt][nt], ah[mt], bh[g][p], bh[g][p + 1]);
                        MMA16816(acc[mt][nt], ah[mt], bl[g][p], bl[g][p + 1]);
                        MMA16816(acc[mt][nt], al[mt], bh[g][p], bh[g][p + 1]);
                    }
                }
        }
        __syncthreads();
    }

    const int gid = lane >> 2, tig = lane & 3;
#pragma unroll
    for (int mt = 0; mt < MTI; mt++) {
#pragma unroll
        for (int h = 0; h < 2; h++) {
            const int m = (int)(blockIdx.x * MT) + wm * (MT / 2) + mt * 16 + gid + h * 8;
#pragma unroll
            for (int nt = 0; nt < 4; nt++) {
                const int n = wn * 32 + nt * 8 + tig * 2;
                float v0 = acc[mt][nt][h * 2];
                float v1 = acc[mt][nt][h * 2 + 1];
                if constexpr (STAGE == 0) {
                    int z = blockIdx.z + zbase;
                    const float* bias = z == 0 ? b0 : z == 1 ? b1 : b2;
                    float scl = (z == 0) ? SCALE : 1.f;
                    v0 = (v0 + bias[n]) * scl; v1 = (v1 + bias[n + 1]) * scl;
                    size_t o = (size_t)m * ATT + n;
                    if (z == 2) {
                        __half h0, l0, h1, l1; split2h(v0, h0, l0); split2h(v1, h1, l1);
                        __half2 hh; hh.x = h0; hh.y = h1;
                        __half2 ll; ll.x = l0; ll.y = l1;
                        *reinterpret_cast<__half2*>(g_vh_h + o) = hh;
                        *reinterpret_cast<__half2*>(g_vh_l + o) = ll;
                    } else {
                        bf16 h0, l0, h1, l1; split2(v0, h0, l0); split2(v1, h1, l1);
                        bf162 hh; hh.x = h0; hh.y = h1;
                        bf162 ll; ll.x = l0; ll.y = l1;
                        bf16* dh = z == 0 ? g_qh_h : g_kh_h;
                        bf16* dl = z == 0 ? g_qh_l : g_kh_l;
                        *reinterpret_cast<bf162*>(dh + o) = hh;
                        *reinterpret_cast<bf162*>(dl + o) = ll;
                    }
                } else if constexpr (STAGE == 2) {
                    size_t z = blockIdx.z;
                    float2 w; w.x = v0; w.y = v1;
                    *reinterpret_cast<float2*>(g_x_bias + (z * SEQ + m) * (size_t)ATT + n) = w;
                } else {
                    const int ng = (int)(blockIdx.y * 128) + n;
                    float2 w; w.x = v0 + b0[ng]; w.y = v1 + b0[ng + 1];
                    *reinterpret_cast<float2*>(pout + (size_t)m * HID + ng) = w;
                }
            }
        }
    }
}

// ======================= flash attention (512 threads, fp16 P/V) ===========
#define FL_QH 0u
#define FL_QL 32768u
#define FL_KB 65536u
#define FL_VB 131072u
#define FL_PH 196608u
#define FL_RS 212992u
#define FL_SMEM 215040

__global__ __launch_bounds__(512, 1) void flash_kernel() {
    extern __shared__ char smem[];
    const uint32_t sb = smem_u32(smem);
    const int tid = threadIdx.x, wid = tid >> 5, lane = tid & 31;
    const int wm = wid & 3, wn = wid >> 2;      // 4 (M) x 4 (N)
    const size_t z = blockIdx.z;
    const size_t q0 = (size_t)blockIdx.x * 128;

    const bf16* Qh = g_qh_h + z * SEQ * ATT;
    const bf16* Ql = g_qh_l + z * SEQ * ATT;
    const bf16* Kh = g_kh_h + z * SEQ * ATT;
    const bf16* Kl = g_kh_l + z * SEQ * ATT;
    const __half* Vh = g_vh_h + z * SEQ * ATT;
    const __half* Vl = g_vh_l + z * SEQ * ATT;

    {
        int t = tid;
#pragma unroll
        for (int i = 0; i < 4; i++) {
            int id = t + i * 512;
            int row = id >> 4, c = id & 15;
            CP_ASYNC16(sb + FL_QH + swz256(row, c), Qh + (q0 + row) * ATT + c * 8);
            CP_ASYNC16(sb + FL_QL + swz256(row, c), Ql + (q0 + row) * ATT + c * 8);
        }
    }
    auto loadKV = [&](int kt, int buf) {
        const size_t r0 = (size_t)kt * 64;
        const uint32_t kb = sb + FL_KB + buf * 32768u;
        const uint32_t vb = sb + FL_VB + buf * 32768u;
        int t = tid;
#pragma unroll
        for (int i = 0; i < 2; i++) {
            int id = t + i * 512;
            int row = id >> 4, c = id & 15;
            CP_ASYNC16(kb + swz256(row, c),          Kh + (r0 + row) * ATT + c * 8);
            CP_ASYNC16(kb + 16384 + swz256(row, c),  Kl + (r0 + row) * ATT + c * 8);
            CP_ASYNC16(vb + swz256(row, c),          Vh + (r0 + row) * ATT + c * 8);
            CP_ASYNC16(vb + 16384 + swz256(row, c),  Vl + (r0 + row) * ATT + c * 8);
        }
    };
    loadKV(0, 0);
    CP_COMMIT();

    float U[2][4][4];
#pragma unroll
    for (int a = 0; a < 2; a++)
#pragma unroll
        for (int b = 0; b < 4; b++)
#pragma unroll
            for (int r = 0; r < 4; r++) U[a][b][r] = 0.f;
    float rsum[2][2];
#pragma unroll
    for (int a = 0; a < 2; a++) { rsum[a][0] = 0.f; rsum[a][1] = 0.f; }

    const int j8 = lane >> 3, r8 = lane & 7;
    const int aRow = wm * 32 + (j8 & 1) * 8 + r8;
    const int aCh  = (j8 >> 1);
    const int kRow = wn * 16 + (j8 >> 1) * 8 + r8;
    const int kCh  = (j8 & 1);
    const int vRow = (j8 & 1) * 8 + r8;
    const int vCh  = wn * 4 + (j8 >> 1);
    const int gid = lane >> 2, tig = lane & 3;

    for (int kt = 0; kt < 32; kt++) {
        CP_WAIT0();
        __syncthreads();
        if (kt + 1 < 32) { loadKV(kt + 1, (kt + 1) & 1); CP_COMMIT(); }

        const uint32_t kb  = sb + FL_KB + (kt & 1) * 32768u;
        const uint32_t kbl = kb + 16384;
        float sacc[2][2][4];
#pragma unroll
        for (int a = 0; a < 2; a++)
#pragma unroll
            for (int b = 0; b < 2; b++)
#pragma unroll
                for (int r = 0; r < 4; r++) sacc[a][b][r] = 0.f;
#pragma unroll
        for (int ks = 0; ks < 8; ks++) {
            uint32_t qa[2][4], ql[2][4], kf[4], lf[4];
#pragma unroll
            for (int mt = 0; mt < 2; mt++) {
                LDSM4(qa[mt], sb + FL_QH + swz256(aRow + mt * 16, ks * 2 + aCh));
                LDSM4(ql[mt], sb + FL_QL + swz256(aRow + mt * 16, ks * 2 + aCh));
            }
            LDSM4(kf, kb  + swz256(kRow, ks * 2 + kCh));
            LDSM4(lf, kbl + swz256(kRow, ks * 2 + kCh));
#pragma unroll
            for (int mt = 0; mt < 2; mt++)
#pragma unroll
                for (int nt = 0; nt < 2; nt++) {
                    const int p = nt * 2;
                    MMA16816(sacc[mt][nt], qa[mt], kf[p], kf[p + 1]);
                    MMA16816(sacc[mt][nt], qa[mt], lf[p], lf[p + 1]);
                    MMA16816(sacc[mt][nt], ql[mt], kf[p], kf[p + 1]);
                }
        }
        // P = exp(S) -> fp16 single, store to smem, accumulate rowsums
#pragma unroll
        for (int mt = 0; mt < 2; mt++)
#pragma unroll
            for (int nt = 0; nt < 2; nt++) {
                float e0 = __expf(sacc[mt][nt][0]);
                float e1 = __expf(sacc[mt][nt][1]);
                float e2 = __expf(sacc[mt][nt][2]);
                float e3 = __expf(sacc[mt][nt][3]);
                rsum[mt][0] += e0 + e1;
                rsum[mt][1] += e2 + e3;
                __half2 p01 = __floats2half2_rn(e0, e1);
                __half2 p23 = __floats2half2_rn(e2, e3);
                const int rlo = wm * 32 + mt * 16 + gid;
                const int chunk = wn * 2 + nt;
                uint32_t oflo = (uint32_t)(rlo * 128 + ((chunk ^ (rlo & 7)) * 16) + tig * 4);
                const int rhi = rlo + 8;
                uint32_t ofhi = (uint32_t)(rhi * 128 + ((chunk ^ (rhi & 7)) * 16) + tig * 4);
                *reinterpret_cast<uint32_t*>(smem + FL_PH + oflo) = *reinterpret_cast<uint32_t*>(&p01);
                *reinterpret_cast<uint32_t*>(smem + FL_PH + ofhi) = *reinterpret_cast<uint32_t*>(&p23);
            }
        __syncthreads();
        const uint32_t vb  = sb + FL_VB + (kt & 1) * 32768u;
        const uint32_t vbl = vb + 16384;
#pragma unroll
        for (int ks2 = 0; ks2 < 4; ks2++) {
            uint32_t pa[2][4], vh_[2][4], vl_[2][4];
#pragma unroll
            for (int mt = 0; mt < 2; mt++)
                LDSM4(pa[mt], sb + FL_PH + swz128(aRow + mt * 16, ks2 * 2 + aCh));
#pragma unroll
            for (int g = 0; g < 2; g++) {
                LDSM4T(vh_[g], vb  + swz256(ks2 * 16 + vRow, vCh + g * 2));
                LDSM4T(vl_[g], vbl + swz256(ks2 * 16 + vRow, vCh + g * 2));
            }
#pragma unroll
            for (int mt = 0; mt < 2; mt++)
#pragma unroll
                for (int nt = 0; nt < 4; nt++) {
                    const int g = nt >> 1, p = (nt & 1) * 2;
                    MMA16816F(U[mt][nt], pa[mt], vh_[g][p], vh_[g][p + 1]);
                    MMA16816F(U[mt][nt], pa[mt], vl_[g][p], vl_[g][p + 1]);
                }
        }
    }
    __syncthreads();

    float* rs = reinterpret_cast<float*>(smem + FL_RS);   // [128][4]
#pragma unroll
    for (int mt = 0; mt < 2; mt++)
#pragma unroll
        for (int h = 0; h < 2; h++) {
            float s = rsum[mt][h];
            s += __shfl_xor_sync(0xffffffffu, s, 1);
            s += __shfl_xor_sync(0xffffffffu, s, 2);
            rsum[mt][h] = s;
        }
    if (tig == 0) {
#pragma unroll
        for (int mt = 0; mt < 2; mt++)
#pragma unroll
            for (int h = 0; h < 2; h++) {
                int row = wm * 32 + mt * 16 + gid + h * 8;
                rs[row * 4 + wn] = rsum[mt][h];
            }
    }
    __syncthreads();

#pragma unroll
    for (int mt = 0; mt < 2; mt++) {
#pragma unroll
        for (int h = 0; h < 2; h++) {
            const int rowL = wm * 32 + mt * 16 + gid + h * 8;
            const float tot = rs[rowL * 4 + 0] + rs[rowL * 4 + 1]
                            + rs[rowL * 4 + 2] + rs[rowL * 4 + 3];
            const float inv = 1.f / tot;
            const size_t m = q0 + rowL;
#pragma unroll
            for (int nt = 0; nt < 4; nt++) {
                const int n = wn * 32 + nt * 8 + tig * 2;
                const size_t o = (z * SEQ + m) * (size_t)ATT + n;
                float2 xb = *reinterpret_cast<const float2*>(g_x_bias + o);
                float v0 = U[mt][nt][h * 2]     * inv + xb.x;
                float v1 = U[mt][nt][h * 2 + 1] * inv + xb.y;
                bf16 h0, l0, h1, l1; split2(v0, h0, l0); split2(v1, h1, l1);
                bf162 hh; hh.x = h0; hh.y = h1;
                bf162 ll; ll.x = l0; ll.y = l1;
                *reinterpret_cast<bf162*>(g_x_h + o) = hh;
                *reinterpret_cast<bf162*>(g_x_l + o) = ll;
            }
        }
    }
}

// ======================= launch ============================================
extern "C" void kernel_launch(void* const* d_in, const int* in_sizes, int n_in,
                              void* d_out, int out_size) {
    const float* q         = (const float*)d_in[0];
    const float* k         = (const float*)d_in[1];
    const float* v         = (const float*)d_in[2];
    const float* attn_bias = (const float*)d_in[3];
    const float* wq        = (const float*)d_in[4];
    const float* bq        = (const float*)d_in[5];
    const float* wk        = (const float*)d_in[6];
    const float* bk        = (const float*)d_in[7];
    const float* wv        = (const float*)d_in[8];
    const float* bv        = (const float*)d_in[9];
    const float* wo        = (const float*)d_in[10];
    const float* bo        = (const float*)d_in[11];
    float* out = (float*)d_out;

    static bool s_init = false;
    static cudaStream_t s2;
    static cudaEvent_t evT, ev2;
    if (!s_init) {
        s_init = true;
        cudaStreamCreateWithFlags(&s2, cudaStreamNonBlocking);
        cudaEventCreateWithFlags(&evT, cudaEventDisableTiming);
        cudaEventCreateWithFlags(&ev2, cudaEventDisableTiming);
        cudaFuncSetAttribute(gemm_kernel<0>, cudaFuncAttributeMaxDynamicSharedMemorySize, 81920);
        cudaFuncSetAttribute(gemm_kernel<2>, cudaFuncAttributeMaxDynamicSharedMemorySize, 53248);
        cudaFuncSetAttribute(gemm_kernel<3>, cudaFuncAttributeMaxDynamicSharedMemorySize, 49152);
        cudaFuncSetAttribute(flash_kernel,   cudaFuncAttributeMaxDynamicSharedMemorySize, FL_SMEM);
    }

    // 1) weights -> wT hi/lo
    transpose_split_w_all<<<dim3(32, 32, 4), dim3(32, 8)>>>(wq, wk, wv, wo);
    cudaEventRecord(evT, 0);
    cudaStreamWaitEvent(s2, evT, 0);

    // side stream: v-projection then bias@vh
    gemm_kernel<0><<<dim3(VIEW * SEQ / 128, 1, 1), GT, 81920, s2>>>(
        q, k, v, bq, bk, bv, nullptr, 2);
    gemm_kernel<2><<<dim3(SEQ / 64, 1, VIEW), GT, 53248, s2>>>(
        attn_bias, nullptr, nullptr, nullptr, nullptr, nullptr, nullptr, 0);
    cudaEventRecord(ev2, s2);

    // main stream: q,k projections
    gemm_kernel<0><<<dim3(VIEW * SEQ / 128, 1, 2), GT, 81920>>>(
        q, k, v, bq, bk, bv, nullptr, 0);

    cudaStreamWaitEvent(0, ev2, 0);
    // 4) flash
    flash_kernel<<<dim3(SEQ / 128, 1, VIEW), 512, FL_SMEM>>>();
    // 5) output projection
    gemm_kernel<3><<<dim3(SEQ / 64, HID / 128), GT, 49152>>>(
        nullptr, nullptr, nullptr, bo, nullptr, nullptr, out, 0);
}

// round 12
// speedup vs baseline: 4.6213x; 1.1928x over previous
#include <cuda_runtime.h>
#include <cuda_bf16.h>
#include <cuda_fp16.h>
#include <cstdint>
#include <math.h>

#define VIEW 8
#define SEQ  2048
#define HID  1024
#define ATT  128
#define SCALE 0.08838834764831845f   // ATT^-0.5

using bf16 = __nv_bfloat16;

// ======================= device scratch (no allocs allowed) =================
__device__ __align__(256) __half g_wqT_h[ATT*HID], g_wqT_l[ATT*HID];
__device__ __align__(256) __half g_wkT_h[ATT*HID], g_wkT_l[ATT*HID];
__device__ __align__(256) __half g_wvT_h[ATT*HID], g_wvT_l[ATT*HID];
__device__ __align__(256) __half g_woT_h[HID*HID], g_woT_l[HID*HID];
__device__ __align__(256) __half g_qh[VIEW*SEQ*ATT];                     // fp16 single
__device__ __align__(256) __half g_kh_h[VIEW*SEQ*ATT], g_kh_l[VIEW*SEQ*ATT];
__device__ __align__(256) __half g_vh_h[VIEW*SEQ*ATT], g_vh_l[VIEW*SEQ*ATT];
__device__ __align__(256) float g_x_bias[VIEW*SEQ*ATT];
__device__ __align__(256) __half g_x[VIEW*SEQ*ATT];                      // fp16 single

// ======================= helpers ===========================================
__device__ __forceinline__ uint32_t smem_u32(const void* p) {
    uint32_t a;
    asm("{ .reg .u64 t; cvta.to.shared.u64 t, %1; cvt.u32.u64 %0, t; }" : "=r"(a) : "l"(p));
    return a;
}
__device__ __forceinline__ void split2h(float x, __half& h, __half& l) {
    h = __float2half_rn(x);
    l = __float2half_rn(x - __half2float(h));
}

#define CP_ASYNC16(saddr, gptr) \
    asm volatile("cp.async.cg.shared.global [%0], [%1], 16;" \
                 :: "r"(saddr), "l"(__cvta_generic_to_global(gptr)) : "memory")
#define CP_COMMIT() asm volatile("cp.async.commit_group;" ::: "memory")
#define CP_WAIT0()  asm volatile("cp.async.wait_group 0;" ::: "memory")
#define CP_WAIT1()  asm volatile("cp.async.wait_group 1;" ::: "memory")

#define LDSM4(R, addr) \
    asm volatile("ldmatrix.sync.aligned.m8n8.x4.shared.b16 {%0,%1,%2,%3}, [%4];" \
                 : "=r"((R)[0]), "=r"((R)[1]), "=r"((R)[2]), "=r"((R)[3]) : "r"(addr))
#define LDSM4T(R, addr) \
    asm volatile("ldmatrix.sync.aligned.m8n8.x4.trans.shared.b16 {%0,%1,%2,%3}, [%4];" \
                 : "=r"((R)[0]), "=r"((R)[1]), "=r"((R)[2]), "=r"((R)[3]) : "r"(addr))

#define MMA16816F(C, A, b0, b1) \
    asm volatile("mma.sync.aligned.m16n8k16.row.col.f32.f16.f16.f32 " \
                 "{%0,%1,%2,%3},{%4,%5,%6,%7},{%8,%9},{%0,%1,%2,%3};" \
                 : "+f"((C)[0]), "+f"((C)[1]), "+f"((C)[2]), "+f"((C)[3]) \
                 : "r"((A)[0]), "r"((A)[1]), "r"((A)[2]), "r"((A)[3]), "r"(b0), "r"(b1))

// ======================= fused weight transpose+split (fp16 h/l) ===========
__global__ void transpose_split_w_all(const float* __restrict__ wq,
                                      const float* __restrict__ wk,
                                      const float* __restrict__ wv,
                                      const float* __restrict__ wo) {
    const int mode = blockIdx.z;
    const float* in;
    __half *dh, *dl; int C;
    if (mode == 0)      { in = wq; dh = g_wqT_h; dl = g_wqT_l; C = ATT; }
    else if (mode == 1) { in = wk; dh = g_wkT_h; dl = g_wkT_l; C = ATT; }
    else if (mode == 2) { in = wv; dh = g_wvT_h; dl = g_wvT_l; C = ATT; }
    else                { in = wo; dh = g_woT_h; dl = g_woT_l; C = HID; }
    if ((int)blockIdx.x * 32 >= C) return;
    __shared__ float t[32][33];
    const int R = HID;
    int c0 = blockIdx.x * 32, r0 = blockIdx.y * 32;
    int tx = threadIdx.x, ty = threadIdx.y;
#pragma unroll
    for (int i = 0; i < 4; i++)
        t[ty + i*8][tx] = in[(size_t)(r0 + ty + i*8) * C + c0 + tx];
    __syncthreads();
#pragma unroll
    for (int i = 0; i < 4; i++) {
        float x = t[tx][ty + i*8];
        __half h, l; split2h(x, h, l);
        size_t o = (size_t)(c0 + ty + i*8) * R + r0 + tx;
        dh[o] = h; dl[o] = l;
    }
}

// ======================= swizzles ==========================================
__device__ __forceinline__ uint32_t swz(int row, int chunk) {       // 64B rows
    return (uint32_t)(row * 64 + ((chunk ^ ((row >> 1) & 3)) * 16));
}
__device__ __forceinline__ uint32_t swz256(int row, int chunk) {    // 256B rows
    return (uint32_t)(row * 256 + ((chunk ^ (row & 7)) * 16));
}
__device__ __forceinline__ uint32_t swz128(int row, int chunk) {    // 128B rows
    return (uint32_t)(row * 128 + ((chunk ^ (row & 7)) * 16));
}

// ======================= GEMM template =====================================
#define GT 256
#define KC 32

template <int ROWS>
__device__ __forceinline__ void load_tile_async(uint32_t sbase,
                                                const __half* __restrict__ src,
                                                size_t row0, size_t ld) {
    int t = threadIdx.x;
#pragma unroll
    for (int i = 0; i < ROWS / 64; i++) {
        int id = t + i * 256;
        int row = id >> 2, c = id & 3;
        CP_ASYNC16(sbase + swz(row, c), src + (row0 + row) * ld + c * 8);
    }
}
__device__ __forceinline__ void load_vtile_async(uint32_t sbase,
                                                 const __half* __restrict__ src,
                                                 size_t row0) {
    int t = threadIdx.x;
#pragma unroll
    for (int i = 0; i < 2; i++) {
        int id = t + i * 256;
        int row = id >> 4, c = id & 15;
        CP_ASYNC16(sbase + swz256(row, c), src + (row0 + row) * ATT + c * 8);
    }
}
template <int ROWS>
__device__ __forceinline__ void load_fp_async(uint32_t sbase,
                                              const float* __restrict__ src,
                                              size_t row0, size_t ld) {
    int t = threadIdx.x;
#pragma unroll
    for (int i = 0; i < ROWS / 32; i++) {
        int id = t + i * 256;
        int row = id >> 3, c = id & 7;
        CP_ASYNC16(sbase + swz128(row, c), src + (row0 + row) * ld + c * 4);
    }
}

// STAGE 0: proj (MT=128)  A = fp32 input -> fp16 single, B wT fp16 h/l, K=1024
// STAGE 2: biasv (MT=64)  A = fp32 attn_bias -> fp16 single, B vh fp16 h/l (trans), K=2048
// STAGE 3: outproj (MT=64) A = g_x fp16 single, B woT fp16 h/l, K=1024
template <int STAGE>
__global__ __launch_bounds__(GT, 2)
void gemm_kernel(const float* __restrict__ i0, const float* __restrict__ i1,
                 const float* __restrict__ i2, const float* __restrict__ b0,
                 const float* __restrict__ b1, const float* __restrict__ b2,
                 float* __restrict__ pout, int zbase) {
    constexpr int MT  = (STAGE == 0) ? 128 : 64;
    constexpr int MTI = MT / 32;
    constexpr bool FPA = (STAGE == 0 || STAGE == 2);
    constexpr uint32_t A_T  = MT * 64;            // fp16-single A tile bytes
    constexpr uint32_t FPB  = MT * 128;           // fp32 staging tile bytes
    constexpr uint32_t AH_OFF = FPA ? 2 * FPB : 0;
    constexpr uint32_t B_OFF  = FPA ? (2 * FPB + A_T) : (2 * A_T);

    extern __shared__ char smem[];
    const uint32_t sb = smem_u32(smem);
    const int tid = threadIdx.x, wid = tid >> 5, lane = tid & 31;
    const int wm = wid & 1, wn = wid >> 1;

    const __half *Bh0 = nullptr, *Bl0 = nullptr;
    const float* Xf = nullptr;
    size_t ldA = 0, ldB = 0, rowA0 = 0, rowB0 = 0;
    int K_TOTAL = 0;
    if constexpr (STAGE == 0) {
        int z = blockIdx.z + zbase;
        Xf  = z == 0 ? i0 : z == 1 ? i1 : i2;
        Bh0 = z == 0 ? g_wqT_h : z == 1 ? g_wkT_h : g_wvT_h;
        Bl0 = z == 0 ? g_wqT_l : z == 1 ? g_wkT_l : g_wvT_l;
        ldA = HID; ldB = HID; rowA0 = (size_t)blockIdx.x * MT; K_TOTAL = HID;
    } else if constexpr (STAGE == 2) {
        size_t z = blockIdx.z;
        Xf  = i0 + z * (size_t)SEQ * SEQ;
        Bh0 = g_vh_h + z * (size_t)SEQ * ATT;
        Bl0 = g_vh_l + z * (size_t)SEQ * ATT;
        ldA = SEQ;
        rowA0 = (size_t)blockIdx.x * MT; K_TOTAL = SEQ;
    } else {
        Bh0 = g_woT_h; Bl0 = g_woT_l;
        ldA = ATT; ldB = HID;
        rowA0 = (size_t)blockIdx.x * MT; rowB0 = (size_t)blockIdx.y * 128; K_TOTAL = HID;
    }
    const int nc = K_TOTAL / KC;

    auto load_chunk = [&](int c, int buf) {
        const int kb = c * KC;
        if constexpr (FPA) {
            load_fp_async<MT>(sb + buf * FPB, Xf + kb, rowA0, ldA);
        } else {
            size_t voff = (size_t)(kb >> 7) * (SEQ * ATT) + (kb & 127);
            load_tile_async<MT>(sb + buf * A_T, g_x + voff, rowA0, ldA);
        }
        if constexpr (STAGE == 2) {
            load_vtile_async(sb + B_OFF + buf * 16384u,        Bh0, (size_t)kb);
            load_vtile_async(sb + B_OFF + buf * 16384u + 8192, Bl0, (size_t)kb);
        } else {
            load_tile_async<128>(sb + B_OFF + buf * 16384u,        Bh0 + kb, rowB0, ldB);
            load_tile_async<128>(sb + B_OFF + buf * 16384u + 8192, Bl0 + kb, rowB0, ldB);
        }
    };

    float acc[MTI][4][4];
#pragma unroll
    for (int a = 0; a < MTI; a++)
#pragma unroll
        for (int b = 0; b < 4; b++)
#pragma unroll
            for (int r2 = 0; r2 < 4; r2++) acc[a][b][r2] = 0.f;

    const int j8 = lane >> 3, r8 = lane & 7;
    const int aRowB = wm * (MT / 2) + (j8 & 1) * 8 + r8;
    const int aChB  = (j8 >> 1);
    const int bRowB = wn * 32 + (j8 >> 1) * 8 + r8;
    const int bChB  = (j8 & 1);
    const int vRowB = (j8 & 1) * 8 + r8;
    const int vChB  = wn * 4 + (j8 >> 1);

    load_chunk(0, 0);
    CP_COMMIT();

    for (int c = 0; c < nc; c++) {
        if (c + 1 < nc) {
            load_chunk(c + 1, (c + 1) & 1);
            CP_COMMIT();
            CP_WAIT1();
        } else {
            CP_WAIT0();
        }
        __syncthreads();

        if constexpr (FPA) {
            // fp32 staging -> fp16 single A tile
            const char* fpb = smem + (c & 1) * FPB;
#pragma unroll
            for (int i = 0; i < MT / 64; i++) {
                int id = tid + i * 256;
                const int row = id >> 2, q = id & 3;
                float4 f0 = *reinterpret_cast<const float4*>(fpb + swz128(row, q * 2));
                float4 f1 = *reinterpret_cast<const float4*>(fpb + swz128(row, q * 2 + 1));
                __half2 p0 = __floats2half2_rn(f0.x, f0.y);
                __half2 p1 = __floats2half2_rn(f0.z, f0.w);
                __half2 p2 = __floats2half2_rn(f1.x, f1.y);
                __half2 p3 = __floats2half2_rn(f1.z, f1.w);
                uint4 hh;
                hh.x = *reinterpret_cast<uint32_t*>(&p0);
                hh.y = *reinterpret_cast<uint32_t*>(&p1);
                hh.z = *reinterpret_cast<uint32_t*>(&p2);
                hh.w = *reinterpret_cast<uint32_t*>(&p3);
                *reinterpret_cast<uint4*>(smem + AH_OFF + swz(row, q)) = hh;
            }
            __syncthreads();
        }

        const uint32_t aB  = FPA ? sb + AH_OFF : sb + (c & 1) * A_T;
        const uint32_t bB  = sb + B_OFF + (c & 1) * 16384u;
        const uint32_t blB = bB + 8192;
#pragma unroll
        for (int s = 0; s < 2; s++) {
            const int c0 = 2 * s;
            uint32_t ah[MTI][4], bh[2][4], bl[2][4];
#pragma unroll
            for (int mt = 0; mt < MTI; mt++)
                LDSM4(ah[mt], aB + swz(aRowB + mt * 16, aChB + c0));
#pragma unroll
            for (int g = 0; g < 2; g++) {
                if constexpr (STAGE == 2) {
                    LDSM4T(bh[g], bB  + swz256(s * 16 + vRowB, vChB + g * 2));
                    LDSM4T(bl[g], blB + swz256(s * 16 + vRowB, vChB + g * 2));
                } else {
                    LDSM4(bh[g], bB  + swz(bRowB + g * 16, bChB + c0));
                    LDSM4(bl[g], blB + swz(bRowB + g * 16, bChB + c0));
                }
            }
#pragma unroll
            for (int mt = 0; mt < MTI; mt++)
#pragma unroll
                for (int nt = 0; nt < 4; nt++) {
                    const int g = nt >> 1, p = (nt & 1) * 2;
                    MMA16816F(acc[mt][nt], ah[mt], bh[g][p], bh[g][p + 1]);
                    MMA16816F(acc[mt][nt], ah[mt], bl[g][p], bl[g][p + 1]);
                }
        }
        __syncthreads();
    }

    const int gid = lane >> 2, tig = lane & 3;
#pragma unroll
    for (int mt = 0; mt < MTI; mt++) {
#pragma unroll
        for (int h = 0; h < 2; h++) {
            const int m = (int)(blockIdx.x * MT) + wm * (MT / 2) + mt * 16 + gid + h * 8;
#pragma unroll
            for (int nt = 0; nt < 4; nt++) {
                const int n = wn * 32 + nt * 8 + tig * 2;
                float v0 = acc[mt][nt][h * 2];
                float v1 = acc[mt][nt][h * 2 + 1];
                if constexpr (STAGE == 0) {
                    int z = blockIdx.z + zbase;
                    const float* bias = z == 0 ? b0 : z == 1 ? b1 : b2;
                    float scl = (z == 0) ? SCALE : 1.f;
                    v0 = (v0 + bias[n]) * scl; v1 = (v1 + bias[n + 1]) * scl;
                    size_t o = (size_t)m * ATT + n;
                    if (z == 0) {
                        __half2 hh = __floats2half2_rn(v0, v1);
                        *reinterpret_cast<__half2*>(g_qh + o) = hh;
                    } else {
                        __half h0, l0, h1, l1; split2h(v0, h0, l0); split2h(v1, h1, l1);
                        __half2 hh; hh.x = h0; hh.y = h1;
                        __half2 ll; ll.x = l0; ll.y = l1;
                        __half* dh = z == 1 ? g_kh_h : g_vh_h;
                        __half* dl = z == 1 ? g_kh_l : g_vh_l;
                        *reinterpret_cast<__half2*>(dh + o) = hh;
                        *reinterpret_cast<__half2*>(dl + o) = ll;
                    }
                } else if constexpr (STAGE == 2) {
                    size_t z = blockIdx.z;
                    float2 w; w.x = v0; w.y = v1;
                    *reinterpret_cast<float2*>(g_x_bias + (z * SEQ + m) * (size_t)ATT + n) = w;
                } else {
                    const int ng = (int)(blockIdx.y * 128) + n;
                    float2 w; w.x = v0 + b0[ng]; w.y = v1 + b0[ng + 1];
                    *reinterpret_cast<float2*>(pout + (size_t)m * HID + ng) = w;
                }
            }
        }
    }
}

// ======================= flash attention (512 threads, fp16) ===============
#define FL_QH 0u
#define FL_KB 32768u
#define FL_VB 98304u
#define FL_PH 163840u
#define FL_RS 180224u
#define FL_SMEM 182272

__global__ __launch_bounds__(512, 1) void flash_kernel() {
    extern __shared__ char smem[];
    const uint32_t sb = smem_u32(smem);
    const int tid = threadIdx.x, wid = tid >> 5, lane = tid & 31;
    const int wm = wid & 3, wn = wid >> 2;      // 4 (M) x 4 (N)
    const size_t z = blockIdx.z;
    const size_t q0 = (size_t)blockIdx.x * 128;

    const __half* Qs = g_qh + z * SEQ * ATT;
    const __half* Kh = g_kh_h + z * SEQ * ATT;
    const __half* Kl = g_kh_l + z * SEQ * ATT;
    const __half* Vh = g_vh_h + z * SEQ * ATT;
    const __half* Vl = g_vh_l + z * SEQ * ATT;

    {
        int t = tid;
#pragma unroll
        for (int i = 0; i < 4; i++) {
            int id = t + i * 512;
            int row = id >> 4, c = id & 15;
            CP_ASYNC16(sb + FL_QH + swz256(row, c), Qs + (q0 + row) * ATT + c * 8);
        }
    }
    auto loadKV = [&](int kt, int buf) {
        const size_t r0 = (size_t)kt * 64;
        const uint32_t kb = sb + FL_KB + buf * 32768u;
        const uint32_t vb = sb + FL_VB + buf * 32768u;
        int t = tid;
#pragma unroll
        for (int i = 0; i < 2; i++) {
            int id = t + i * 512;
            int row = id >> 4, c = id & 15;
            CP_ASYNC16(kb + swz256(row, c),          Kh + (r0 + row) * ATT + c * 8);
            CP_ASYNC16(kb + 16384 + swz256(row, c),  Kl + (r0 + row) * ATT + c * 8);
            CP_ASYNC16(vb + swz256(row, c),          Vh + (r0 + row) * ATT + c * 8);
            CP_ASYNC16(vb + 16384 + swz256(row, c),  Vl + (r0 + row) * ATT + c * 8);
        }
    };
    loadKV(0, 0);
    CP_COMMIT();

    float U[2][4][4];
#pragma unroll
    for (int a = 0; a < 2; a++)
#pragma unroll
        for (int b = 0; b < 4; b++)
#pragma unroll
            for (int r = 0; r < 4; r++) U[a][b][r] = 0.f;
    float rsum[2][2];
#pragma unroll
    for (int a = 0; a < 2; a++) { rsum[a][0] = 0.f; rsum[a][1] = 0.f; }

    const int j8 = lane >> 3, r8 = lane & 7;
    const int aRow = wm * 32 + (j8 & 1) * 8 + r8;
    const int aCh  = (j8 >> 1);
    const int kRow = wn * 16 + (j8 >> 1) * 8 + r8;
    const int kCh  = (j8 & 1);
    const int vRow = (j8 & 1) * 8 + r8;
    const int vCh  = wn * 4 + (j8 >> 1);
    const int gid = lane >> 2, tig = lane & 3;

    for (int kt = 0; kt < 32; kt++) {
        CP_WAIT0();
        __syncthreads();
        if (kt + 1 < 32) { loadKV(kt + 1, (kt + 1) & 1); CP_COMMIT(); }

        const uint32_t kb  = sb + FL_KB + (kt & 1) * 32768u;
        const uint32_t kbl = kb + 16384;
        float sacc[2][2][4];
#pragma unroll
        for (int a = 0; a < 2; a++)
#pragma unroll
            for (int b = 0; b < 2; b++)
#pragma unroll
                for (int r = 0; r < 4; r++) sacc[a][b][r] = 0.f;
#pragma unroll
        for (int ks = 0; ks < 8; ks++) {
            uint32_t qa[2][4], kf[4], lf[4];
#pragma unroll
            for (int mt = 0; mt < 2; mt++)
                LDSM4(qa[mt], sb + FL_QH + swz256(aRow + mt * 16, ks * 2 + aCh));
            LDSM4(kf, kb  + swz256(kRow, ks * 2 + kCh));
            LDSM4(lf, kbl + swz256(kRow, ks * 2 + kCh));
#pragma unroll
            for (int mt = 0; mt < 2; mt++)
#pragma unroll
                for (int nt = 0; nt < 2; nt++) {
                    const int p = nt * 2;
                    MMA16816F(sacc[mt][nt], qa[mt], kf[p], kf[p + 1]);
                    MMA16816F(sacc[mt][nt], qa[mt], lf[p], lf[p + 1]);
                }
        }
        // P = exp(S) -> fp16 single, store to smem, accumulate rowsums
#pragma unroll
        for (int mt = 0; mt < 2; mt++)
#pragma unroll
            for (int nt = 0; nt < 2; nt++) {
                float e0 = __expf(sacc[mt][nt][0]);
                float e1 = __expf(sacc[mt][nt][1]);
                float e2 = __expf(sacc[mt][nt][2]);
                float e3 = __expf(sacc[mt][nt][3]);
                rsum[mt][0] += e0 + e1;
                rsum[mt][1] += e2 + e3;
                __half2 p01 = __floats2half2_rn(e0, e1);
                __half2 p23 = __floats2half2_rn(e2, e3);
                const int rlo = wm * 32 + mt * 16 + gid;
                const int chunk = wn * 2 + nt;
                uint32_t oflo = (uint32_t)(rlo * 128 + ((chunk ^ (rlo & 7)) * 16) + tig * 4);
                const int rhi = rlo + 8;
                uint32_t ofhi = (uint32_t)(rhi * 128 + ((chunk ^ (rhi & 7)) * 16) + tig * 4);
                *reinterpret_cast<uint32_t*>(smem + FL_PH + oflo) = *reinterpret_cast<uint32_t*>(&p01);
                *reinterpret_cast<uint32_t*>(smem + FL_PH + ofhi) = *reinterpret_cast<uint32_t*>(&p23);
            }
        __syncthreads();
        const uint32_t vb  = sb + FL_VB + (kt & 1) * 32768u;
        const uint32_t vbl = vb + 16384;
#pragma unroll
        for (int ks2 = 0; ks2 < 4; ks2++) {
            uint32_t pa[2][4], vh_[2][4], vl_[2][4];
#pragma unroll
            for (int mt = 0; mt < 2; mt++)
                LDSM4(pa[mt], sb + FL_PH + swz128(aRow + mt * 16, ks2 * 2 + aCh));
#pragma unroll
            for (int g = 0; g < 2; g++) {
                LDSM4T(vh_[g], vb  + swz256(ks2 * 16 + vRow, vCh + g * 2));
                LDSM4T(vl_[g], vbl + swz256(ks2 * 16 + vRow, vCh + g * 2));
            }
#pragma unroll
            for (int mt = 0; mt < 2; mt++)
#pragma unroll
                for (int nt = 0; nt < 4; nt++) {
                    const int g = nt >> 1, p = (nt & 1) * 2;
                    MMA16816F(U[mt][nt], pa[mt], vh_[g][p], vh_[g][p + 1]);
                    MMA16816F(U[mt][nt], pa[mt], vl_[g][p], vl_[g][p + 1]);
                }
        }
    }
    __syncthreads();

    float* rs = reinterpret_cast<float*>(smem + FL_RS);   // [128][4]
#pragma unroll
    for (int mt = 0; mt < 2; mt++)
#pragma unroll
        for (int h = 0; h < 2; h++) {
            float s = rsum[mt][h];
            s += __shfl_xor_sync(0xffffffffu, s, 1);
            s += __shfl_xor_sync(0xffffffffu, s, 2);
            rsum[mt][h] = s;
        }
    if (tig == 0) {
#pragma unroll
        for (int mt = 0; mt < 2; mt++)
#pragma unroll
            for (int h = 0; h < 2; h++) {
                int row = wm * 32 + mt * 16 + gid + h * 8;
                rs[row * 4 + wn] = rsum[mt][h];
            }
    }
    __syncthreads();

#pragma unroll
    for (int mt = 0; mt < 2; mt++) {
#pragma unroll
        for (int h = 0; h < 2; h++) {
            const int rowL = wm * 32 + mt * 16 + gid + h * 8;
            const float tot = rs[rowL * 4 + 0] + rs[rowL * 4 + 1]
                            + rs[rowL * 4 + 2] + rs[rowL * 4 + 3];
            const float inv = 1.f / tot;
            const size_t m = q0 + rowL;
#pragma unroll
            for (int nt = 0; nt < 4; nt++) {
                const int n = wn * 32 + nt * 8 + tig * 2;
                const size_t o = (z * SEQ + m) * (size_t)ATT + n;
                float2 xb = *reinterpret_cast<const float2*>(g_x_bias + o);
                float v0 = U[mt][nt][h * 2]     * inv + xb.x;
                float v1 = U[mt][nt][h * 2 + 1] * inv + xb.y;
                __half2 hh = __floats2half2_rn(v0, v1);
                *reinterpret_cast<__half2*>(g_x + o) = hh;
            }
        }
    }
}

// ======================= launch ============================================
extern "C" void kernel_launch(void* const* d_in, const int* in_sizes, int n_in,
                              void* d_out, int out_size) {
    const float* q         = (const float*)d_in[0];
    const float* k         = (const float*)d_in[1];
    const float* v         = (const float*)d_in[2];
    const float* attn_bias = (const float*)d_in[3];
    const float* wq        = (const float*)d_in[4];
    const float* bq        = (const float*)d_in[5];
    const float* wk        = (const float*)d_in[6];
    const float* bk        = (const float*)d_in[7];
    const float* wv        = (const float*)d_in[8];
    const float* bv        = (const float*)d_in[9];
    const float* wo        = (const float*)d_in[10];
    const float* bo        = (const float*)d_in[11];
    float* out = (float*)d_out;

    static bool s_init = false;
    static cudaStream_t s2;
    static cudaEvent_t evT, ev2;
    if (!s_init) {
        s_init = true;
        cudaStreamCreateWithFlags(&s2, cudaStreamNonBlocking);
        cudaEventCreateWithFlags(&evT, cudaEventDisableTiming);
        cudaEventCreateWithFlags(&ev2, cudaEventDisableTiming);
        cudaFuncSetAttribute(gemm_kernel<0>, cudaFuncAttributeMaxDynamicSharedMemorySize, 73728);
        cudaFuncSetAttribute(gemm_kernel<2>, cudaFuncAttributeMaxDynamicSharedMemorySize, 53248);
        cudaFuncSetAttribute(gemm_kernel<3>, cudaFuncAttributeMaxDynamicSharedMemorySize, 40960);
        cudaFuncSetAttribute(flash_kernel,   cudaFuncAttributeMaxDynamicSharedMemorySize, FL_SMEM);
    }

    // 1) weights -> wT fp16 hi/lo
    transpose_split_w_all<<<dim3(32, 32, 4), dim3(32, 8)>>>(wq, wk, wv, wo);
    cudaEventRecord(evT, 0);
    cudaStreamWaitEvent(s2, evT, 0);

    // side stream: v-projection then bias@vh
    gemm_kernel<0><<<dim3(VIEW * SEQ / 128, 1, 1), GT, 73728, s2>>>(
        q, k, v, bq, bk, bv, nullptr, 2);
    gemm_kernel<2><<<dim3(SEQ / 64, 1, VIEW), GT, 53248, s2>>>(
        attn_bias, nullptr, nullptr, nullptr, nullptr, nullptr, nullptr, 0);
    cudaEventRecord(ev2, s2);

    // main stream: q,k projections
    gemm_kernel<0><<<dim3(VIEW * SEQ / 128, 1, 2), GT, 73728>>>(
        q, k, v, bq, bk, bv, nullptr, 0);

    cudaStreamWaitEvent(0, ev2, 0);
    // 4) flash
    flash_kernel<<<dim3(SEQ / 128, 1, VIEW), 512, FL_SMEM>>>();
    // 5) output projection
    gemm_kernel<3><<<dim3(SEQ / 64, HID / 128), GT, 40960>>>(
        nullptr, nullptr, nullptr, bo, nullptr, nullptr, out, 0);
}

// round 13
// speedup vs baseline: 5.5414x; 1.1991x over previous
#include <cuda_runtime.h>
#include <cuda_bf16.h>
#include <cuda_fp16.h>
#include <cstdint>
#include <math.h>

#define VIEW 8
#define SEQ  2048
#define HID  1024
#define ATT  128
#define SCALE 0.08838834764831845f   // ATT^-0.5

// ======================= device scratch (no allocs allowed) =================
__device__ __align__(256) __half g_wqT_h[ATT*HID], g_wqT_l[ATT*HID];
__device__ __align__(256) __half g_wkT_h[ATT*HID], g_wkT_l[ATT*HID];
__device__ __align__(256) __half g_wvT_h[ATT*HID], g_wvT_l[ATT*HID];
__device__ __align__(256) __half g_woT_h[HID*HID], g_woT_l[HID*HID];
__device__ __align__(256) __half g_qh[VIEW*SEQ*ATT];     // fp16 single
__device__ __align__(256) __half g_kh[VIEW*SEQ*ATT];     // fp16 single
__device__ __align__(256) __half g_vh[VIEW*SEQ*ATT];     // fp16 single
__device__ __align__(256) float g_x_bias[VIEW*SEQ*ATT];
__device__ __align__(256) __half g_x[VIEW*SEQ*ATT];      // fp16 single

// ======================= helpers ===========================================
__device__ __forceinline__ uint32_t smem_u32(const void* p) {
    uint32_t a;
    asm("{ .reg .u64 t; cvta.to.shared.u64 t, %1; cvt.u32.u64 %0, t; }" : "=r"(a) : "l"(p));
    return a;
}
__device__ __forceinline__ void split2h(float x, __half& h, __half& l) {
    h = __float2half_rn(x);
    l = __float2half_rn(x - __half2float(h));
}

#define CP_ASYNC16(saddr, gptr) \
    asm volatile("cp.async.cg.shared.global [%0], [%1], 16;" \
                 :: "r"(saddr), "l"(__cvta_generic_to_global(gptr)) : "memory")
#define CP_COMMIT() asm volatile("cp.async.commit_group;" ::: "memory")
#define CP_WAIT0()  asm volatile("cp.async.wait_group 0;" ::: "memory")
#define CP_WAIT1()  asm volatile("cp.async.wait_group 1;" ::: "memory")

#define LDSM4(R, addr) \
    asm volatile("ldmatrix.sync.aligned.m8n8.x4.shared.b16 {%0,%1,%2,%3}, [%4];" \
                 : "=r"((R)[0]), "=r"((R)[1]), "=r"((R)[2]), "=r"((R)[3]) : "r"(addr))
#define LDSM4T(R, addr) \
    asm volatile("ldmatrix.sync.aligned.m8n8.x4.trans.shared.b16 {%0,%1,%2,%3}, [%4];" \
                 : "=r"((R)[0]), "=r"((R)[1]), "=r"((R)[2]), "=r"((R)[3]) : "r"(addr))

#define MMA16816F(C, A, b0, b1) \
    asm volatile("mma.sync.aligned.m16n8k16.row.col.f32.f16.f16.f32 " \
                 "{%0,%1,%2,%3},{%4,%5,%6,%7},{%8,%9},{%0,%1,%2,%3};" \
                 : "+f"((C)[0]), "+f"((C)[1]), "+f"((C)[2]), "+f"((C)[3]) \
                 : "r"((A)[0]), "r"((A)[1]), "r"((A)[2]), "r"((A)[3]), "r"(b0), "r"(b1))

// ======================= fused weight transpose+split (fp16 h/l) ===========
__global__ void transpose_split_w_all(const float* __restrict__ wq,
                                      const float* __restrict__ wk,
                                      const float* __restrict__ wv,
                                      const float* __restrict__ wo) {
    const int mode = blockIdx.z;
    const float* in;
    __half *dh, *dl; int C;
    if (mode == 0)      { in = wq; dh = g_wqT_h; dl = g_wqT_l; C = ATT; }
    else if (mode == 1) { in = wk; dh = g_wkT_h; dl = g_wkT_l; C = ATT; }
    else if (mode == 2) { in = wv; dh = g_wvT_h; dl = g_wvT_l; C = ATT; }
    else                { in = wo; dh = g_woT_h; dl = g_woT_l; C = HID; }
    if ((int)blockIdx.x * 32 >= C) return;
    __shared__ float t[32][33];
    const int R = HID;
    int c0 = blockIdx.x * 32, r0 = blockIdx.y * 32;
    int tx = threadIdx.x, ty = threadIdx.y;
#pragma unroll
    for (int i = 0; i < 4; i++)
        t[ty + i*8][tx] = in[(size_t)(r0 + ty + i*8) * C + c0 + tx];
    __syncthreads();
#pragma unroll
    for (int i = 0; i < 4; i++) {
        float x = t[tx][ty + i*8];
        __half h, l; split2h(x, h, l);
        size_t o = (size_t)(c0 + ty + i*8) * R + r0 + tx;
        dh[o] = h; dl[o] = l;
    }
}

// ======================= swizzles ==========================================
__device__ __forceinline__ uint32_t swz(int row, int chunk) {       // 64B rows
    return (uint32_t)(row * 64 + ((chunk ^ ((row >> 1) & 3)) * 16));
}
__device__ __forceinline__ uint32_t swz256(int row, int chunk) {    // 256B rows
    return (uint32_t)(row * 256 + ((chunk ^ (row & 7)) * 16));
}
__device__ __forceinline__ uint32_t swz128(int row, int chunk) {    // 128B rows
    return (uint32_t)(row * 128 + ((chunk ^ (row & 7)) * 16));
}

// ======================= GEMM template =====================================
#define GT 256
#define KC 32

template <int ROWS>
__device__ __forceinline__ void load_tile_async(uint32_t sbase,
                                                const __half* __restrict__ src,
                                                size_t row0, size_t ld) {
    int t = threadIdx.x;
#pragma unroll
    for (int i = 0; i < ROWS / 64; i++) {
        int id = t + i * 256;
        int row = id >> 2, c = id & 3;
        CP_ASYNC16(sbase + swz(row, c), src + (row0 + row) * ld + c * 8);
    }
}
__device__ __forceinline__ void load_vtile_async(uint32_t sbase,
                                                 const __half* __restrict__ src,
                                                 size_t row0) {
    int t = threadIdx.x;
#pragma unroll
    for (int i = 0; i < 2; i++) {
        int id = t + i * 256;
        int row = id >> 4, c = id & 15;
        CP_ASYNC16(sbase + swz256(row, c), src + (row0 + row) * ATT + c * 8);
    }
}
template <int ROWS>
__device__ __forceinline__ void load_fp_async(uint32_t sbase,
                                              const float* __restrict__ src,
                                              size_t row0, size_t ld) {
    int t = threadIdx.x;
#pragma unroll
    for (int i = 0; i < ROWS / 32; i++) {
        int id = t + i * 256;
        int row = id >> 3, c = id & 7;
        CP_ASYNC16(sbase + swz128(row, c), src + (row0 + row) * ld + c * 4);
    }
}

// STAGE 0: proj (MT=128)  A = fp32 input -> fp16, B wT fp16 h/l, K=1024
// STAGE 2: biasv (MT=64)  A = fp32 attn_bias -> fp16, B vh fp16 single (trans), K=2048
// STAGE 3: outproj (MT=64) A = g_x fp16, B woT fp16 h/l, K=1024
template <int STAGE>
__global__ __launch_bounds__(GT, 2)
void gemm_kernel(const float* __restrict__ i0, const float* __restrict__ i1,
                 const float* __restrict__ i2, const float* __restrict__ b0,
                 const float* __restrict__ b1, const float* __restrict__ b2,
                 float* __restrict__ pout, int zbase) {
    constexpr int MT  = (STAGE == 0) ? 128 : 64;
    constexpr int MTI = MT / 32;
    constexpr bool FPA = (STAGE == 0 || STAGE == 2);
    constexpr bool BSINGLE = (STAGE == 2);
    constexpr uint32_t A_T  = MT * 64;            // fp16 A tile bytes
    constexpr uint32_t FPB  = MT * 128;           // fp32 staging tile bytes
    constexpr uint32_t AH_OFF = FPA ? 2 * FPB : 0;
    constexpr uint32_t B_OFF  = FPA ? (2 * FPB + A_T) : (2 * A_T);
    constexpr uint32_t B_STRIDE = BSINGLE ? 8192u : 16384u;

    extern __shared__ char smem[];
    const uint32_t sb = smem_u32(smem);
    const int tid = threadIdx.x, wid = tid >> 5, lane = tid & 31;
    const int wm = wid & 1, wn = wid >> 1;

    const __half *Bh0 = nullptr, *Bl0 = nullptr;
    const float* Xf = nullptr;
    size_t ldA = 0, ldB = 0, rowA0 = 0, rowB0 = 0;
    int K_TOTAL = 0;
    if constexpr (STAGE == 0) {
        int z = blockIdx.z + zbase;
        Xf  = z == 0 ? i0 : z == 1 ? i1 : i2;
        Bh0 = z == 0 ? g_wqT_h : z == 1 ? g_wkT_h : g_wvT_h;
        Bl0 = z == 0 ? g_wqT_l : z == 1 ? g_wkT_l : g_wvT_l;
        ldA = HID; ldB = HID; rowA0 = (size_t)blockIdx.x * MT; K_TOTAL = HID;
    } else if constexpr (STAGE == 2) {
        size_t z = blockIdx.z;
        Xf  = i0 + z * (size_t)SEQ * SEQ;
        Bh0 = g_vh + z * (size_t)SEQ * ATT;
        ldA = SEQ;
        rowA0 = (size_t)blockIdx.x * MT; K_TOTAL = SEQ;
    } else {
        Bh0 = g_woT_h; Bl0 = g_woT_l;
        ldA = ATT; ldB = HID;
        rowA0 = (size_t)blockIdx.x * MT; rowB0 = (size_t)blockIdx.y * 128; K_TOTAL = HID;
    }
    const int nc = K_TOTAL / KC;

    auto load_chunk = [&](int c, int buf) {
        const int kb = c * KC;
        if constexpr (FPA) {
            load_fp_async<MT>(sb + buf * FPB, Xf + kb, rowA0, ldA);
        } else {
            size_t voff = (size_t)(kb >> 7) * (SEQ * ATT) + (kb & 127);
            load_tile_async<MT>(sb + buf * A_T, g_x + voff, rowA0, ldA);
        }
        if constexpr (STAGE == 2) {
            load_vtile_async(sb + B_OFF + buf * B_STRIDE, Bh0, (size_t)kb);
        } else {
            load_tile_async<128>(sb + B_OFF + buf * B_STRIDE,        Bh0 + kb, rowB0, ldB);
            load_tile_async<128>(sb + B_OFF + buf * B_STRIDE + 8192, Bl0 + kb, rowB0, ldB);
        }
    };

    float acc[MTI][4][4];
#pragma unroll
    for (int a = 0; a < MTI; a++)
#pragma unroll
        for (int b = 0; b < 4; b++)
#pragma unroll
            for (int r2 = 0; r2 < 4; r2++) acc[a][b][r2] = 0.f;

    const int j8 = lane >> 3, r8 = lane & 7;
    const int aRowB = wm * (MT / 2) + (j8 & 1) * 8 + r8;
    const int aChB  = (j8 >> 1);
    const int bRowB = wn * 32 + (j8 >> 1) * 8 + r8;
    const int bChB  = (j8 & 1);
    const int vRowB = (j8 & 1) * 8 + r8;
    const int vChB  = wn * 4 + (j8 >> 1);

    load_chunk(0, 0);
    CP_COMMIT();

    for (int c = 0; c < nc; c++) {
        if (c + 1 < nc) {
            load_chunk(c + 1, (c + 1) & 1);
            CP_COMMIT();
            CP_WAIT1();
        } else {
            CP_WAIT0();
        }
        __syncthreads();

        if constexpr (FPA) {
            const char* fpb = smem + (c & 1) * FPB;
#pragma unroll
            for (int i = 0; i < MT / 64; i++) {
                int id = tid + i * 256;
                const int row = id >> 2, q = id & 3;
                float4 f0 = *reinterpret_cast<const float4*>(fpb + swz128(row, q * 2));
                float4 f1 = *reinterpret_cast<const float4*>(fpb + swz128(row, q * 2 + 1));
                __half2 p0 = __floats2half2_rn(f0.x, f0.y);
                __half2 p1 = __floats2half2_rn(f0.z, f0.w);
                __half2 p2 = __floats2half2_rn(f1.x, f1.y);
                __half2 p3 = __floats2half2_rn(f1.z, f1.w);
                uint4 hh;
                hh.x = *reinterpret_cast<uint32_t*>(&p0);
                hh.y = *reinterpret_cast<uint32_t*>(&p1);
                hh.z = *reinterpret_cast<uint32_t*>(&p2);
                hh.w = *reinterpret_cast<uint32_t*>(&p3);
                *reinterpret_cast<uint4*>(smem + AH_OFF + swz(row, q)) = hh;
            }
            __syncthreads();
        }

        const uint32_t aB = FPA ? sb + AH_OFF : sb + (c & 1) * A_T;
        const uint32_t bB = sb + B_OFF + (c & 1) * B_STRIDE;
        const uint32_t blB = bB + 8192;
#pragma unroll
        for (int s = 0; s < 2; s++) {
            const int c0 = 2 * s;
            uint32_t ah[MTI][4], bh[2][4], bl[2][4];
#pragma unroll
            for (int mt = 0; mt < MTI; mt++)
                LDSM4(ah[mt], aB + swz(aRowB + mt * 16, aChB + c0));
#pragma unroll
            for (int g = 0; g < 2; g++) {
                if constexpr (STAGE == 2) {
                    LDSM4T(bh[g], bB + swz256(s * 16 + vRowB, vChB + g * 2));
                } else {
                    LDSM4(bh[g], bB  + swz(bRowB + g * 16, bChB + c0));
                    LDSM4(bl[g], blB + swz(bRowB + g * 16, bChB + c0));
                }
            }
#pragma unroll
            for (int mt = 0; mt < MTI; mt++)
#pragma unroll
                for (int nt = 0; nt < 4; nt++) {
                    const int g = nt >> 1, p = (nt & 1) * 2;
                    MMA16816F(acc[mt][nt], ah[mt], bh[g][p], bh[g][p + 1]);
                    if constexpr (!BSINGLE)
                        MMA16816F(acc[mt][nt], ah[mt], bl[g][p], bl[g][p + 1]);
                }
        }
        __syncthreads();
    }

    const int gid = lane >> 2, tig = lane & 3;
#pragma unroll
    for (int mt = 0; mt < MTI; mt++) {
#pragma unroll
        for (int h = 0; h < 2; h++) {
            const int m = (int)(blockIdx.x * MT) + wm * (MT / 2) + mt * 16 + gid + h * 8;
#pragma unroll
            for (int nt = 0; nt < 4; nt++) {
                const int n = wn * 32 + nt * 8 + tig * 2;
                float v0 = acc[mt][nt][h * 2];
                float v1 = acc[mt][nt][h * 2 + 1];
                if constexpr (STAGE == 0) {
                    int z = blockIdx.z + zbase;
                    const float* bias = z == 0 ? b0 : z == 1 ? b1 : b2;
                    float scl = (z == 0) ? SCALE : 1.f;
                    v0 = (v0 + bias[n]) * scl; v1 = (v1 + bias[n + 1]) * scl;
                    size_t o = (size_t)m * ATT + n;
                    __half* dst = z == 0 ? g_qh : z == 1 ? g_kh : g_vh;
                    __half2 hh = __floats2half2_rn(v0, v1);
                    *reinterpret_cast<__half2*>(dst + o) = hh;
                } else if constexpr (STAGE == 2) {
                    size_t z = blockIdx.z;
                    float2 w; w.x = v0; w.y = v1;
                    *reinterpret_cast<float2*>(g_x_bias + (z * SEQ + m) * (size_t)ATT + n) = w;
                } else {
                    const int ng = (int)(blockIdx.y * 128) + n;
                    float2 w; w.x = v0 + b0[ng]; w.y = v1 + b0[ng + 1];
                    *reinterpret_cast<float2*>(pout + (size_t)m * HID + ng) = w;
                }
            }
        }
    }
}

// ======================= flash attention (512 threads, fp16 single) ========
#define FL_QH 0u
#define FL_KB 32768u
#define FL_VB 65536u
#define FL_PH 98304u
#define FL_RS 114688u
#define FL_SMEM 116736

__global__ __launch_bounds__(512, 1) void flash_kernel() {
    extern __shared__ char smem[];
    const uint32_t sb = smem_u32(smem);
    const int tid = threadIdx.x, wid = tid >> 5, lane = tid & 31;
    const int wm = wid & 3, wn = wid >> 2;      // 4 (M) x 4 (N)
    const size_t z = blockIdx.z;
    const size_t q0 = (size_t)blockIdx.x * 128;

    const __half* Qs = g_qh + z * SEQ * ATT;
    const __half* Ks = g_kh + z * SEQ * ATT;
    const __half* Vs = g_vh + z * SEQ * ATT;

    {
        int t = tid;
#pragma unroll
        for (int i = 0; i < 4; i++) {
            int id = t + i * 512;
            int row = id >> 4, c = id & 15;
            CP_ASYNC16(sb + FL_QH + swz256(row, c), Qs + (q0 + row) * ATT + c * 8);
        }
    }
    auto loadKV = [&](int kt, int buf) {
        const size_t r0 = (size_t)kt * 64;
        const uint32_t kb = sb + FL_KB + buf * 16384u;
        const uint32_t vb = sb + FL_VB + buf * 16384u;
        int t = tid;
#pragma unroll
        for (int i = 0; i < 2; i++) {
            int id = t + i * 512;
            int row = id >> 4, c = id & 15;
            CP_ASYNC16(kb + swz256(row, c), Ks + (r0 + row) * ATT + c * 8);
            CP_ASYNC16(vb + swz256(row, c), Vs + (r0 + row) * ATT + c * 8);
        }
    };
    loadKV(0, 0);
    CP_COMMIT();

    float U[2][4][4];
#pragma unroll
    for (int a = 0; a < 2; a++)
#pragma unroll
        for (int b = 0; b < 4; b++)
#pragma unroll
            for (int r = 0; r < 4; r++) U[a][b][r] = 0.f;
    float rsum[2][2];
#pragma unroll
    for (int a = 0; a < 2; a++) { rsum[a][0] = 0.f; rsum[a][1] = 0.f; }

    const int j8 = lane >> 3, r8 = lane & 7;
    const int aRow = wm * 32 + (j8 & 1) * 8 + r8;
    const int aCh  = (j8 >> 1);
    const int kRow = wn * 16 + (j8 >> 1) * 8 + r8;
    const int kCh  = (j8 & 1);
    const int vRow = (j8 & 1) * 8 + r8;
    const int vCh  = wn * 4 + (j8 >> 1);
    const int gid = lane >> 2, tig = lane & 3;

    for (int kt = 0; kt < 32; kt++) {
        CP_WAIT0();
        __syncthreads();
        if (kt + 1 < 32) { loadKV(kt + 1, (kt + 1) & 1); CP_COMMIT(); }

        const uint32_t kb = sb + FL_KB + (kt & 1) * 16384u;
        float sacc[2][2][4];
#pragma unroll
        for (int a = 0; a < 2; a++)
#pragma unroll
            for (int b = 0; b < 2; b++)
#pragma unroll
                for (int r = 0; r < 4; r++) sacc[a][b][r] = 0.f;
#pragma unroll
        for (int ks = 0; ks < 8; ks++) {
            uint32_t qa[2][4], kf[4];
#pragma unroll
            for (int mt = 0; mt < 2; mt++)
                LDSM4(qa[mt], sb + FL_QH + swz256(aRow + mt * 16, ks * 2 + aCh));
            LDSM4(kf, kb + swz256(kRow, ks * 2 + kCh));
#pragma unroll
            for (int mt = 0; mt < 2; mt++)
#pragma unroll
                for (int nt = 0; nt < 2; nt++) {
                    const int p = nt * 2;
                    MMA16816F(sacc[mt][nt], qa[mt], kf[p], kf[p + 1]);
                }
        }
        // P = exp(S) -> fp16, store to smem, accumulate rowsums
#pragma unroll
        for (int mt = 0; mt < 2; mt++)
#pragma unroll
            for (int nt = 0; nt < 2; nt++) {
                float e0 = __expf(sacc[mt][nt][0]);
                float e1 = __expf(sacc[mt][nt][1]);
                float e2 = __expf(sacc[mt][nt][2]);
                float e3 = __expf(sacc[mt][nt][3]);
                rsum[mt][0] += e0 + e1;
                rsum[mt][1] += e2 + e3;
                __half2 p01 = __floats2half2_rn(e0, e1);
                __half2 p23 = __floats2half2_rn(e2, e3);
                const int rlo = wm * 32 + mt * 16 + gid;
                const int chunk = wn * 2 + nt;
                uint32_t oflo = (uint32_t)(rlo * 128 + ((chunk ^ (rlo & 7)) * 16) + tig * 4);
                const int rhi = rlo + 8;
                uint32_t ofhi = (uint32_t)(rhi * 128 + ((chunk ^ (rhi & 7)) * 16) + tig * 4);
                *reinterpret_cast<uint32_t*>(smem + FL_PH + oflo) = *reinterpret_cast<uint32_t*>(&p01);
                *reinterpret_cast<uint32_t*>(smem + FL_PH + ofhi) = *reinterpret_cast<uint32_t*>(&p23);
            }
        __syncthreads();
        const uint32_t vb = sb + FL_VB + (kt & 1) * 16384u;
#pragma unroll
        for (int ks2 = 0; ks2 < 4; ks2++) {
            uint32_t pa[2][4], vh_[2][4];
#pragma unroll
            for (int mt = 0; mt < 2; mt++)
                LDSM4(pa[mt], sb + FL_PH + swz128(aRow + mt * 16, ks2 * 2 + aCh));
#pragma unroll
            for (int g = 0; g < 2; g++)
                LDSM4T(vh_[g], vb + swz256(ks2 * 16 + vRow, vCh + g * 2));
#pragma unroll
            for (int mt = 0; mt < 2; mt++)
#pragma unroll
                for (int nt = 0; nt < 4; nt++) {
                    const int g = nt >> 1, p = (nt & 1) * 2;
                    MMA16816F(U[mt][nt], pa[mt], vh_[g][p], vh_[g][p + 1]);
                }
        }
    }
    __syncthreads();

    float* rs = reinterpret_cast<float*>(smem + FL_RS);   // [128][4]
#pragma unroll
    for (int mt = 0; mt < 2; mt++)
#pragma unroll
        for (int h = 0; h < 2; h++) {
            float s = rsum[mt][h];
            s += __shfl_xor_sync(0xffffffffu, s, 1);
            s += __shfl_xor_sync(0xffffffffu, s, 2);
            rsum[mt][h] = s;
        }
    if (tig == 0) {
#pragma unroll
        for (int mt = 0; mt < 2; mt++)
#pragma unroll
            for (int h = 0; h < 2; h++) {
                int row = wm * 32 + mt * 16 + gid + h * 8;
                rs[row * 4 + wn] = rsum[mt][h];
            }
    }
    __syncthreads();

#pragma unroll
    for (int mt = 0; mt < 2; mt++) {
#pragma unroll
        for (int h = 0; h < 2; h++) {
            const int rowL = wm * 32 + mt * 16 + gid + h * 8;
            const float tot = rs[rowL * 4 + 0] + rs[rowL * 4 + 1]
                            + rs[rowL * 4 + 2] + rs[rowL * 4 + 3];
            const float inv = 1.f / tot;
            const size_t m = q0 + rowL;
#pragma unroll
            for (int nt = 0; nt < 4; nt++) {
                const int n = wn * 32 + nt * 8 + tig * 2;
                const size_t o = (z * SEQ + m) * (size_t)ATT + n;
                float2 xb = *reinterpret_cast<const float2*>(g_x_bias + o);
                float v0 = U[mt][nt][h * 2]     * inv + xb.x;
                float v1 = U[mt][nt][h * 2 + 1] * inv + xb.y;
                __half2 hh = __floats2half2_rn(v0, v1);
                *reinterpret_cast<__half2*>(g_x + o) = hh;
            }
        }
    }
}

// ======================= launch ============================================
extern "C" void kernel_launch(void* const* d_in, const int* in_sizes, int n_in,
                              void* d_out, int out_size) {
    const float* q         = (const float*)d_in[0];
    const float* k         = (const float*)d_in[1];
    const float* v         = (const float*)d_in[2];
    const float* attn_bias = (const float*)d_in[3];
    const float* wq        = (const float*)d_in[4];
    const float* bq        = (const float*)d_in[5];
    const float* wk        = (const float*)d_in[6];
    const float* bk        = (const float*)d_in[7];
    const float* wv        = (const float*)d_in[8];
    const float* bv        = (const float*)d_in[9];
    const float* wo        = (const float*)d_in[10];
    const float* bo        = (const float*)d_in[11];
    float* out = (float*)d_out;

    static bool s_init = false;
    static cudaStream_t s2;
    static cudaEvent_t evT, ev2;
    if (!s_init) {
        s_init = true;
        cudaStreamCreateWithFlags(&s2, cudaStreamNonBlocking);
        cudaEventCreateWithFlags(&evT, cudaEventDisableTiming);
        cudaEventCreateWithFlags(&ev2, cudaEventDisableTiming);
        cudaFuncSetAttribute(gemm_kernel<0>, cudaFuncAttributeMaxDynamicSharedMemorySize, 73728);
        cudaFuncSetAttribute(gemm_kernel<2>, cudaFuncAttributeMaxDynamicSharedMemorySize, 36864);
        cudaFuncSetAttribute(gemm_kernel<3>, cudaFuncAttributeMaxDynamicSharedMemorySize, 40960);
        cudaFuncSetAttribute(flash_kernel,   cudaFuncAttributeMaxDynamicSharedMemorySize, FL_SMEM);
    }

    // 1) weights -> wT fp16 hi/lo
    transpose_split_w_all<<<dim3(32, 32, 4), dim3(32, 8)>>>(wq, wk, wv, wo);
    cudaEventRecord(evT, 0);
    cudaStreamWaitEvent(s2, evT, 0);

    // side stream: v-projection then bias@vh
    gemm_kernel<0><<<dim3(VIEW * SEQ / 128, 1, 1), GT, 73728, s2>>>(
        q, k, v, bq, bk, bv, nullptr, 2);
    gemm_kernel<2><<<dim3(SEQ / 64, 1, VIEW), GT, 36864, s2>>>(
        attn_bias, nullptr, nullptr, nullptr, nullptr, nullptr, nullptr, 0);
    cudaEventRecord(ev2, s2);

    // main stream: q,k projections
    gemm_kernel<0><<<dim3(VIEW * SEQ / 128, 1, 2), GT, 73728>>>(
        q, k, v, bq, bk, bv, nullptr, 0);

    cudaStreamWaitEvent(0, ev2, 0);
    // 4) flash
    flash_kernel<<<dim3(SEQ / 128, 1, VIEW), 512, FL_SMEM>>>();
    // 5) output projection
    gemm_kernel<3><<<dim3(SEQ / 64, HID / 128), GT, 40960>>>(
        nullptr, nullptr, nullptr, bo, nullptr, nullptr, out, 0);
}

// round 14
// speedup vs baseline: 6.3042x; 1.1376x over previous
#include <cuda_runtime.h>
#include <cuda_bf16.h>
#include <cuda_fp16.h>
#include <cstdint>
#include <math.h>

#define VIEW 8
#define SEQ  2048
#define HID  1024
#define ATT  128
#define SCALE 0.08838834764831845f   // ATT^-0.5

// ======================= device scratch (no allocs allowed) =================
__device__ __align__(256) __half g_wqT_h[ATT*HID], g_wqT_l[ATT*HID];
__device__ __align__(256) __half g_wkT_h[ATT*HID], g_wkT_l[ATT*HID];
__device__ __align__(256) __half g_wvT_h[ATT*HID], g_wvT_l[ATT*HID];
__device__ __align__(256) __half g_woT_h[HID*HID], g_woT_l[HID*HID];
__device__ __align__(256) __half g_qh[VIEW*SEQ*ATT];
__device__ __align__(256) __half g_kh[VIEW*SEQ*ATT];
__device__ __align__(256) __half g_vh[VIEW*SEQ*ATT];
__device__ __align__(256) float g_x_bias[VIEW*SEQ*ATT];
__device__ __align__(256) __half g_x[VIEW*SEQ*ATT];

// ======================= helpers ===========================================
__device__ __forceinline__ uint32_t smem_u32(const void* p) {
    uint32_t a;
    asm("{ .reg .u64 t; cvta.to.shared.u64 t, %1; cvt.u32.u64 %0, t; }" : "=r"(a) : "l"(p));
    return a;
}
__device__ __forceinline__ void split2h(float x, __half& h, __half& l) {
    h = __float2half_rn(x);
    l = __float2half_rn(x - __half2float(h));
}

#define CP_ASYNC16(saddr, gptr) \
    asm volatile("cp.async.cg.shared.global [%0], [%1], 16;" \
                 :: "r"(saddr), "l"(__cvta_generic_to_global(gptr)) : "memory")
#define CP_COMMIT() asm volatile("cp.async.commit_group;" ::: "memory")
#define CP_WAIT0()  asm volatile("cp.async.wait_group 0;" ::: "memory")
#define CP_WAIT1()  asm volatile("cp.async.wait_group 1;" ::: "memory")

#define LDSM4(R, addr) \
    asm volatile("ldmatrix.sync.aligned.m8n8.x4.shared.b16 {%0,%1,%2,%3}, [%4];" \
                 : "=r"((R)[0]), "=r"((R)[1]), "=r"((R)[2]), "=r"((R)[3]) : "r"(addr))
#define LDSM4T(R, addr) \
    asm volatile("ldmatrix.sync.aligned.m8n8.x4.trans.shared.b16 {%0,%1,%2,%3}, [%4];" \
                 : "=r"((R)[0]), "=r"((R)[1]), "=r"((R)[2]), "=r"((R)[3]) : "r"(addr))

#define MMA16816F(C, A, b0, b1) \
    asm volatile("mma.sync.aligned.m16n8k16.row.col.f32.f16.f16.f32 " \
                 "{%0,%1,%2,%3},{%4,%5,%6,%7},{%8,%9},{%0,%1,%2,%3};" \
                 : "+f"((C)[0]), "+f"((C)[1]), "+f"((C)[2]), "+f"((C)[3]) \
                 : "r"((A)[0]), "r"((A)[1]), "r"((A)[2]), "r"((A)[3]), "r"(b0), "r"(b1))

// ======================= fused weight transpose+split (fp16 h/l) ===========
__global__ void transpose_split_w_all(const float* __restrict__ wq,
                                      const float* __restrict__ wk,
                                      const float* __restrict__ wv,
                                      const float* __restrict__ wo) {
    const int mode = blockIdx.z;
    const float* in;
    __half *dh, *dl; int C;
    if (mode == 0)      { in = wq; dh = g_wqT_h; dl = g_wqT_l; C = ATT; }
    else if (mode == 1) { in = wk; dh = g_wkT_h; dl = g_wkT_l; C = ATT; }
    else if (mode == 2) { in = wv; dh = g_wvT_h; dl = g_wvT_l; C = ATT; }
    else                { in = wo; dh = g_woT_h; dl = g_woT_l; C = HID; }
    if ((int)blockIdx.x * 32 >= C) return;
    __shared__ float t[32][33];
    const int R = HID;
    int c0 = blockIdx.x * 32, r0 = blockIdx.y * 32;
    int tx = threadIdx.x, ty = threadIdx.y;
#pragma unroll
    for (int i = 0; i < 4; i++)
        t[ty + i*8][tx] = in[(size_t)(r0 + ty + i*8) * C + c0 + tx];
    __syncthreads();
#pragma unroll
    for (int i = 0; i < 4; i++) {
        float x = t[tx][ty + i*8];
        __half h, l; split2h(x, h, l);
        size_t o = (size_t)(c0 + ty + i*8) * R + r0 + tx;
        dh[o] = h; dl[o] = l;
    }
}

// ======================= swizzles ==========================================
__device__ __forceinline__ uint32_t swz(int row, int chunk) {       // 64B rows
    return (uint32_t)(row * 64 + ((chunk ^ ((row >> 1) & 3)) * 16));
}
__device__ __forceinline__ uint32_t swz256(int row, int chunk) {    // 256B rows
    return (uint32_t)(row * 256 + ((chunk ^ (row & 7)) * 16));
}
__device__ __forceinline__ uint32_t swz128(int row, int chunk) {    // 128B rows
    return (uint32_t)(row * 128 + ((chunk ^ (row & 7)) * 16));
}

// ======================= GEMM template =====================================
#define GT 256
#define KC 32

template <int ROWS>
__device__ __forceinline__ void load_tile_async(uint32_t sbase,
                                                const __half* __restrict__ src,
                                                size_t row0, size_t ld) {
    int t = threadIdx.x;
#pragma unroll
    for (int i = 0; i < ROWS / 64; i++) {
        int id = t + i * 256;
        int row = id >> 2, c = id & 3;
        CP_ASYNC16(sbase + swz(row, c), src + (row0 + row) * ld + c * 8);
    }
}
__device__ __forceinline__ void load_vtile_async(uint32_t sbase,
                                                 const __half* __restrict__ src,
                                                 size_t row0) {
    int t = threadIdx.x;
#pragma unroll
    for (int i = 0; i < 2; i++) {
        int id = t + i * 256;
        int row = id >> 4, c = id & 15;
        CP_ASYNC16(sbase + swz256(row, c), src + (row0 + row) * ATT + c * 8);
    }
}
template <int ROWS>
__device__ __forceinline__ void load_fp_async(uint32_t sbase,
                                              const float* __restrict__ src,
                                              size_t row0, size_t ld) {
    int t = threadIdx.x;
#pragma unroll
    for (int i = 0; i < ROWS / 32; i++) {
        int id = t + i * 256;
        int row = id >> 3, c = id & 7;
        CP_ASYNC16(sbase + swz128(row, c), src + (row0 + row) * ld + c * 4);
    }
}

// STAGE 0: proj (MT=128)  A = fp32 input -> fp16, B wT fp16 SINGLE, K=1024
// STAGE 2: biasv (MT=64)  A = fp32 attn_bias -> fp16, B vh fp16 single (trans), K=2048
// STAGE 3: outproj (MT=64) A = g_x fp16, B woT fp16 h/l, K=1024
template <int STAGE>
__global__ __launch_bounds__(GT, 2)
void gemm_kernel(const float* __restrict__ i0, const float* __restrict__ i1,
                 const float* __restrict__ i2, const float* __restrict__ b0,
                 const float* __restrict__ b1, const float* __restrict__ b2,
                 float* __restrict__ pout, int zbase) {
    constexpr int MT  = (STAGE == 0) ? 128 : 64;
    constexpr int MTI = MT / 32;
    constexpr bool FPA = (STAGE == 0 || STAGE == 2);
    constexpr bool BSINGLE = (STAGE == 0 || STAGE == 2);
    constexpr uint32_t A_T  = MT * 64;
    constexpr uint32_t FPB  = MT * 128;
    constexpr uint32_t AH_OFF = FPA ? 2 * FPB : 0;
    constexpr uint32_t B_OFF  = FPA ? (2 * FPB + A_T) : (2 * A_T);
    constexpr uint32_t B_STRIDE = BSINGLE ? 8192u : 16384u;

    extern __shared__ char smem[];
    const uint32_t sb = smem_u32(smem);
    const int tid = threadIdx.x, wid = tid >> 5, lane = tid & 31;
    const int wm = wid & 1, wn = wid >> 1;

    const __half *Bh0 = nullptr, *Bl0 = nullptr;
    const float* Xf = nullptr;
    size_t ldA = 0, ldB = 0, rowA0 = 0, rowB0 = 0;
    int K_TOTAL = 0;
    if constexpr (STAGE == 0) {
        int z = blockIdx.z + zbase;
        Xf  = z == 0 ? i0 : z == 1 ? i1 : i2;
        Bh0 = z == 0 ? g_wqT_h : z == 1 ? g_wkT_h : g_wvT_h;
        ldA = HID; ldB = HID; rowA0 = (size_t)blockIdx.x * MT; K_TOTAL = HID;
    } else if constexpr (STAGE == 2) {
        size_t z = blockIdx.z;
        Xf  = i0 + z * (size_t)SEQ * SEQ;
        Bh0 = g_vh + z * (size_t)SEQ * ATT;
        ldA = SEQ;
        rowA0 = (size_t)blockIdx.x * MT; K_TOTAL = SEQ;
    } else {
        Bh0 = g_woT_h; Bl0 = g_woT_l;
        ldA = ATT; ldB = HID;
        rowA0 = (size_t)blockIdx.x * MT; rowB0 = (size_t)blockIdx.y * 128; K_TOTAL = HID;
    }
    const int nc = K_TOTAL / KC;

    auto load_chunk = [&](int c, int buf) {
        const int kb = c * KC;
        if constexpr (FPA) {
            load_fp_async<MT>(sb + buf * FPB, Xf + kb, rowA0, ldA);
        } else {
            size_t voff = (size_t)(kb >> 7) * (SEQ * ATT) + (kb & 127);
            load_tile_async<MT>(sb + buf * A_T, g_x + voff, rowA0, ldA);
        }
        if constexpr (STAGE == 2) {
            load_vtile_async(sb + B_OFF + buf * B_STRIDE, Bh0, (size_t)kb);
        } else if constexpr (STAGE == 0) {
            load_tile_async<128>(sb + B_OFF + buf * B_STRIDE, Bh0 + kb, rowB0, ldB);
        } else {
            load_tile_async<128>(sb + B_OFF + buf * B_STRIDE,        Bh0 + kb, rowB0, ldB);
            load_tile_async<128>(sb + B_OFF + buf * B_STRIDE + 8192, Bl0 + kb, rowB0, ldB);
        }
    };

    float acc[MTI][4][4];
#pragma unroll
    for (int a = 0; a < MTI; a++)
#pragma unroll
        for (int b = 0; b < 4; b++)
#pragma unroll
            for (int r2 = 0; r2 < 4; r2++) acc[a][b][r2] = 0.f;

    const int j8 = lane >> 3, r8 = lane & 7;
    const int aRowB = wm * (MT / 2) + (j8 & 1) * 8 + r8;
    const int aChB  = (j8 >> 1);
    const int bRowB = wn * 32 + (j8 >> 1) * 8 + r8;
    const int bChB  = (j8 & 1);
    const int vRowB = (j8 & 1) * 8 + r8;
    const int vChB  = wn * 4 + (j8 >> 1);

    load_chunk(0, 0);
    CP_COMMIT();

    for (int c = 0; c < nc; c++) {
        if (c + 1 < nc) {
            load_chunk(c + 1, (c + 1) & 1);
            CP_COMMIT();
            CP_WAIT1();
        } else {
            CP_WAIT0();
        }
        __syncthreads();

        if constexpr (FPA) {
            const char* fpb = smem + (c & 1) * FPB;
#pragma unroll
            for (int i = 0; i < MT / 64; i++) {
                int id = tid + i * 256;
                const int row = id >> 2, q = id & 3;
                float4 f0 = *reinterpret_cast<const float4*>(fpb + swz128(row, q * 2));
                float4 f1 = *reinterpret_cast<const float4*>(fpb + swz128(row, q * 2 + 1));
                __half2 p0 = __floats2half2_rn(f0.x, f0.y);
                __half2 p1 = __floats2half2_rn(f0.z, f0.w);
                __half2 p2 = __floats2half2_rn(f1.x, f1.y);
                __half2 p3 = __floats2half2_rn(f1.z, f1.w);
                uint4 hh;
                hh.x = *reinterpret_cast<uint32_t*>(&p0);
                hh.y = *reinterpret_cast<uint32_t*>(&p1);
                hh.z = *reinterpret_cast<uint32_t*>(&p2);
                hh.w = *reinterpret_cast<uint32_t*>(&p3);
                *reinterpret_cast<uint4*>(smem + AH_OFF + swz(row, q)) = hh;
            }
            __syncthreads();
        }

        const uint32_t aB = FPA ? sb + AH_OFF : sb + (c & 1) * A_T;
        const uint32_t bB = sb + B_OFF + (c & 1) * B_STRIDE;
        const uint32_t blB = bB + 8192;
#pragma unroll
        for (int s = 0; s < 2; s++) {
            const int c0 = 2 * s;
            uint32_t ah[MTI][4], bh[2][4], bl[2][4];
#pragma unroll
            for (int mt = 0; mt < MTI; mt++)
                LDSM4(ah[mt], aB + swz(aRowB + mt * 16, aChB + c0));
#pragma unroll
            for (int g = 0; g < 2; g++) {
                if constexpr (STAGE == 2) {
                    LDSM4T(bh[g], bB + swz256(s * 16 + vRowB, vChB + g * 2));
                } else if constexpr (STAGE == 0) {
                    LDSM4(bh[g], bB + swz(bRowB + g * 16, bChB + c0));
                } else {
                    LDSM4(bh[g], bB  + swz(bRowB + g * 16, bChB + c0));
                    LDSM4(bl[g], blB + swz(bRowB + g * 16, bChB + c0));
                }
            }
#pragma unroll
            for (int mt = 0; mt < MTI; mt++)
#pragma unroll
                for (int nt = 0; nt < 4; nt++) {
                    const int g = nt >> 1, p = (nt & 1) * 2;
                    MMA16816F(acc[mt][nt], ah[mt], bh[g][p], bh[g][p + 1]);
                    if constexpr (!BSINGLE)
                        MMA16816F(acc[mt][nt], ah[mt], bl[g][p], bl[g][p + 1]);
                }
        }
        __syncthreads();
    }

    const int gid = lane >> 2, tig = lane & 3;
#pragma unroll
    for (int mt = 0; mt < MTI; mt++) {
#pragma unroll
        for (int h = 0; h < 2; h++) {
            const int m = (int)(blockIdx.x * MT) + wm * (MT / 2) + mt * 16 + gid + h * 8;
#pragma unroll
            for (int nt = 0; nt < 4; nt++) {
                const int n = wn * 32 + nt * 8 + tig * 2;
                float v0 = acc[mt][nt][h * 2];
                float v1 = acc[mt][nt][h * 2 + 1];
                if constexpr (STAGE == 0) {
                    int z = blockIdx.z + zbase;
                    const float* bias = z == 0 ? b0 : z == 1 ? b1 : b2;
                    float scl = (z == 0) ? SCALE : 1.f;
                    v0 = (v0 + bias[n]) * scl; v1 = (v1 + bias[n + 1]) * scl;
                    size_t o = (size_t)m * ATT + n;
                    __half* dst = z == 0 ? g_qh : z == 1 ? g_kh : g_vh;
                    __half2 hh = __floats2half2_rn(v0, v1);
                    *reinterpret_cast<__half2*>(dst + o) = hh;
                } else if constexpr (STAGE == 2) {
                    size_t z = blockIdx.z;
                    float2 w; w.x = v0; w.y = v1;
                    *reinterpret_cast<float2*>(g_x_bias + (z * SEQ + m) * (size_t)ATT + n) = w;
                } else {
                    const int ng = (int)(blockIdx.y * 128) + n;
                    float2 w; w.x = v0 + b0[ng]; w.y = v1 + b0[ng + 1];
                    *reinterpret_cast<float2*>(pout + (size_t)m * HID + ng) = w;
                }
            }
        }
    }
}

// ======================= flash attention (512 thr, 128-key tiles) ==========
#define FL_QH 0u
#define FL_KB 32768u
#define FL_VB 98304u
#define FL_PH 163840u
#define FL_RS 196608u
#define FL_SMEM 198656

__global__ __launch_bounds__(512, 1) void flash_kernel() {
    extern __shared__ char smem[];
    const uint32_t sb = smem_u32(smem);
    const int tid = threadIdx.x, wid = tid >> 5, lane = tid & 31;
    const int wm = wid & 3, wn = wid >> 2;      // 4 (M) x 4 (N)
    const size_t z = blockIdx.z;
    const size_t q0 = (size_t)blockIdx.x * 128;

    const __half* Qs = g_qh + z * SEQ * ATT;
    const __half* Ks = g_kh + z * SEQ * ATT;
    const __half* Vs = g_vh + z * SEQ * ATT;

    {
        int t = tid;
#pragma unroll
        for (int i = 0; i < 4; i++) {
            int id = t + i * 512;
            int row = id >> 4, c = id & 15;
            CP_ASYNC16(sb + FL_QH + swz256(row, c), Qs + (q0 + row) * ATT + c * 8);
        }
    }
    auto loadKV = [&](int kt, int buf) {
        const size_t r0 = (size_t)kt * 128;
        const uint32_t kb = sb + FL_KB + buf * 32768u;
        const uint32_t vb = sb + FL_VB + buf * 32768u;
        int t = tid;
#pragma unroll
        for (int i = 0; i < 4; i++) {
            int id = t + i * 512;
            int row = id >> 4, c = id & 15;
            CP_ASYNC16(kb + swz256(row, c), Ks + (r0 + row) * ATT + c * 8);
            CP_ASYNC16(vb + swz256(row, c), Vs + (r0 + row) * ATT + c * 8);
        }
    };
    loadKV(0, 0);
    CP_COMMIT();

    float U[2][4][4];
#pragma unroll
    for (int a = 0; a < 2; a++)
#pragma unroll
        for (int b = 0; b < 4; b++)
#pragma unroll
            for (int r = 0; r < 4; r++) U[a][b][r] = 0.f;
    float rsum[2][2];
#pragma unroll
    for (int a = 0; a < 2; a++) { rsum[a][0] = 0.f; rsum[a][1] = 0.f; }

    const int j8 = lane >> 3, r8 = lane & 7;
    const int aRow = wm * 32 + (j8 & 1) * 8 + r8;   // + mt*16 (Q and P A-frags)
    const int aCh  = (j8 >> 1);
    const int kRowB = wn * 32 + (j8 >> 1) * 8 + r8; // + g*16 (K as B, 32 keys/warp)
    const int kCh  = (j8 & 1);
    const int vRow = (j8 & 1) * 8 + r8;             // + ks2*16 (V trans B)
    const int vCh  = wn * 4 + (j8 >> 1);
    const int gid = lane >> 2, tig = lane & 3;

    for (int kt = 0; kt < 16; kt++) {
        CP_WAIT0();
        __syncthreads();
        if (kt + 1 < 16) { loadKV(kt + 1, (kt + 1) & 1); CP_COMMIT(); }

        const uint32_t kb = sb + FL_KB + (kt & 1) * 32768u;
        float sacc[2][4][4];
#pragma unroll
        for (int a = 0; a < 2; a++)
#pragma unroll
            for (int b = 0; b < 4; b++)
#pragma unroll
                for (int r = 0; r < 4; r++) sacc[a][b][r] = 0.f;
#pragma unroll
        for (int ks = 0; ks < 8; ks++) {
            uint32_t qa[2][4], kf[2][4];
#pragma unroll
            for (int mt = 0; mt < 2; mt++)
                LDSM4(qa[mt], sb + FL_QH + swz256(aRow + mt * 16, ks * 2 + aCh));
#pragma unroll
            for (int g = 0; g < 2; g++)
                LDSM4(kf[g], kb + swz256(kRowB + g * 16, ks * 2 + kCh));
#pragma unroll
            for (int mt = 0; mt < 2; mt++)
#pragma unroll
                for (int nt = 0; nt < 4; nt++) {
                    const int g = nt >> 1, p = (nt & 1) * 2;
                    MMA16816F(sacc[mt][nt], qa[mt], kf[g][p], kf[g][p + 1]);
                }
        }
        // P = exp(S) -> fp16, store to smem (256B rows), accumulate rowsums
#pragma unroll
        for (int mt = 0; mt < 2; mt++)
#pragma unroll
            for (int nt = 0; nt < 4; nt++) {
                float e0 = __expf(sacc[mt][nt][0]);
                float e1 = __expf(sacc[mt][nt][1]);
                float e2 = __expf(sacc[mt][nt][2]);
                float e3 = __expf(sacc[mt][nt][3]);
                rsum[mt][0] += e0 + e1;
                rsum[mt][1] += e2 + e3;
                __half2 p01 = __floats2half2_rn(e0, e1);
                __half2 p23 = __floats2half2_rn(e2, e3);
                const int rlo = wm * 32 + mt * 16 + gid;
                const int chunk = wn * 4 + nt;
                uint32_t oflo = (uint32_t)(rlo * 256 + ((chunk ^ (rlo & 7)) * 16) + tig * 4);
                const int rhi = rlo + 8;
                uint32_t ofhi = (uint32_t)(rhi * 256 + ((chunk ^ (rhi & 7)) * 16) + tig * 4);
                *reinterpret_cast<uint32_t*>(smem + FL_PH + oflo) = *reinterpret_cast<uint32_t*>(&p01);
                *reinterpret_cast<uint32_t*>(smem + FL_PH + ofhi) = *reinterpret_cast<uint32_t*>(&p23);
            }
        __syncthreads();
        const uint32_t vb = sb + FL_VB + (kt & 1) * 32768u;
#pragma unroll
        for (int ks2 = 0; ks2 < 8; ks2++) {
            uint32_t pa[2][4], vh_[2][4];
#pragma unroll
            for (int mt = 0; mt < 2; mt++)
                LDSM4(pa[mt], sb + FL_PH + swz256(aRow + mt * 16, ks2 * 2 + aCh));
#pragma unroll
            for (int g = 0; g < 2; g++)
                LDSM4T(vh_[g], vb + swz256(ks2 * 16 + vRow, vCh + g * 2));
#pragma unroll
            for (int mt = 0; mt < 2; mt++)
#pragma unroll
                for (int nt = 0; nt < 4; nt++) {
                    const int g = nt >> 1, p = (nt & 1) * 2;
                    MMA16816F(U[mt][nt], pa[mt], vh_[g][p], vh_[g][p + 1]);
                }
        }
    }
    __syncthreads();

    float* rs = reinterpret_cast<float*>(smem + FL_RS);   // [128][4]
#pragma unroll
    for (int mt = 0; mt < 2; mt++)
#pragma unroll
        for (int h = 0; h < 2; h++) {
            float s = rsum[mt][h];
            s += __shfl_xor_sync(0xffffffffu, s, 1);
            s += __shfl_xor_sync(0xffffffffu, s, 2);
            rsum[mt][h] = s;
        }
    if (tig == 0) {
#pragma unroll
        for (int mt = 0; mt < 2; mt++)
#pragma unroll
            for (int h = 0; h < 2; h++) {
                int row = wm * 32 + mt * 16 + gid + h * 8;
                rs[row * 4 + wn] = rsum[mt][h];
            }
    }
    __syncthreads();

#pragma unroll
    for (int mt = 0; mt < 2; mt++) {
#pragma unroll
        for (int h = 0; h < 2; h++) {
            const int rowL = wm * 32 + mt * 16 + gid + h * 8;
            const float tot = rs[rowL * 4 + 0] + rs[rowL * 4 + 1]
                            + rs[rowL * 4 + 2] + rs[rowL * 4 + 3];
            const float inv = 1.f / tot;
            const size_t m = q0 + rowL;
#pragma unroll
            for (int nt = 0; nt < 4; nt++) {
                const int n = wn * 32 + nt * 8 + tig * 2;
                const size_t o = (z * SEQ + m) * (size_t)ATT + n;
                float2 xb = *reinterpret_cast<const float2*>(g_x_bias + o);
                float v0 = U[mt][nt][h * 2]     * inv + xb.x;
                float v1 = U[mt][nt][h * 2 + 1] * inv + xb.y;
                __half2 hh = __floats2half2_rn(v0, v1);
                *reinterpret_cast<__half2*>(g_x + o) = hh;
            }
        }
    }
}

// ======================= launch ============================================
extern "C" void kernel_launch(void* const* d_in, const int* in_sizes, int n_in,
                              void* d_out, int out_size) {
    const float* q         = (const float*)d_in[0];
    const float* k         = (const float*)d_in[1];
    const float* v         = (const float*)d_in[2];
    const float* attn_bias = (const float*)d_in[3];
    const float* wq        = (const float*)d_in[4];
    const float* bq        = (const float*)d_in[5];
    const float* wk        = (const float*)d_in[6];
    const float* bk        = (const float*)d_in[7];
    const float* wv        = (const float*)d_in[8];
    const float* bv        = (const float*)d_in[9];
    const float* wo        = (const float*)d_in[10];
    const float* bo        = (const float*)d_in[11];
    float* out = (float*)d_out;

    static bool s_init = false;
    static cudaStream_t s2;
    static cudaEvent_t evT, ev2;
    if (!s_init) {
        s_init = true;
        cudaStreamCreateWithFlags(&s2, cudaStreamNonBlocking);
        cudaEventCreateWithFlags(&evT, cudaEventDisableTiming);
        cudaEventCreateWithFlags(&ev2, cudaEventDisableTiming);
        cudaFuncSetAttribute(gemm_kernel<0>, cudaFuncAttributeMaxDynamicSharedMemorySize, 57344);
        cudaFuncSetAttribute(gemm_kernel<2>, cudaFuncAttributeMaxDynamicSharedMemorySize, 36864);
        cudaFuncSetAttribute(gemm_kernel<3>, cudaFuncAttributeMaxDynamicSharedMemorySize, 40960);
        cudaFuncSetAttribute(flash_kernel,   cudaFuncAttributeMaxDynamicSharedMemorySize, FL_SMEM);
    }

    // 1) weights -> wT fp16 hi/lo
    transpose_split_w_all<<<dim3(32, 32, 4), dim3(32, 8)>>>(wq, wk, wv, wo);
    cudaEventRecord(evT, 0);
    cudaStreamWaitEvent(s2, evT, 0);

    // side stream: v-projection then bias@vh
    gemm_kernel<0><<<dim3(VIEW * SEQ / 128, 1, 1), GT, 57344, s2>>>(
        q, k, v, bq, bk, bv, nullptr, 2);
    gemm_kernel<2><<<dim3(SEQ / 64, 1, VIEW), GT, 36864, s2>>>(
        attn_bias, nullptr, nullptr, nullptr, nullptr, nullptr, nullptr, 0);
    cudaEventRecord(ev2, s2);

    // main stream: q,k projections
    gemm_kernel<0><<<dim3(VIEW * SEQ / 128, 1, 2), GT, 57344>>>(
        q, k, v, bq, bk, bv, nullptr, 0);

    cudaStreamWaitEvent(0, ev2, 0);
    // 4) flash (128-key tiles)
    flash_kernel<<<dim3(SEQ / 128, 1, VIEW), 512, FL_SMEM>>>();
    // 5) output projection
    gemm_kernel<3><<<dim3(SEQ / 64, HID / 128), GT, 40960>>>(
        nullptr, nullptr, nullptr, bo, nullptr, nullptr, out, 0);
}